// round 2
// baseline (speedup 1.0000x reference)
#include <cuda_runtime.h>
#include <math.h>

// Problem constants
#define BATCH   16
#define SRC_LEN 512
#define MEL_LEN 2048
#define DMODEL  256

#define BM 128
#define BN 128
#define BK 16
#define TM 8
#define TN 8

// Scratch (sanctioned __device__ globals; no runtime allocation)
__device__ float Qbuf[BATCH * SRC_LEN * DMODEL];   // 8 MB
__device__ float Kbuf[BATCH * MEL_LEN * DMODEL];   // 32 MB
__device__ float Vbuf[BATCH * MEL_LEN * DMODEL];   // 32 MB

// ---------------------------------------------------------------------------
// Projection GEMM: C[M,256] = X[M,256] @ W[256,256]^T   grid(2, M/128), 256 thr
// ---------------------------------------------------------------------------
__global__ void __launch_bounds__(256) proj_kernel(
    const float* __restrict__ X, const float* __restrict__ W, float* __restrict__ C)
{
    __shared__ float As[BK][BM + 4];
    __shared__ float Bs[BK][BN + 4];
    const int tid = threadIdx.x;
    const int tx = tid & 15, ty = tid >> 4;
    const float* Ab = X + (size_t)blockIdx.y * BM * DMODEL;
    const float* Bb = W + (size_t)blockIdx.x * BN * DMODEL;
    const int lr = tid >> 2, lc = (tid & 3) << 2;

    float acc[TM][TN] = {};

    for (int k0 = 0; k0 < DMODEL; k0 += BK) {
        #pragma unroll
        for (int r = 0; r < BM; r += 64) {
            float4 v = *(const float4*)(Ab + (size_t)(lr + r) * DMODEL + k0 + lc);
            As[lc + 0][lr + r] = v.x; As[lc + 1][lr + r] = v.y;
            As[lc + 2][lr + r] = v.z; As[lc + 3][lr + r] = v.w;
        }
        #pragma unroll
        for (int r = 0; r < BN; r += 64) {
            float4 v = *(const float4*)(Bb + (size_t)(lr + r) * DMODEL + k0 + lc);
            Bs[lc + 0][lr + r] = v.x; Bs[lc + 1][lr + r] = v.y;
            Bs[lc + 2][lr + r] = v.z; Bs[lc + 3][lr + r] = v.w;
        }
        __syncthreads();
        #pragma unroll
        for (int k = 0; k < BK; ++k) {
            float4 a0 = *(const float4*)&As[k][ty * TM];
            float4 a1 = *(const float4*)&As[k][ty * TM + 4];
            float4 b0 = *(const float4*)&Bs[k][tx * TN];
            float4 b1 = *(const float4*)&Bs[k][tx * TN + 4];
            float a[TM] = {a0.x, a0.y, a0.z, a0.w, a1.x, a1.y, a1.z, a1.w};
            float b[TN] = {b0.x, b0.y, b0.z, b0.w, b1.x, b1.y, b1.z, b1.w};
            #pragma unroll
            for (int i = 0; i < TM; ++i)
                #pragma unroll
                for (int j = 0; j < TN; ++j)
                    acc[i][j] = fmaf(a[i], b[j], acc[i][j]);
        }
        __syncthreads();
    }

    float* Cb = C + (size_t)(blockIdx.y * BM + ty * TM) * DMODEL + blockIdx.x * BN + tx * TN;
    #pragma unroll
    for (int i = 0; i < TM; ++i) {
        *(float4*)(Cb + (size_t)i * DMODEL)     = make_float4(acc[i][0], acc[i][1], acc[i][2], acc[i][3]);
        *(float4*)(Cb + (size_t)i * DMODEL + 4) = make_float4(acc[i][4], acc[i][5], acc[i][6], acc[i][7]);
    }
}

// ---------------------------------------------------------------------------
// Logits: S[b,t,s] = (Q[b,t] . K[b,s]) / 16, mel_mask -> -1e30
// grid(16, 4, 16) = (S/128, T/128, B), 256 thr. Writes into attn region.
// mel_mask is int32 (bool widened by harness).
// ---------------------------------------------------------------------------
__global__ void __launch_bounds__(256) qk_kernel(
    const int* __restrict__ mel_mask, float* __restrict__ attn)
{
    __shared__ float As[BK][BM + 4];
    __shared__ float Bs[BK][BN + 4];
    const int tid = threadIdx.x;
    const int tx = tid & 15, ty = tid >> 4;
    const int b = blockIdx.z;
    const float* Ab = Qbuf + ((size_t)b * SRC_LEN + blockIdx.y * BM) * DMODEL;
    const float* Bb = Kbuf + ((size_t)b * MEL_LEN + blockIdx.x * BN) * DMODEL;
    const int lr = tid >> 2, lc = (tid & 3) << 2;

    float acc[TM][TN] = {};

    for (int k0 = 0; k0 < DMODEL; k0 += BK) {
        #pragma unroll
        for (int r = 0; r < BM; r += 64) {
            float4 v = *(const float4*)(Ab + (size_t)(lr + r) * DMODEL + k0 + lc);
            As[lc + 0][lr + r] = v.x; As[lc + 1][lr + r] = v.y;
            As[lc + 2][lr + r] = v.z; As[lc + 3][lr + r] = v.w;
        }
        #pragma unroll
        for (int r = 0; r < BN; r += 64) {
            float4 v = *(const float4*)(Bb + (size_t)(lr + r) * DMODEL + k0 + lc);
            Bs[lc + 0][lr + r] = v.x; Bs[lc + 1][lr + r] = v.y;
            Bs[lc + 2][lr + r] = v.z; Bs[lc + 3][lr + r] = v.w;
        }
        __syncthreads();
        #pragma unroll
        for (int k = 0; k < BK; ++k) {
            float4 a0 = *(const float4*)&As[k][ty * TM];
            float4 a1 = *(const float4*)&As[k][ty * TM + 4];
            float4 b0 = *(const float4*)&Bs[k][tx * TN];
            float4 b1 = *(const float4*)&Bs[k][tx * TN + 4];
            float a[TM] = {a0.x, a0.y, a0.z, a0.w, a1.x, a1.y, a1.z, a1.w};
            float bv[TN] = {b0.x, b0.y, b0.z, b0.w, b1.x, b1.y, b1.z, b1.w};
            #pragma unroll
            for (int i = 0; i < TM; ++i)
                #pragma unroll
                for (int j = 0; j < TN; ++j)
                    acc[i][j] = fmaf(a[i], bv[j], acc[i][j]);
        }
        __syncthreads();
    }

    const int* mm = mel_mask + (size_t)b * MEL_LEN + blockIdx.x * BN + tx * TN;
    int mloc[TN];
    #pragma unroll
    for (int j = 0; j < TN; ++j) mloc[j] = mm[j];

    float* Cb = attn + ((size_t)b * SRC_LEN + blockIdx.y * BM + ty * TM) * MEL_LEN
                     + blockIdx.x * BN + tx * TN;
    #pragma unroll
    for (int i = 0; i < TM; ++i) {
        float r[TN];
        #pragma unroll
        for (int j = 0; j < TN; ++j) {
            float v = acc[i][j] * 0.0625f;   // 1/sqrt(256)
            r[j] = mloc[j] ? -1e30f : v;
        }
        *(float4*)(Cb + (size_t)i * MEL_LEN)     = make_float4(r[0], r[1], r[2], r[3]);
        *(float4*)(Cb + (size_t)i * MEL_LEN + 4) = make_float4(r[4], r[5], r[6], r[7]);
    }
}

// ---------------------------------------------------------------------------
// Row softmax over 2048 keys, in place; src_mask (int32) zeroes the row.
// grid(B*T), 256 thr
// ---------------------------------------------------------------------------
__global__ void __launch_bounds__(256) softmax_kernel(
    float* __restrict__ attn, const int* __restrict__ src_mask)
{
    const int row = blockIdx.x;                 // 0..8191
    const int tid = threadIdx.x;
    float* p = attn + (size_t)row * MEL_LEN;

    float v[8];
    float m = -3.0e38f;
    #pragma unroll
    for (int i = 0; i < 8; ++i) { v[i] = p[tid + i * 256]; m = fmaxf(m, v[i]); }

    __shared__ float red[9];
    #pragma unroll
    for (int o = 16; o > 0; o >>= 1) m = fmaxf(m, __shfl_xor_sync(0xffffffffu, m, o));
    if ((tid & 31) == 0) red[tid >> 5] = m;
    __syncthreads();
    if (tid == 0) {
        float mm = red[0];
        #pragma unroll
        for (int i = 1; i < 8; ++i) mm = fmaxf(mm, red[i]);
        red[8] = mm;
    }
    __syncthreads();
    m = red[8];

    float s = 0.0f;
    #pragma unroll
    for (int i = 0; i < 8; ++i) { v[i] = expf(v[i] - m); s += v[i]; }
    #pragma unroll
    for (int o = 16; o > 0; o >>= 1) s += __shfl_xor_sync(0xffffffffu, s, o);
    __syncthreads();
    if ((tid & 31) == 0) red[tid >> 5] = s;
    __syncthreads();
    if (tid == 0) {
        float ss = 0.0f;
        #pragma unroll
        for (int i = 0; i < 8; ++i) ss += red[i];
        red[8] = ss;
    }
    __syncthreads();
    s = red[8];

    const float z = src_mask[row] ? 0.0f : (1.0f / s);
    #pragma unroll
    for (int i = 0; i < 8; ++i) p[tid + i * 256] = v[i] * z;
}

// ---------------------------------------------------------------------------
// O = P @ V : per batch M=512, N=256, K=2048. grid(2, 4, 16), 256 thr
// ---------------------------------------------------------------------------
__global__ void __launch_bounds__(256) pv_kernel(
    const float* __restrict__ attn, float* __restrict__ outp)
{
    __shared__ float As[BK][BM + 4];
    __shared__ float Bs[BK][BN + 4];
    const int tid = threadIdx.x;
    const int tx = tid & 15, ty = tid >> 4;
    const int b = blockIdx.z;
    const float* Ab = attn + ((size_t)b * SRC_LEN + blockIdx.y * BM) * MEL_LEN;
    const float* Bb = Vbuf + (size_t)b * MEL_LEN * DMODEL + blockIdx.x * BN;
    const int lr = tid >> 2, lc = (tid & 3) << 2;   // A loader
    const int br = tid >> 5, bc = (tid & 31) << 2;  // B loader (row-major [K,N])

    float acc[TM][TN] = {};

    for (int k0 = 0; k0 < MEL_LEN; k0 += BK) {
        #pragma unroll
        for (int r = 0; r < BM; r += 64) {
            float4 v = *(const float4*)(Ab + (size_t)(lr + r) * MEL_LEN + k0 + lc);
            As[lc + 0][lr + r] = v.x; As[lc + 1][lr + r] = v.y;
            As[lc + 2][lr + r] = v.z; As[lc + 3][lr + r] = v.w;
        }
        #pragma unroll
        for (int r = 0; r < BK; r += 8) {
            float4 v = *(const float4*)(Bb + (size_t)(k0 + br + r) * DMODEL + bc);
            *(float4*)&Bs[br + r][bc] = v;
        }
        __syncthreads();
        #pragma unroll
        for (int k = 0; k < BK; ++k) {
            float4 a0 = *(const float4*)&As[k][ty * TM];
            float4 a1 = *(const float4*)&As[k][ty * TM + 4];
            float4 b0 = *(const float4*)&Bs[k][tx * TN];
            float4 b1 = *(const float4*)&Bs[k][tx * TN + 4];
            float a[TM] = {a0.x, a0.y, a0.z, a0.w, a1.x, a1.y, a1.z, a1.w};
            float bv[TN] = {b0.x, b0.y, b0.z, b0.w, b1.x, b1.y, b1.z, b1.w};
            #pragma unroll
            for (int i = 0; i < TM; ++i)
                #pragma unroll
                for (int j = 0; j < TN; ++j)
                    acc[i][j] = fmaf(a[i], bv[j], acc[i][j]);
        }
        __syncthreads();
    }

    float* Cb = outp + ((size_t)b * SRC_LEN + blockIdx.y * BM + ty * TM) * DMODEL
                     + blockIdx.x * BN + tx * TN;
    #pragma unroll
    for (int i = 0; i < TM; ++i) {
        *(float4*)(Cb + (size_t)i * DMODEL)     = make_float4(acc[i][0], acc[i][1], acc[i][2], acc[i][3]);
        *(float4*)(Cb + (size_t)i * DMODEL + 4) = make_float4(acc[i][4], acc[i][5], acc[i][6], acc[i][7]);
    }
}

// ---------------------------------------------------------------------------
// LayerNorm over last dim (256), in place. grid(B*T), 256 thr
// ---------------------------------------------------------------------------
__global__ void __launch_bounds__(256) ln_kernel(
    float* __restrict__ o, const float* __restrict__ gamma, const float* __restrict__ beta)
{
    const int row = blockIdx.x;
    const int tid = threadIdx.x;
    float* x = o + (size_t)row * DMODEL;
    float v = x[tid];

    __shared__ float red[9];
    float s = v;
    #pragma unroll
    for (int off = 16; off > 0; off >>= 1) s += __shfl_xor_sync(0xffffffffu, s, off);
    if ((tid & 31) == 0) red[tid >> 5] = s;
    __syncthreads();
    if (tid == 0) {
        float ss = 0.0f;
        #pragma unroll
        for (int i = 0; i < 8; ++i) ss += red[i];
        red[8] = ss * (1.0f / DMODEL);
    }
    __syncthreads();
    const float mu = red[8];
    __syncthreads();

    float d = v - mu;
    float q = d * d;
    #pragma unroll
    for (int off = 16; off > 0; off >>= 1) q += __shfl_xor_sync(0xffffffffu, q, off);
    if ((tid & 31) == 0) red[tid >> 5] = q;
    __syncthreads();
    if (tid == 0) {
        float qq = 0.0f;
        #pragma unroll
        for (int i = 0; i < 8; ++i) qq += red[i];
        red[8] = rsqrtf(qq * (1.0f / DMODEL) + 1e-5f);
    }
    __syncthreads();
    x[tid] = d * red[8] * gamma[tid] + beta[tid];
}

// ---------------------------------------------------------------------------
extern "C" void kernel_launch(void* const* d_in, const int* in_sizes, int n_in,
                              void* d_out, int out_size)
{
    const float* mel      = (const float*)d_in[0];   // [16,2048,256]
    const float* text     = (const float*)d_in[1];   // [16,512,256]
    const int*   mel_mask = (const int*)d_in[2];     // [16,2048] bool->int32
    const int*   src_mask = (const int*)d_in[3];     // [16,512]  bool->int32
    const float* Wq       = (const float*)d_in[4];   // [256,256]
    const float* Wk       = (const float*)d_in[5];
    const float* Wv       = (const float*)d_in[6];
    const float* gamma    = (const float*)d_in[7];
    const float* beta     = (const float*)d_in[8];

    float* out       = (float*)d_out;
    float* out_o     = out;                                    // [16,512,256]
    float* out_attn  = out + (size_t)BATCH * SRC_LEN * DMODEL; // [16,512,2048]

    float *qb, *kb, *vb;
    cudaGetSymbolAddress((void**)&qb, Qbuf);
    cudaGetSymbolAddress((void**)&kb, Kbuf);
    cudaGetSymbolAddress((void**)&vb, Vbuf);

    // Projections
    proj_kernel<<<dim3(2, (BATCH * SRC_LEN) / BM), 256>>>(text, Wq, qb);
    proj_kernel<<<dim3(2, (BATCH * MEL_LEN) / BM), 256>>>(mel, Wk, kb);
    proj_kernel<<<dim3(2, (BATCH * MEL_LEN) / BM), 256>>>(mel, Wv, vb);

    // Logits + mel mask (into attn output region)
    qk_kernel<<<dim3(MEL_LEN / BN, SRC_LEN / BM, BATCH), 256>>>(mel_mask, out_attn);

    // Softmax + src mask (in place)
    softmax_kernel<<<BATCH * SRC_LEN, 256>>>(out_attn, src_mask);

    // P @ V
    pv_kernel<<<dim3(DMODEL / BN, SRC_LEN / BM, BATCH), 256>>>(out_attn, out_o);

    // LayerNorm (in place)
    ln_kernel<<<BATCH * SRC_LEN, 256>>>(out_o, gamma, beta);
}

// round 4
// speedup vs baseline: 1.9892x; 1.9892x over previous
#include <cuda_runtime.h>
#include <cuda_bf16.h>
#include <math.h>
#include <stdint.h>

#define BATCH   16
#define SRC_LEN 512
#define MEL_LEN 2048
#define DMODEL  256

// ---------------------------------------------------------------------------
// Device-global scratch
// ---------------------------------------------------------------------------
__device__ __nv_bfloat16 Thi[BATCH * SRC_LEN * DMODEL], Tlo[BATCH * SRC_LEN * DMODEL];
__device__ __nv_bfloat16 Mhi[BATCH * MEL_LEN * DMODEL], Mlo[BATCH * MEL_LEN * DMODEL];
__device__ __nv_bfloat16 Wqhi[DMODEL * DMODEL], Wqlo[DMODEL * DMODEL];
__device__ __nv_bfloat16 Wkhi[DMODEL * DMODEL], Wklo[DMODEL * DMODEL];
__device__ __nv_bfloat16 Wvhi[DMODEL * DMODEL], Wvlo[DMODEL * DMODEL];
__device__ __nv_bfloat16 Qhi[BATCH * SRC_LEN * DMODEL], Qlo[BATCH * SRC_LEN * DMODEL];
__device__ __nv_bfloat16 Khi[BATCH * MEL_LEN * DMODEL], Klo[BATCH * MEL_LEN * DMODEL];
__device__ __nv_bfloat16 Vhi[BATCH * MEL_LEN * DMODEL], Vlo[BATCH * MEL_LEN * DMODEL]; // [b][s][m]
__device__ __nv_bfloat16 Phi[BATCH * SRC_LEN * MEL_LEN], Plo[BATCH * SRC_LEN * MEL_LEN];

// ---------------------------------------------------------------------------
// PTX helpers (base sm_80+ features only: mma.sync / ldmatrix / cp.async)
// ---------------------------------------------------------------------------
__device__ __forceinline__ uint32_t smem_u32(const void* p) {
    uint32_t a;
    asm("{ .reg .u64 t; cvta.to.shared.u64 t, %1; cvt.u32.u64 %0, t; }" : "=r"(a) : "l"(p));
    return a;
}
__device__ __forceinline__ void cp16(uint32_t s, const void* g) {
    asm volatile("cp.async.cg.shared.global [%0], [%1], 16;"
                 :: "r"(s), "l"(__cvta_generic_to_global(g)));
}
#define CP_COMMIT() asm volatile("cp.async.commit_group;" ::: "memory")
#define CP_WAIT1()  asm volatile("cp.async.wait_group 1;" ::: "memory")

__device__ __forceinline__ void ldsm_x4(uint32_t* r, uint32_t a) {
    asm volatile("ldmatrix.sync.aligned.m8n8.x4.shared.b16 {%0,%1,%2,%3}, [%4];"
                 : "=r"(r[0]), "=r"(r[1]), "=r"(r[2]), "=r"(r[3]) : "r"(a));
}
__device__ __forceinline__ void ldsm_x2t(uint32_t* r, uint32_t a) {
    asm volatile("ldmatrix.sync.aligned.m8n8.x2.trans.shared.b16 {%0,%1}, [%2];"
                 : "=r"(r[0]), "=r"(r[1]) : "r"(a));
}
__device__ __forceinline__ void mma16816(float* c, const uint32_t* a, const uint32_t* b) {
    asm volatile(
        "mma.sync.aligned.m16n8k16.row.col.f32.bf16.bf16.f32 "
        "{%0,%1,%2,%3}, {%4,%5,%6,%7}, {%8,%9}, {%0,%1,%2,%3};"
        : "+f"(c[0]), "+f"(c[1]), "+f"(c[2]), "+f"(c[3])
        : "r"(a[0]), "r"(a[1]), "r"(a[2]), "r"(a[3]), "r"(b[0]), "r"(b[1]));
}

// ---------------------------------------------------------------------------
// fp32 -> (bf16 hi, bf16 lo) elementwise split
// ---------------------------------------------------------------------------
__global__ void __launch_bounds__(256) split_kernel(
    const float* __restrict__ x, __nv_bfloat16* __restrict__ hi,
    __nv_bfloat16* __restrict__ lo, int n)
{
    int i = blockIdx.x * 256 + threadIdx.x;
    if (i < n) {
        float v = x[i];
        __nv_bfloat16 h = __float2bfloat16(v);
        hi[i] = h;
        lo[i] = __float2bfloat16(v - __bfloat162float(h));
    }
}

// ---------------------------------------------------------------------------
// Split-bf16 3-term mma.sync GEMM. Block tile 128x128x32, 8 warps (2x4),
// warp tile 64x32. A row-major [m][k]; B: MODE!=3 -> [n][k]; MODE==3 -> [k][n]
// (V, loaded with ldmatrix.trans). 3-stage cp.async pipeline.
// MODE 0: split bf16 out (ld=DMODEL)
// MODE 2: *1/16 + mel-mask -> fp32 logits (ld=MEL_LEN)
// MODE 3: fp32 out (ld=DMODEL)
// ---------------------------------------------------------------------------
#define NSTAGE 3
#define STG_BYTES 40960
#define GEMM_SMEM (NSTAGE * STG_BYTES)

template <int MODE>
__global__ void __launch_bounds__(256) gemm_mma(
    const __nv_bfloat16* __restrict__ Ah, const __nv_bfloat16* __restrict__ Al,
    const __nv_bfloat16* __restrict__ Bh, const __nv_bfloat16* __restrict__ Bl,
    int K, long long strideAz, long long strideBz,
    float* __restrict__ outF,
    __nv_bfloat16* __restrict__ outHi, __nv_bfloat16* __restrict__ outLo,
    const int* __restrict__ mask)
{
    extern __shared__ char smem[];
    const uint32_t sb = smem_u32(smem);
    const int tid = threadIdx.x;
    const int wid = tid >> 5, lane = tid & 31;
    const int warp_m = wid & 1, warp_n = wid >> 1;
    const int z = blockIdx.z;
    const int n0 = blockIdx.x * 128;

    const __nv_bfloat16* gAh = Ah + (size_t)z * strideAz + (size_t)blockIdx.y * 128 * K;
    const __nv_bfloat16* gAl = Al + (size_t)z * strideAz + (size_t)blockIdx.y * 128 * K;
    const __nv_bfloat16* gBh = Bh + (size_t)z * strideBz;
    const __nv_bfloat16* gBl = Bl + (size_t)z * strideBz;
    if (MODE == 3) { gBh += n0; gBl += n0; }
    else           { gBh += (size_t)n0 * K; gBl += (size_t)n0 * K; }

    const int kiters = K >> 5;

    auto load_stage = [&](int stg, int kc) {
        const uint32_t sbase = sb + (uint32_t)stg * STG_BYTES;
        const int k0 = kc << 5;
        #pragma unroll
        for (int i = 0; i < 2; ++i) {
            int q = tid + i * 256;
            int r = q >> 2, c = q & 3;
            uint32_t so = sbase + r * 80 + c * 16;
            size_t g = (size_t)r * K + k0 + c * 8;
            cp16(so, gAh + g);
            cp16(so + 10240u, gAl + g);
        }
        if (MODE == 3) {
            #pragma unroll
            for (int i = 0; i < 2; ++i) {
                int q = tid + i * 256;
                int r = q >> 4, c = q & 15;
                uint32_t so = sbase + 20480u + r * 272 + c * 16;
                size_t g = (size_t)(k0 + r) * DMODEL + c * 8;
                cp16(so, gBh + g);
                cp16(so + 10240u, gBl + g);
            }
        } else {
            #pragma unroll
            for (int i = 0; i < 2; ++i) {
                int q = tid + i * 256;
                int r = q >> 2, c = q & 3;
                uint32_t so = sbase + 20480u + r * 80 + c * 16;
                size_t g = (size_t)r * K + k0 + c * 8;
                cp16(so, gBh + g);
                cp16(so + 10240u, gBl + g);
            }
        }
    };

    float acc[4][4][4] = {};

    load_stage(0, 0); CP_COMMIT();
    load_stage(1, 1); CP_COMMIT();

    for (int kc = 0; kc < kiters; ++kc) {
        CP_WAIT1();
        __syncthreads();
        // prefetch kc+2 (overwrites stage computed in iter kc-1; all done by sync)
        if (kc + 2 < kiters) load_stage((kc + 2) % NSTAGE, kc + 2);
        CP_COMMIT();

        const uint32_t sbase = sb + (uint32_t)(kc % NSTAGE) * STG_BYTES;
        #pragma unroll
        for (int ks = 0; ks < 2; ++ks) {
            uint32_t a_hi[4][4], a_lo[4][4], b_hi[4][2], b_lo[4][2];
            #pragma unroll
            for (int mt = 0; mt < 4; ++mt) {
                int row = warp_m * 64 + mt * 16 + (lane & 15);
                uint32_t ad = sbase + row * 80 + ks * 32 + ((lane >> 4) << 4);
                ldsm_x4(a_hi[mt], ad);
                ldsm_x4(a_lo[mt], ad + 10240u);
            }
            if (MODE == 3) {
                #pragma unroll
                for (int nt = 0; nt < 4; ++nt) {
                    uint32_t ad = sbase + 20480u + (ks * 16 + (lane & 15)) * 272
                                + (warp_n * 32 + nt * 8) * 2;
                    ldsm_x2t(b_hi[nt], ad);
                    ldsm_x2t(b_lo[nt], ad + 10240u);
                }
            } else {
                #pragma unroll
                for (int h = 0; h < 2; ++h) {
                    // lanes: 0-7 -> (n 0-7, k0-7), 8-15 -> (n 0-7, k8-15),
                    //        16-23 -> (n 8-15, k0-7), 24-31 -> (n 8-15, k8-15)
                    int row = warp_n * 32 + h * 16 + ((lane >> 4) << 3) + (lane & 7);
                    uint32_t ad = sbase + 20480u + row * 80 + ks * 32 + (((lane >> 3) & 1) << 4);
                    uint32_t rh[4], rl[4];
                    ldsm_x4(rh, ad);
                    ldsm_x4(rl, ad + 10240u);
                    b_hi[h * 2][0] = rh[0]; b_hi[h * 2][1] = rh[1];
                    b_hi[h * 2 + 1][0] = rh[2]; b_hi[h * 2 + 1][1] = rh[3];
                    b_lo[h * 2][0] = rl[0]; b_lo[h * 2][1] = rl[1];
                    b_lo[h * 2 + 1][0] = rl[2]; b_lo[h * 2 + 1][1] = rl[3];
                }
            }
            #pragma unroll
            for (int mt = 0; mt < 4; ++mt)
                #pragma unroll
                for (int nt = 0; nt < 4; ++nt) {
                    mma16816(acc[mt][nt], a_hi[mt], b_hi[nt]);
                    mma16816(acc[mt][nt], a_hi[mt], b_lo[nt]);
                    mma16816(acc[mt][nt], a_lo[mt], b_hi[nt]);
                }
        }
    }

    // Epilogue: direct stores. d-frag: c0,c1 -> (r0, c0..c0+1); c2,c3 -> (r0+8, ..)
    const int gId = lane >> 2, t4 = lane & 3;
    const int rowB = blockIdx.y * 128 + warp_m * 64 + gId;

    #pragma unroll
    for (int mt = 0; mt < 4; ++mt) {
        #pragma unroll
        for (int nt = 0; nt < 4; ++nt) {
            const int col = n0 + warp_n * 32 + nt * 8 + t4 * 2;
            const int r0 = rowB + mt * 16;
            float* cc = acc[mt][nt];
            if (MODE == 2) {
                const int* mk = mask + z * MEL_LEN + col;
                const int m0 = mk[0], m1 = mk[1];
                float* O = outF + (size_t)z * SRC_LEN * MEL_LEN;
                float2 v0, v1;
                v0.x = m0 ? -1e30f : cc[0] * 0.0625f;
                v0.y = m1 ? -1e30f : cc[1] * 0.0625f;
                v1.x = m0 ? -1e30f : cc[2] * 0.0625f;
                v1.y = m1 ? -1e30f : cc[3] * 0.0625f;
                *(float2*)(O + (size_t)r0 * MEL_LEN + col) = v0;
                *(float2*)(O + (size_t)(r0 + 8) * MEL_LEN + col) = v1;
            } else if (MODE == 3) {
                float* O = outF + (size_t)z * SRC_LEN * DMODEL;
                *(float2*)(O + (size_t)r0 * DMODEL + col) = make_float2(cc[0], cc[1]);
                *(float2*)(O + (size_t)(r0 + 8) * DMODEL + col) = make_float2(cc[2], cc[3]);
            } else {
                #pragma unroll
                for (int h = 0; h < 2; ++h) {
                    size_t o = (size_t)(r0 + h * 8) * DMODEL + col;
                    float v0 = cc[h * 2], v1 = cc[h * 2 + 1];
                    __nv_bfloat16 h0 = __float2bfloat16(v0);
                    __nv_bfloat16 h1 = __float2bfloat16(v1);
                    __nv_bfloat162 hh; hh.x = h0; hh.y = h1;
                    __nv_bfloat162 ll;
                    ll.x = __float2bfloat16(v0 - __bfloat162float(h0));
                    ll.y = __float2bfloat16(v1 - __bfloat162float(h1));
                    *(__nv_bfloat162*)(outHi + o) = hh;
                    *(__nv_bfloat162*)(outLo + o) = ll;
                }
            }
        }
    }
}

// ---------------------------------------------------------------------------
// Row softmax over 2048 keys (in place fp32) + split-bf16 emit for PV.
// ---------------------------------------------------------------------------
__global__ void __launch_bounds__(256) softmax_kernel(
    float* __restrict__ attn, const int* __restrict__ src_mask,
    __nv_bfloat16* __restrict__ phi, __nv_bfloat16* __restrict__ plo)
{
    const int row = blockIdx.x;
    const int tid = threadIdx.x;
    float* p = attn + (size_t)row * MEL_LEN;

    float v[8];
    float m = -3.0e38f;
    #pragma unroll
    for (int i = 0; i < 8; ++i) { v[i] = p[tid + i * 256]; m = fmaxf(m, v[i]); }

    __shared__ float red[9];
    #pragma unroll
    for (int o = 16; o > 0; o >>= 1) m = fmaxf(m, __shfl_xor_sync(0xffffffffu, m, o));
    if ((tid & 31) == 0) red[tid >> 5] = m;
    __syncthreads();
    if (tid == 0) {
        float mm = red[0];
        #pragma unroll
        for (int i = 1; i < 8; ++i) mm = fmaxf(mm, red[i]);
        red[8] = mm;
    }
    __syncthreads();
    m = red[8];

    float s = 0.0f;
    #pragma unroll
    for (int i = 0; i < 8; ++i) { v[i] = expf(v[i] - m); s += v[i]; }
    #pragma unroll
    for (int o = 16; o > 0; o >>= 1) s += __shfl_xor_sync(0xffffffffu, s, o);
    __syncthreads();
    if ((tid & 31) == 0) red[tid >> 5] = s;
    __syncthreads();
    if (tid == 0) {
        float ss = 0.0f;
        #pragma unroll
        for (int i = 0; i < 8; ++i) ss += red[i];
        red[8] = ss;
    }
    __syncthreads();
    s = red[8];

    const float zf = src_mask[row] ? 0.0f : (1.0f / s);
    __nv_bfloat16* ph = phi + (size_t)row * MEL_LEN;
    __nv_bfloat16* pl = plo + (size_t)row * MEL_LEN;
    #pragma unroll
    for (int i = 0; i < 8; ++i) {
        float pv = v[i] * zf;
        p[tid + i * 256] = pv;
        __nv_bfloat16 h = __float2bfloat16(pv);
        ph[tid + i * 256] = h;
        pl[tid + i * 256] = __float2bfloat16(pv - __bfloat162float(h));
    }
}

// ---------------------------------------------------------------------------
// LayerNorm over last dim (256), in place.
// ---------------------------------------------------------------------------
__global__ void __launch_bounds__(256) ln_kernel(
    float* __restrict__ o, const float* __restrict__ gamma, const float* __restrict__ beta)
{
    const int row = blockIdx.x;
    const int tid = threadIdx.x;
    float* x = o + (size_t)row * DMODEL;
    float v = x[tid];

    __shared__ float red[9];
    float s = v;
    #pragma unroll
    for (int off = 16; off > 0; off >>= 1) s += __shfl_xor_sync(0xffffffffu, s, off);
    if ((tid & 31) == 0) red[tid >> 5] = s;
    __syncthreads();
    if (tid == 0) {
        float ss = 0.0f;
        #pragma unroll
        for (int i = 0; i < 8; ++i) ss += red[i];
        red[8] = ss * (1.0f / DMODEL);
    }
    __syncthreads();
    const float mu = red[8];
    __syncthreads();

    float d = v - mu;
    float q = d * d;
    #pragma unroll
    for (int off = 16; off > 0; off >>= 1) q += __shfl_xor_sync(0xffffffffu, q, off);
    if ((tid & 31) == 0) red[tid >> 5] = q;
    __syncthreads();
    if (tid == 0) {
        float qq = 0.0f;
        #pragma unroll
        for (int i = 0; i < 8; ++i) qq += red[i];
        red[8] = rsqrtf(qq * (1.0f / DMODEL) + 1e-5f);
    }
    __syncthreads();
    x[tid] = d * red[8] * gamma[tid] + beta[tid];
}

// ---------------------------------------------------------------------------
extern "C" void kernel_launch(void* const* d_in, const int* in_sizes, int n_in,
                              void* d_out, int out_size)
{
    const float* mel      = (const float*)d_in[0];   // [16,2048,256]
    const float* text     = (const float*)d_in[1];   // [16,512,256]
    const int*   mel_mask = (const int*)d_in[2];     // [16,2048] int32
    const int*   src_mask = (const int*)d_in[3];     // [16,512]  int32
    const float* Wq       = (const float*)d_in[4];
    const float* Wk       = (const float*)d_in[5];
    const float* Wv       = (const float*)d_in[6];
    const float* gamma    = (const float*)d_in[7];
    const float* beta     = (const float*)d_in[8];

    float* out      = (float*)d_out;
    float* out_o    = out;                                      // [16,512,256]
    float* out_attn = out + (size_t)BATCH * SRC_LEN * DMODEL;   // [16,512,2048]

    __nv_bfloat16 *thi, *tlo, *mhi, *mlo, *wqh, *wql, *wkh, *wkl, *wvh, *wvl;
    __nv_bfloat16 *qhi, *qlo, *khi, *klo, *vhi, *vlo, *phi, *plo;
    cudaGetSymbolAddress((void**)&thi, Thi);  cudaGetSymbolAddress((void**)&tlo, Tlo);
    cudaGetSymbolAddress((void**)&mhi, Mhi);  cudaGetSymbolAddress((void**)&mlo, Mlo);
    cudaGetSymbolAddress((void**)&wqh, Wqhi); cudaGetSymbolAddress((void**)&wql, Wqlo);
    cudaGetSymbolAddress((void**)&wkh, Wkhi); cudaGetSymbolAddress((void**)&wkl, Wklo);
    cudaGetSymbolAddress((void**)&wvh, Wvhi); cudaGetSymbolAddress((void**)&wvl, Wvlo);
    cudaGetSymbolAddress((void**)&qhi, Qhi);  cudaGetSymbolAddress((void**)&qlo, Qlo);
    cudaGetSymbolAddress((void**)&khi, Khi);  cudaGetSymbolAddress((void**)&klo, Klo);
    cudaGetSymbolAddress((void**)&vhi, Vhi);  cudaGetSymbolAddress((void**)&vlo, Vlo);
    cudaGetSymbolAddress((void**)&phi, Phi);  cudaGetSymbolAddress((void**)&plo, Plo);

    cudaFuncSetAttribute(gemm_mma<0>, cudaFuncAttributeMaxDynamicSharedMemorySize, GEMM_SMEM);
    cudaFuncSetAttribute(gemm_mma<2>, cudaFuncAttributeMaxDynamicSharedMemorySize, GEMM_SMEM);
    cudaFuncSetAttribute(gemm_mma<3>, cudaFuncAttributeMaxDynamicSharedMemorySize, GEMM_SMEM);

    const int nText = BATCH * SRC_LEN * DMODEL;
    const int nMel  = BATCH * MEL_LEN * DMODEL;
    const int nW    = DMODEL * DMODEL;

    // 1) Split inputs & weights
    split_kernel<<<(nText + 255) / 256, 256>>>(text, thi, tlo, nText);
    split_kernel<<<(nMel + 255) / 256, 256>>>(mel, mhi, mlo, nMel);
    split_kernel<<<(nW + 255) / 256, 256>>>(Wq, wqh, wql, nW);
    split_kernel<<<(nW + 255) / 256, 256>>>(Wk, wkh, wkl, nW);
    split_kernel<<<(nW + 255) / 256, 256>>>(Wv, wvh, wvl, nW);

    // 2) Projections
    gemm_mma<0><<<dim3(2, 64, 1), 256, GEMM_SMEM>>>(
        thi, tlo, wqh, wql, DMODEL, 0, 0, nullptr, qhi, qlo, nullptr);
    gemm_mma<0><<<dim3(2, 256, 1), 256, GEMM_SMEM>>>(
        mhi, mlo, wkh, wkl, DMODEL, 0, 0, nullptr, khi, klo, nullptr);
    gemm_mma<0><<<dim3(2, 256, 1), 256, GEMM_SMEM>>>(
        mhi, mlo, wvh, wvl, DMODEL, 0, 0, nullptr, vhi, vlo, nullptr);

    // 3) Logits (scaled + mel-masked) -> fp32 attn region of d_out
    gemm_mma<2><<<dim3(MEL_LEN / 128, SRC_LEN / 128, BATCH), 256, GEMM_SMEM>>>(
        qhi, qlo, khi, klo, DMODEL,
        (long long)SRC_LEN * DMODEL, (long long)MEL_LEN * DMODEL,
        out_attn, nullptr, nullptr, mel_mask);

    // 4) Softmax + src mask + split-bf16 P emit
    softmax_kernel<<<BATCH * SRC_LEN, 256>>>(out_attn, src_mask, phi, plo);

    // 5) O = P @ V   (B = V [s][m], trans-ldmatrix path)
    gemm_mma<3><<<dim3(DMODEL / 128, SRC_LEN / 128, BATCH), 256, GEMM_SMEM>>>(
        phi, plo, vhi, vlo, MEL_LEN,
        (long long)SRC_LEN * MEL_LEN, (long long)MEL_LEN * DMODEL,
        out_o, nullptr, nullptr, nullptr);

    // 6) LayerNorm
    ln_kernel<<<BATCH * SRC_LEN, 256>>>(out_o, gamma, beta);
}

// round 6
// speedup vs baseline: 2.3393x; 1.1760x over previous
#include <cuda_runtime.h>
#include <cuda_bf16.h>
#include <cuda_fp16.h>
#include <math.h>
#include <stdint.h>

#define BATCH   16
#define SRC_LEN 512
#define MEL_LEN 2048
#define DMODEL  256

// ---------------------------------------------------------------------------
// Device-global scratch
// ---------------------------------------------------------------------------
__device__ __nv_bfloat16 Thi[BATCH * SRC_LEN * DMODEL], Tlo[BATCH * SRC_LEN * DMODEL];
__device__ __nv_bfloat16 Mhi[BATCH * MEL_LEN * DMODEL], Mlo[BATCH * MEL_LEN * DMODEL];
__device__ __nv_bfloat16 Wqhi[DMODEL * DMODEL], Wqlo[DMODEL * DMODEL];
__device__ __nv_bfloat16 Wkhi[DMODEL * DMODEL], Wklo[DMODEL * DMODEL];
__device__ __nv_bfloat16 Wvhi[DMODEL * DMODEL], Wvlo[DMODEL * DMODEL];
__device__ __nv_bfloat16 Qhi[BATCH * SRC_LEN * DMODEL], Qlo[BATCH * SRC_LEN * DMODEL];
__device__ __nv_bfloat16 Khi[BATCH * MEL_LEN * DMODEL], Klo[BATCH * MEL_LEN * DMODEL];
__device__ __half        Vf16[BATCH * MEL_LEN * DMODEL];           // [b][s][m] fp16
__device__ __half        Pf16[BATCH * SRC_LEN * MEL_LEN];          // [b][t][s] fp16

// ---------------------------------------------------------------------------
// PTX helpers (base sm_80+ features only)
// ---------------------------------------------------------------------------
__device__ __forceinline__ uint32_t smem_u32(const void* p) {
    uint32_t a;
    asm("{ .reg .u64 t; cvta.to.shared.u64 t, %1; cvt.u32.u64 %0, t; }" : "=r"(a) : "l"(p));
    return a;
}
__device__ __forceinline__ void cp16(uint32_t s, const void* g) {
    asm volatile("cp.async.cg.shared.global [%0], [%1], 16;"
                 :: "r"(s), "l"(__cvta_generic_to_global(g)));
}
#define CP_COMMIT() asm volatile("cp.async.commit_group;" ::: "memory")
#define CP_WAIT1()  asm volatile("cp.async.wait_group 1;" ::: "memory")

__device__ __forceinline__ void ldsm_x4(uint32_t* r, uint32_t a) {
    asm volatile("ldmatrix.sync.aligned.m8n8.x4.shared.b16 {%0,%1,%2,%3}, [%4];"
                 : "=r"(r[0]), "=r"(r[1]), "=r"(r[2]), "=r"(r[3]) : "r"(a));
}
__device__ __forceinline__ void ldsm_x2t(uint32_t* r, uint32_t a) {
    asm volatile("ldmatrix.sync.aligned.m8n8.x2.trans.shared.b16 {%0,%1}, [%2];"
                 : "=r"(r[0]), "=r"(r[1]) : "r"(a));
}
__device__ __forceinline__ void mma16816(float* c, const uint32_t* a, const uint32_t* b) {
    asm volatile(
        "mma.sync.aligned.m16n8k16.row.col.f32.bf16.bf16.f32 "
        "{%0,%1,%2,%3}, {%4,%5,%6,%7}, {%8,%9}, {%0,%1,%2,%3};"
        : "+f"(c[0]), "+f"(c[1]), "+f"(c[2]), "+f"(c[3])
        : "r"(a[0]), "r"(a[1]), "r"(a[2]), "r"(a[3]), "r"(b[0]), "r"(b[1]));
}
__device__ __forceinline__ void mma16816h(float* c, const uint32_t* a, const uint32_t* b) {
    asm volatile(
        "mma.sync.aligned.m16n8k16.row.col.f32.f16.f16.f32 "
        "{%0,%1,%2,%3}, {%4,%5,%6,%7}, {%8,%9}, {%0,%1,%2,%3};"
        : "+f"(c[0]), "+f"(c[1]), "+f"(c[2]), "+f"(c[3])
        : "r"(a[0]), "r"(a[1]), "r"(a[2]), "r"(a[3]), "r"(b[0]), "r"(b[1]));
}

// ---------------------------------------------------------------------------
// fp32 -> (bf16 hi, bf16 lo) elementwise split
// ---------------------------------------------------------------------------
__global__ void __launch_bounds__(256) split_kernel(
    const float* __restrict__ x, __nv_bfloat16* __restrict__ hi,
    __nv_bfloat16* __restrict__ lo, int n)
{
    int i = blockIdx.x * 256 + threadIdx.x;
    if (i < n) {
        float v = x[i];
        __nv_bfloat16 h = __float2bfloat16(v);
        hi[i] = h;
        lo[i] = __float2bfloat16(v - __bfloat162float(h));
    }
}

// ---------------------------------------------------------------------------
// Split-bf16 3-term mma.sync GEMM. Block 128x128x32, 8 warps (2x4),
// warp tile 64x32. A [m][k]; B [n][k]. 3-stage cp.async pipeline.
// MODE 0: split bf16 out (ld=DMODEL)       -> outHi/outLo
// MODE 1: fp16 single out (ld=DMODEL)      -> outH      (V projection)
// MODE 2: *1/16 + mel-mask fp32 logits     -> outF (+ mask)
// ---------------------------------------------------------------------------
#define NSTAGE 3
#define STG_BYTES 40960
#define GEMM_SMEM (NSTAGE * STG_BYTES)

template <int MODE>
__global__ void __launch_bounds__(256) gemm_mma(
    const __nv_bfloat16* __restrict__ Ah, const __nv_bfloat16* __restrict__ Al,
    const __nv_bfloat16* __restrict__ Bh, const __nv_bfloat16* __restrict__ Bl,
    int K, long long strideAz, long long strideBz,
    float* __restrict__ outF,
    __nv_bfloat16* __restrict__ outHi, __nv_bfloat16* __restrict__ outLo,
    __half* __restrict__ outH,
    const int* __restrict__ mask)
{
    extern __shared__ char smem[];
    const uint32_t sb = smem_u32(smem);
    const int tid = threadIdx.x;
    const int wid = tid >> 5, lane = tid & 31;
    const int warp_m = wid & 1, warp_n = wid >> 1;
    const int z = blockIdx.z;
    const int n0 = blockIdx.x * 128;

    const __nv_bfloat16* gAh = Ah + (size_t)z * strideAz + (size_t)blockIdx.y * 128 * K;
    const __nv_bfloat16* gAl = Al + (size_t)z * strideAz + (size_t)blockIdx.y * 128 * K;
    const __nv_bfloat16* gBh = Bh + (size_t)z * strideBz + (size_t)n0 * K;
    const __nv_bfloat16* gBl = Bl + (size_t)z * strideBz + (size_t)n0 * K;

    const int kiters = K >> 5;

    auto load_stage = [&](int stg, int kc) {
        const uint32_t sbase = sb + (uint32_t)stg * STG_BYTES;
        const int k0 = kc << 5;
        #pragma unroll
        for (int i = 0; i < 2; ++i) {
            int q = tid + i * 256;
            int r = q >> 2, c = q & 3;
            uint32_t so = sbase + r * 80 + c * 16;
            size_t g = (size_t)r * K + k0 + c * 8;
            cp16(so, gAh + g);
            cp16(so + 10240u, gAl + g);
            cp16(so + 20480u, gBh + g);
            cp16(so + 30720u, gBl + g);
        }
    };

    float acc[4][4][4] = {};

    load_stage(0, 0); CP_COMMIT();
    load_stage(1, 1); CP_COMMIT();

    for (int kc = 0; kc < kiters; ++kc) {
        CP_WAIT1();
        __syncthreads();
        if (kc + 2 < kiters) load_stage((kc + 2) % NSTAGE, kc + 2);
        CP_COMMIT();

        const uint32_t sbase = sb + (uint32_t)(kc % NSTAGE) * STG_BYTES;
        #pragma unroll
        for (int ks = 0; ks < 2; ++ks) {
            uint32_t a_hi[4][4], a_lo[4][4], b_hi[4][2], b_lo[4][2];
            #pragma unroll
            for (int mt = 0; mt < 4; ++mt) {
                int row = warp_m * 64 + mt * 16 + (lane & 15);
                uint32_t ad = sbase + row * 80 + ks * 32 + ((lane >> 4) << 4);
                ldsm_x4(a_hi[mt], ad);
                ldsm_x4(a_lo[mt], ad + 10240u);
            }
            #pragma unroll
            for (int h = 0; h < 2; ++h) {
                int row = warp_n * 32 + h * 16 + ((lane >> 4) << 3) + (lane & 7);
                uint32_t ad = sbase + 20480u + row * 80 + ks * 32 + (((lane >> 3) & 1) << 4);
                uint32_t rh[4], rl[4];
                ldsm_x4(rh, ad);
                ldsm_x4(rl, ad + 10240u);
                b_hi[h * 2][0] = rh[0]; b_hi[h * 2][1] = rh[1];
                b_hi[h * 2 + 1][0] = rh[2]; b_hi[h * 2 + 1][1] = rh[3];
                b_lo[h * 2][0] = rl[0]; b_lo[h * 2][1] = rl[1];
                b_lo[h * 2 + 1][0] = rl[2]; b_lo[h * 2 + 1][1] = rl[3];
            }
            #pragma unroll
            for (int mt = 0; mt < 4; ++mt)
                #pragma unroll
                for (int nt = 0; nt < 4; ++nt) {
                    mma16816(acc[mt][nt], a_hi[mt], b_hi[nt]);
                    mma16816(acc[mt][nt], a_hi[mt], b_lo[nt]);
                    mma16816(acc[mt][nt], a_lo[mt], b_hi[nt]);
                }
        }
    }

    const int gId = lane >> 2, t4 = lane & 3;
    const int rowB = blockIdx.y * 128 + warp_m * 64 + gId;

    #pragma unroll
    for (int mt = 0; mt < 4; ++mt) {
        #pragma unroll
        for (int nt = 0; nt < 4; ++nt) {
            const int col = n0 + warp_n * 32 + nt * 8 + t4 * 2;
            const int r0 = rowB + mt * 16;
            float* cc = acc[mt][nt];
            if (MODE == 2) {
                const int* mk = mask + z * MEL_LEN + col;
                const int m0 = mk[0], m1 = mk[1];
                float* O = outF + (size_t)z * SRC_LEN * MEL_LEN;
                float2 v0, v1;
                v0.x = m0 ? -1e30f : cc[0] * 0.0625f;
                v0.y = m1 ? -1e30f : cc[1] * 0.0625f;
                v1.x = m0 ? -1e30f : cc[2] * 0.0625f;
                v1.y = m1 ? -1e30f : cc[3] * 0.0625f;
                *(float2*)(O + (size_t)r0 * MEL_LEN + col) = v0;
                *(float2*)(O + (size_t)(r0 + 8) * MEL_LEN + col) = v1;
            } else if (MODE == 1) {
                #pragma unroll
                for (int h = 0; h < 2; ++h) {
                    size_t o = (size_t)(r0 + h * 8) * DMODEL + col;
                    __half2 hv;
                    hv.x = __float2half(cc[h * 2]);
                    hv.y = __float2half(cc[h * 2 + 1]);
                    *(__half2*)(outH + o) = hv;
                }
            } else {
                #pragma unroll
                for (int h = 0; h < 2; ++h) {
                    size_t o = (size_t)(r0 + h * 8) * DMODEL + col;
                    float v0 = cc[h * 2], v1 = cc[h * 2 + 1];
                    __nv_bfloat16 h0 = __float2bfloat16(v0);
                    __nv_bfloat16 h1 = __float2bfloat16(v1);
                    __nv_bfloat162 hh; hh.x = h0; hh.y = h1;
                    __nv_bfloat162 ll;
                    ll.x = __float2bfloat16(v0 - __bfloat162float(h0));
                    ll.y = __float2bfloat16(v1 - __bfloat162float(h1));
                    *(__nv_bfloat162*)(outHi + o) = hh;
                    *(__nv_bfloat162*)(outLo + o) = ll;
                }
            }
        }
    }
}

// ---------------------------------------------------------------------------
// PV GEMM: O[b] = P[b](fp16,[t][s]) @ V[b](fp16,[s][m]), single-term fp16 MMA.
// Block 128x128x32, 8 warps (2x4). B loaded [k][n] with ldmatrix.trans.
// ---------------------------------------------------------------------------
#define PV_STG 20480
#define PV_SMEM (NSTAGE * PV_STG)

__global__ void __launch_bounds__(256) gemm_pv(
    const __half* __restrict__ P, const __half* __restrict__ V,
    float* __restrict__ outF)
{
    extern __shared__ char smem[];
    const uint32_t sb = smem_u32(smem);
    const int tid = threadIdx.x;
    const int wid = tid >> 5, lane = tid & 31;
    const int warp_m = wid & 1, warp_n = wid >> 1;
    const int z = blockIdx.z;
    const int n0 = blockIdx.x * 128;
    const int K = MEL_LEN;

    const __half* gA = P + (size_t)z * SRC_LEN * MEL_LEN + (size_t)blockIdx.y * 128 * K;
    const __half* gB = V + (size_t)z * MEL_LEN * DMODEL + n0;

    const int kiters = K >> 5;   // 64

    auto load_stage = [&](int stg, int kc) {
        const uint32_t sbase = sb + (uint32_t)stg * PV_STG;
        const int k0 = kc << 5;
        #pragma unroll
        for (int i = 0; i < 2; ++i) {
            int q = tid + i * 256;
            int r = q >> 2, c = q & 3;                         // A: 128 rows x 4 chunks
            cp16(sbase + r * 80 + c * 16, gA + (size_t)r * K + k0 + c * 8);
        }
        #pragma unroll
        for (int i = 0; i < 2; ++i) {
            int q = tid + i * 256;
            int r = q >> 4, c = q & 15;                        // B: 32 rows x 16 chunks
            cp16(sbase + 10240u + r * 272 + c * 16, gB + (size_t)(k0 + r) * DMODEL + c * 8);
        }
    };

    float acc[4][4][4] = {};

    load_stage(0, 0); CP_COMMIT();
    load_stage(1, 1); CP_COMMIT();

    for (int kc = 0; kc < kiters; ++kc) {
        CP_WAIT1();
        __syncthreads();
        if (kc + 2 < kiters) load_stage((kc + 2) % NSTAGE, kc + 2);
        CP_COMMIT();

        const uint32_t sbase = sb + (uint32_t)(kc % NSTAGE) * PV_STG;
        #pragma unroll
        for (int ks = 0; ks < 2; ++ks) {
            uint32_t a[4][4], b[4][2];
            #pragma unroll
            for (int mt = 0; mt < 4; ++mt) {
                int row = warp_m * 64 + mt * 16 + (lane & 15);
                uint32_t ad = sbase + row * 80 + ks * 32 + ((lane >> 4) << 4);
                ldsm_x4(a[mt], ad);
            }
            #pragma unroll
            for (int nt = 0; nt < 4; ++nt) {
                uint32_t ad = sbase + 10240u + (ks * 16 + (lane & 15)) * 272
                            + (warp_n * 32 + nt * 8) * 2;
                ldsm_x2t(b[nt], ad);
            }
            #pragma unroll
            for (int mt = 0; mt < 4; ++mt)
                #pragma unroll
                for (int nt = 0; nt < 4; ++nt)
                    mma16816h(acc[mt][nt], a[mt], b[nt]);
        }
    }

    const int gId = lane >> 2, t4 = lane & 3;
    const int rowB = blockIdx.y * 128 + warp_m * 64 + gId;
    float* O = outF + (size_t)z * SRC_LEN * DMODEL;

    #pragma unroll
    for (int mt = 0; mt < 4; ++mt)
        #pragma unroll
        for (int nt = 0; nt < 4; ++nt) {
            const int col = n0 + warp_n * 32 + nt * 8 + t4 * 2;
            const int r0 = rowB + mt * 16;
            float* cc = acc[mt][nt];
            *(float2*)(O + (size_t)r0 * DMODEL + col) = make_float2(cc[0], cc[1]);
            *(float2*)(O + (size_t)(r0 + 8) * DMODEL + col) = make_float2(cc[2], cc[3]);
        }
}

// ---------------------------------------------------------------------------
// Row softmax over 2048 keys (in place fp32) + fp16 P emit for PV.
// ---------------------------------------------------------------------------
__global__ void __launch_bounds__(256) softmax_kernel(
    float* __restrict__ attn, const int* __restrict__ src_mask,
    __half* __restrict__ pf)
{
    const int row = blockIdx.x;
    const int tid = threadIdx.x;
    float* p = attn + (size_t)row * MEL_LEN;

    float v[8];
    float m = -3.0e38f;
    #pragma unroll
    for (int i = 0; i < 8; ++i) { v[i] = p[tid + i * 256]; m = fmaxf(m, v[i]); }

    __shared__ float red[9];
    #pragma unroll
    for (int o = 16; o > 0; o >>= 1) m = fmaxf(m, __shfl_xor_sync(0xffffffffu, m, o));
    if ((tid & 31) == 0) red[tid >> 5] = m;
    __syncthreads();
    if (tid == 0) {
        float mm = red[0];
        #pragma unroll
        for (int i = 1; i < 8; ++i) mm = fmaxf(mm, red[i]);
        red[8] = mm;
    }
    __syncthreads();
    m = red[8];

    float s = 0.0f;
    #pragma unroll
    for (int i = 0; i < 8; ++i) { v[i] = expf(v[i] - m); s += v[i]; }
    #pragma unroll
    for (int o = 16; o > 0; o >>= 1) s += __shfl_xor_sync(0xffffffffu, s, o);
    __syncthreads();
    if ((tid & 31) == 0) red[tid >> 5] = s;
    __syncthreads();
    if (tid == 0) {
        float ss = 0.0f;
        #pragma unroll
        for (int i = 0; i < 8; ++i) ss += red[i];
        red[8] = ss;
    }
    __syncthreads();
    s = red[8];

    const float zf = src_mask[row] ? 0.0f : (1.0f / s);
    __half* ph = pf + (size_t)row * MEL_LEN;
    #pragma unroll
    for (int i = 0; i < 8; ++i) {
        float pv = v[i] * zf;
        p[tid + i * 256] = pv;
        ph[tid + i * 256] = __float2half(pv);
    }
}

// ---------------------------------------------------------------------------
// LayerNorm over last dim (256), in place.
// ---------------------------------------------------------------------------
__global__ void __launch_bounds__(256) ln_kernel(
    float* __restrict__ o, const float* __restrict__ gamma, const float* __restrict__ beta)
{
    const int row = blockIdx.x;
    const int tid = threadIdx.x;
    float* x = o + (size_t)row * DMODEL;
    float v = x[tid];

    __shared__ float red[9];
    float s = v;
    #pragma unroll
    for (int off = 16; off > 0; off >>= 1) s += __shfl_xor_sync(0xffffffffu, s, off);
    if ((tid & 31) == 0) red[tid >> 5] = s;
    __syncthreads();
    if (tid == 0) {
        float ss = 0.0f;
        #pragma unroll
        for (int i = 0; i < 8; ++i) ss += red[i];
        red[8] = ss * (1.0f / DMODEL);
    }
    __syncthreads();
    const float mu = red[8];
    __syncthreads();

    float d = v - mu;
    float q = d * d;
    #pragma unroll
    for (int off = 16; off > 0; off >>= 1) q += __shfl_xor_sync(0xffffffffu, q, off);
    if ((tid & 31) == 0) red[tid >> 5] = q;
    __syncthreads();
    if (tid == 0) {
        float qq = 0.0f;
        #pragma unroll
        for (int i = 0; i < 8; ++i) qq += red[i];
        red[8] = rsqrtf(qq * (1.0f / DMODEL) + 1e-5f);
    }
    __syncthreads();
    x[tid] = d * red[8] * gamma[tid] + beta[tid];
}

// ---------------------------------------------------------------------------
extern "C" void kernel_launch(void* const* d_in, const int* in_sizes, int n_in,
                              void* d_out, int out_size)
{
    const float* mel      = (const float*)d_in[0];
    const float* text     = (const float*)d_in[1];
    const int*   mel_mask = (const int*)d_in[2];
    const int*   src_mask = (const int*)d_in[3];
    const float* Wq       = (const float*)d_in[4];
    const float* Wk       = (const float*)d_in[5];
    const float* Wv       = (const float*)d_in[6];
    const float* gamma    = (const float*)d_in[7];
    const float* beta     = (const float*)d_in[8];

    float* out      = (float*)d_out;
    float* out_o    = out;                                      // [16,512,256]
    float* out_attn = out + (size_t)BATCH * SRC_LEN * DMODEL;   // [16,512,2048]

    __nv_bfloat16 *thi, *tlo, *mhi, *mlo, *wqh, *wql, *wkh, *wkl, *wvh, *wvl;
    __nv_bfloat16 *qhi, *qlo, *khi, *klo;
    __half *vf16, *pf16;
    cudaGetSymbolAddress((void**)&thi, Thi);  cudaGetSymbolAddress((void**)&tlo, Tlo);
    cudaGetSymbolAddress((void**)&mhi, Mhi);  cudaGetSymbolAddress((void**)&mlo, Mlo);
    cudaGetSymbolAddress((void**)&wqh, Wqhi); cudaGetSymbolAddress((void**)&wql, Wqlo);
    cudaGetSymbolAddress((void**)&wkh, Wkhi); cudaGetSymbolAddress((void**)&wkl, Wklo);
    cudaGetSymbolAddress((void**)&wvh, Wvhi); cudaGetSymbolAddress((void**)&wvl, Wvlo);
    cudaGetSymbolAddress((void**)&qhi, Qhi);  cudaGetSymbolAddress((void**)&qlo, Qlo);
    cudaGetSymbolAddress((void**)&khi, Khi);  cudaGetSymbolAddress((void**)&klo, Klo);
    cudaGetSymbolAddress((void**)&vf16, Vf16);
    cudaGetSymbolAddress((void**)&pf16, Pf16);

    cudaFuncSetAttribute(gemm_mma<0>, cudaFuncAttributeMaxDynamicSharedMemorySize, GEMM_SMEM);
    cudaFuncSetAttribute(gemm_mma<1>, cudaFuncAttributeMaxDynamicSharedMemorySize, GEMM_SMEM);
    cudaFuncSetAttribute(gemm_mma<2>, cudaFuncAttributeMaxDynamicSharedMemorySize, GEMM_SMEM);
    cudaFuncSetAttribute(gemm_pv,     cudaFuncAttributeMaxDynamicSharedMemorySize, PV_SMEM);

    const int nText = BATCH * SRC_LEN * DMODEL;
    const int nMel  = BATCH * MEL_LEN * DMODEL;
    const int nW    = DMODEL * DMODEL;

    // 1) Split inputs & weights
    split_kernel<<<(nText + 255) / 256, 256>>>(text, thi, tlo, nText);
    split_kernel<<<(nMel + 255) / 256, 256>>>(mel, mhi, mlo, nMel);
    split_kernel<<<(nW + 255) / 256, 256>>>(Wq, wqh, wql, nW);
    split_kernel<<<(nW + 255) / 256, 256>>>(Wk, wkh, wkl, nW);
    split_kernel<<<(nW + 255) / 256, 256>>>(Wv, wvh, wvl, nW);

    // 2) Projections: Q, K (split bf16 out), V (3-term compute, fp16 out)
    gemm_mma<0><<<dim3(2, 64, 1), 256, GEMM_SMEM>>>(
        thi, tlo, wqh, wql, DMODEL, 0, 0, nullptr, qhi, qlo, nullptr, nullptr);
    gemm_mma<0><<<dim3(2, 256, 1), 256, GEMM_SMEM>>>(
        mhi, mlo, wkh, wkl, DMODEL, 0, 0, nullptr, khi, klo, nullptr, nullptr);
    gemm_mma<1><<<dim3(2, 256, 1), 256, GEMM_SMEM>>>(
        mhi, mlo, wvh, wvl, DMODEL, 0, 0, nullptr, nullptr, nullptr, vf16, nullptr);

    // 3) Logits (scaled + mel-masked) -> fp32 attn region of d_out
    gemm_mma<2><<<dim3(MEL_LEN / 128, SRC_LEN / 128, BATCH), 256, GEMM_SMEM>>>(
        qhi, qlo, khi, klo, DMODEL,
        (long long)SRC_LEN * DMODEL, (long long)MEL_LEN * DMODEL,
        out_attn, nullptr, nullptr, nullptr, mel_mask);

    // 4) Softmax + src mask + fp16 P emit
    softmax_kernel<<<BATCH * SRC_LEN, 256>>>(out_attn, src_mask, pf16);

    // 5) O = P @ V  (fp16 single-term)
    gemm_pv<<<dim3(DMODEL / 128, SRC_LEN / 128, BATCH), 256, PV_SMEM>>>(
        pf16, vf16, out_o);

    // 6) LayerNorm
    ln_kernel<<<BATCH * SRC_LEN, 256>>>(out_o, gamma, beta);
}

// round 7
// speedup vs baseline: 2.8826x; 1.2322x over previous
#include <cuda_runtime.h>
#include <cuda_bf16.h>
#include <cuda_fp16.h>
#include <math.h>
#include <stdint.h>

#define BATCH   16
#define SRC_LEN 512
#define MEL_LEN 2048
#define DMODEL  256

// ---------------------------------------------------------------------------
// Device-global scratch
// ---------------------------------------------------------------------------
__device__ __nv_bfloat16 Thi[BATCH * SRC_LEN * DMODEL], Tlo[BATCH * SRC_LEN * DMODEL];
__device__ __nv_bfloat16 Mhi[BATCH * MEL_LEN * DMODEL], Mlo[BATCH * MEL_LEN * DMODEL];
__device__ __nv_bfloat16 Wqhi[DMODEL * DMODEL], Wqlo[DMODEL * DMODEL];
__device__ __nv_bfloat16 Wkhi[DMODEL * DMODEL], Wklo[DMODEL * DMODEL];
__device__ __nv_bfloat16 Wvhi[DMODEL * DMODEL], Wvlo[DMODEL * DMODEL];
__device__ __half        Qf16[BATCH * SRC_LEN * DMODEL];    // [b][t][m]
__device__ __half        Kf16[BATCH * MEL_LEN * DMODEL];    // [b][s][m]
__device__ __half        Vf16[BATCH * MEL_LEN * DMODEL];    // [b][s][m]
__device__ __half        Pf16[BATCH * SRC_LEN * MEL_LEN];   // [b][t][s]

// ---------------------------------------------------------------------------
// PTX helpers (base sm_80+ features only)
// ---------------------------------------------------------------------------
__device__ __forceinline__ uint32_t smem_u32(const void* p) {
    uint32_t a;
    asm("{ .reg .u64 t; cvta.to.shared.u64 t, %1; cvt.u32.u64 %0, t; }" : "=r"(a) : "l"(p));
    return a;
}
__device__ __forceinline__ void cp16(uint32_t s, const void* g) {
    asm volatile("cp.async.cg.shared.global [%0], [%1], 16;"
                 :: "r"(s), "l"(__cvta_generic_to_global(g)));
}
#define CP_COMMIT() asm volatile("cp.async.commit_group;" ::: "memory")
#define CP_WAIT1()  asm volatile("cp.async.wait_group 1;" ::: "memory")

__device__ __forceinline__ void ldsm_x4(uint32_t* r, uint32_t a) {
    asm volatile("ldmatrix.sync.aligned.m8n8.x4.shared.b16 {%0,%1,%2,%3}, [%4];"
                 : "=r"(r[0]), "=r"(r[1]), "=r"(r[2]), "=r"(r[3]) : "r"(a));
}
__device__ __forceinline__ void ldsm_x2t(uint32_t* r, uint32_t a) {
    asm volatile("ldmatrix.sync.aligned.m8n8.x2.trans.shared.b16 {%0,%1}, [%2];"
                 : "=r"(r[0]), "=r"(r[1]) : "r"(a));
}
__device__ __forceinline__ void mma16816(float* c, const uint32_t* a, const uint32_t* b) {
    asm volatile(
        "mma.sync.aligned.m16n8k16.row.col.f32.bf16.bf16.f32 "
        "{%0,%1,%2,%3}, {%4,%5,%6,%7}, {%8,%9}, {%0,%1,%2,%3};"
        : "+f"(c[0]), "+f"(c[1]), "+f"(c[2]), "+f"(c[3])
        : "r"(a[0]), "r"(a[1]), "r"(a[2]), "r"(a[3]), "r"(b[0]), "r"(b[1]));
}
__device__ __forceinline__ void mma16816h(float* c, const uint32_t* a, const uint32_t* b) {
    asm volatile(
        "mma.sync.aligned.m16n8k16.row.col.f32.f16.f16.f32 "
        "{%0,%1,%2,%3}, {%4,%5,%6,%7}, {%8,%9}, {%0,%1,%2,%3};"
        : "+f"(c[0]), "+f"(c[1]), "+f"(c[2]), "+f"(c[3])
        : "r"(a[0]), "r"(a[1]), "r"(a[2]), "r"(a[3]), "r"(b[0]), "r"(b[1]));
}

// ---------------------------------------------------------------------------
// fp32 -> (bf16 hi, bf16 lo) elementwise split
// ---------------------------------------------------------------------------
__global__ void __launch_bounds__(256) split_kernel(
    const float* __restrict__ x, __nv_bfloat16* __restrict__ hi,
    __nv_bfloat16* __restrict__ lo, int n)
{
    int i = blockIdx.x * 256 + threadIdx.x;
    if (i < n) {
        float v = x[i];
        __nv_bfloat16 h = __float2bfloat16(v);
        hi[i] = h;
        lo[i] = __float2bfloat16(v - __bfloat162float(h));
    }
}

#define NSTAGE 3

// ---------------------------------------------------------------------------
// Projection GEMM: 3-term split-bf16 compute, fp16 output.
// Block 128x128x32, 8 warps (2x4), warp tile 64x32. A [m][k]; B [n][k].
// ---------------------------------------------------------------------------
#define PR_STG 40960
#define PR_SMEM (NSTAGE * PR_STG)

__global__ void __launch_bounds__(256) gemm_proj(
    const __nv_bfloat16* __restrict__ Ah, const __nv_bfloat16* __restrict__ Al,
    const __nv_bfloat16* __restrict__ Bh, const __nv_bfloat16* __restrict__ Bl,
    __half* __restrict__ outH)
{
    extern __shared__ char smem[];
    const uint32_t sb = smem_u32(smem);
    const int tid = threadIdx.x;
    const int wid = tid >> 5, lane = tid & 31;
    const int warp_m = wid & 1, warp_n = wid >> 1;
    const int n0 = blockIdx.x * 128;
    const int K = DMODEL;

    const __nv_bfloat16* gAh = Ah + (size_t)blockIdx.y * 128 * K;
    const __nv_bfloat16* gAl = Al + (size_t)blockIdx.y * 128 * K;
    const __nv_bfloat16* gBh = Bh + (size_t)n0 * K;
    const __nv_bfloat16* gBl = Bl + (size_t)n0 * K;

    const int kiters = K >> 5;   // 8

    auto load_stage = [&](int stg, int kc) {
        const uint32_t sbase = sb + (uint32_t)stg * PR_STG;
        const int k0 = kc << 5;
        #pragma unroll
        for (int i = 0; i < 2; ++i) {
            int q = tid + i * 256;
            int r = q >> 2, c = q & 3;
            uint32_t so = sbase + r * 80 + c * 16;
            size_t g = (size_t)r * K + k0 + c * 8;
            cp16(so, gAh + g);
            cp16(so + 10240u, gAl + g);
            cp16(so + 20480u, gBh + g);
            cp16(so + 30720u, gBl + g);
        }
    };

    float acc[4][4][4] = {};

    load_stage(0, 0); CP_COMMIT();
    load_stage(1, 1); CP_COMMIT();

    for (int kc = 0; kc < kiters; ++kc) {
        CP_WAIT1();
        __syncthreads();
        if (kc + 2 < kiters) load_stage((kc + 2) % NSTAGE, kc + 2);
        CP_COMMIT();

        const uint32_t sbase = sb + (uint32_t)(kc % NSTAGE) * PR_STG;
        #pragma unroll
        for (int ks = 0; ks < 2; ++ks) {
            uint32_t a_hi[4][4], a_lo[4][4], b_hi[4][2], b_lo[4][2];
            #pragma unroll
            for (int mt = 0; mt < 4; ++mt) {
                int row = warp_m * 64 + mt * 16 + (lane & 15);
                uint32_t ad = sbase + row * 80 + ks * 32 + ((lane >> 4) << 4);
                ldsm_x4(a_hi[mt], ad);
                ldsm_x4(a_lo[mt], ad + 10240u);
            }
            #pragma unroll
            for (int h = 0; h < 2; ++h) {
                int row = warp_n * 32 + h * 16 + ((lane >> 4) << 3) + (lane & 7);
                uint32_t ad = sbase + 20480u + row * 80 + ks * 32 + (((lane >> 3) & 1) << 4);
                uint32_t rh[4], rl[4];
                ldsm_x4(rh, ad);
                ldsm_x4(rl, ad + 10240u);
                b_hi[h * 2][0] = rh[0]; b_hi[h * 2][1] = rh[1];
                b_hi[h * 2 + 1][0] = rh[2]; b_hi[h * 2 + 1][1] = rh[3];
                b_lo[h * 2][0] = rl[0]; b_lo[h * 2][1] = rl[1];
                b_lo[h * 2 + 1][0] = rl[2]; b_lo[h * 2 + 1][1] = rl[3];
            }
            #pragma unroll
            for (int mt = 0; mt < 4; ++mt)
                #pragma unroll
                for (int nt = 0; nt < 4; ++nt) {
                    mma16816(acc[mt][nt], a_hi[mt], b_hi[nt]);
                    mma16816(acc[mt][nt], a_hi[mt], b_lo[nt]);
                    mma16816(acc[mt][nt], a_lo[mt], b_hi[nt]);
                }
        }
    }

    const int gId = lane >> 2, t4 = lane & 3;
    const int rowB = blockIdx.y * 128 + warp_m * 64 + gId;

    #pragma unroll
    for (int mt = 0; mt < 4; ++mt)
        #pragma unroll
        for (int nt = 0; nt < 4; ++nt) {
            const int col = n0 + warp_n * 32 + nt * 8 + t4 * 2;
            const int r0 = rowB + mt * 16;
            float* cc = acc[mt][nt];
            #pragma unroll
            for (int h = 0; h < 2; ++h) {
                size_t o = (size_t)(r0 + h * 8) * DMODEL + col;
                __half2 hv;
                hv.x = __float2half(cc[h * 2]);
                hv.y = __float2half(cc[h * 2 + 1]);
                *(__half2*)(outH + o) = hv;
            }
        }
}

// ---------------------------------------------------------------------------
// QK logits: fp16 single-term. A = Q [t][m], B = K [s][m] (both [.][k] layout).
// Epilogue: *1/16, mel-mask -> fp32 attn region. Block 128x128x32.
// ---------------------------------------------------------------------------
#define H_STG 20480
#define H_SMEM (NSTAGE * H_STG)

__global__ void __launch_bounds__(256) gemm_qk(
    const __half* __restrict__ Q, const __half* __restrict__ Kb,
    const int* __restrict__ mask, float* __restrict__ attn)
{
    extern __shared__ char smem[];
    const uint32_t sb = smem_u32(smem);
    const int tid = threadIdx.x;
    const int wid = tid >> 5, lane = tid & 31;
    const int warp_m = wid & 1, warp_n = wid >> 1;
    const int z = blockIdx.z;
    const int n0 = blockIdx.x * 128;
    const int K = DMODEL;

    const __half* gA = Q + (size_t)z * SRC_LEN * DMODEL + (size_t)blockIdx.y * 128 * K;
    const __half* gB = Kb + (size_t)z * MEL_LEN * DMODEL + (size_t)n0 * K;

    const int kiters = K >> 5;   // 8

    auto load_stage = [&](int stg, int kc) {
        const uint32_t sbase = sb + (uint32_t)stg * H_STG;
        const int k0 = kc << 5;
        #pragma unroll
        for (int i = 0; i < 2; ++i) {
            int q = tid + i * 256;
            int r = q >> 2, c = q & 3;
            uint32_t so = sbase + r * 80 + c * 16;
            size_t g = (size_t)r * K + k0 + c * 8;
            cp16(so, gA + g);
            cp16(so + 10240u, gB + g);
        }
    };

    float acc[4][4][4] = {};

    load_stage(0, 0); CP_COMMIT();
    load_stage(1, 1); CP_COMMIT();

    for (int kc = 0; kc < kiters; ++kc) {
        CP_WAIT1();
        __syncthreads();
        if (kc + 2 < kiters) load_stage((kc + 2) % NSTAGE, kc + 2);
        CP_COMMIT();

        const uint32_t sbase = sb + (uint32_t)(kc % NSTAGE) * H_STG;
        #pragma unroll
        for (int ks = 0; ks < 2; ++ks) {
            uint32_t a[4][4], b[4][2];
            #pragma unroll
            for (int mt = 0; mt < 4; ++mt) {
                int row = warp_m * 64 + mt * 16 + (lane & 15);
                uint32_t ad = sbase + row * 80 + ks * 32 + ((lane >> 4) << 4);
                ldsm_x4(a[mt], ad);
            }
            #pragma unroll
            for (int h = 0; h < 2; ++h) {
                int row = warp_n * 32 + h * 16 + ((lane >> 4) << 3) + (lane & 7);
                uint32_t ad = sbase + 10240u + row * 80 + ks * 32 + (((lane >> 3) & 1) << 4);
                uint32_t rr[4];
                ldsm_x4(rr, ad);
                b[h * 2][0] = rr[0]; b[h * 2][1] = rr[1];
                b[h * 2 + 1][0] = rr[2]; b[h * 2 + 1][1] = rr[3];
            }
            #pragma unroll
            for (int mt = 0; mt < 4; ++mt)
                #pragma unroll
                for (int nt = 0; nt < 4; ++nt)
                    mma16816h(acc[mt][nt], a[mt], b[nt]);
        }
    }

    const int gId = lane >> 2, t4 = lane & 3;
    const int rowB = blockIdx.y * 128 + warp_m * 64 + gId;
    float* O = attn + (size_t)z * SRC_LEN * MEL_LEN;

    #pragma unroll
    for (int mt = 0; mt < 4; ++mt)
        #pragma unroll
        for (int nt = 0; nt < 4; ++nt) {
            const int col = n0 + warp_n * 32 + nt * 8 + t4 * 2;
            const int r0 = rowB + mt * 16;
            const int* mk = mask + z * MEL_LEN + col;
            const int m0 = mk[0], m1 = mk[1];
            float* cc = acc[mt][nt];
            float2 v0, v1;
            v0.x = m0 ? -1e30f : cc[0] * 0.0625f;
            v0.y = m1 ? -1e30f : cc[1] * 0.0625f;
            v1.x = m0 ? -1e30f : cc[2] * 0.0625f;
            v1.y = m1 ? -1e30f : cc[3] * 0.0625f;
            *(float2*)(O + (size_t)r0 * MEL_LEN + col) = v0;
            *(float2*)(O + (size_t)(r0 + 8) * MEL_LEN + col) = v1;
        }
}

// ---------------------------------------------------------------------------
// PV GEMM: O[b] = P[b](fp16,[t][s]) @ V[b](fp16,[s][m]), single-term fp16 MMA.
// B loaded [k][n] with ldmatrix.trans.
// ---------------------------------------------------------------------------
__global__ void __launch_bounds__(256) gemm_pv(
    const __half* __restrict__ P, const __half* __restrict__ V,
    float* __restrict__ outF)
{
    extern __shared__ char smem[];
    const uint32_t sb = smem_u32(smem);
    const int tid = threadIdx.x;
    const int wid = tid >> 5, lane = tid & 31;
    const int warp_m = wid & 1, warp_n = wid >> 1;
    const int z = blockIdx.z;
    const int n0 = blockIdx.x * 128;
    const int K = MEL_LEN;

    const __half* gA = P + (size_t)z * SRC_LEN * MEL_LEN + (size_t)blockIdx.y * 128 * K;
    const __half* gB = V + (size_t)z * MEL_LEN * DMODEL + n0;

    const int kiters = K >> 5;   // 64

    auto load_stage = [&](int stg, int kc) {
        const uint32_t sbase = sb + (uint32_t)stg * H_STG;
        const int k0 = kc << 5;
        #pragma unroll
        for (int i = 0; i < 2; ++i) {
            int q = tid + i * 256;
            int r = q >> 2, c = q & 3;                         // A: 128 rows x 4 chunks
            cp16(sbase + r * 80 + c * 16, gA + (size_t)r * K + k0 + c * 8);
        }
        #pragma unroll
        for (int i = 0; i < 2; ++i) {
            int q = tid + i * 256;
            int r = q >> 4, c = q & 15;                        // B: 32 rows x 16 chunks
            cp16(sbase + 10240u + r * 272 + c * 16, gB + (size_t)(k0 + r) * DMODEL + c * 8);
        }
    };

    float acc[4][4][4] = {};

    load_stage(0, 0); CP_COMMIT();
    load_stage(1, 1); CP_COMMIT();

    for (int kc = 0; kc < kiters; ++kc) {
        CP_WAIT1();
        __syncthreads();
        if (kc + 2 < kiters) load_stage((kc + 2) % NSTAGE, kc + 2);
        CP_COMMIT();

        const uint32_t sbase = sb + (uint32_t)(kc % NSTAGE) * H_STG;
        #pragma unroll
        for (int ks = 0; ks < 2; ++ks) {
            uint32_t a[4][4], b[4][2];
            #pragma unroll
            for (int mt = 0; mt < 4; ++mt) {
                int row = warp_m * 64 + mt * 16 + (lane & 15);
                uint32_t ad = sbase + row * 80 + ks * 32 + ((lane >> 4) << 4);
                ldsm_x4(a[mt], ad);
            }
            #pragma unroll
            for (int nt = 0; nt < 4; ++nt) {
                uint32_t ad = sbase + 10240u + (ks * 16 + (lane & 15)) * 272
                            + (warp_n * 32 + nt * 8) * 2;
                ldsm_x2t(b[nt], ad);
            }
            #pragma unroll
            for (int mt = 0; mt < 4; ++mt)
                #pragma unroll
                for (int nt = 0; nt < 4; ++nt)
                    mma16816h(acc[mt][nt], a[mt], b[nt]);
        }
    }

    const int gId = lane >> 2, t4 = lane & 3;
    const int rowB = blockIdx.y * 128 + warp_m * 64 + gId;
    float* O = outF + (size_t)z * SRC_LEN * DMODEL;

    #pragma unroll
    for (int mt = 0; mt < 4; ++mt)
        #pragma unroll
        for (int nt = 0; nt < 4; ++nt) {
            const int col = n0 + warp_n * 32 + nt * 8 + t4 * 2;
            const int r0 = rowB + mt * 16;
            float* cc = acc[mt][nt];
            *(float2*)(O + (size_t)r0 * DMODEL + col) = make_float2(cc[0], cc[1]);
            *(float2*)(O + (size_t)(r0 + 8) * DMODEL + col) = make_float2(cc[2], cc[3]);
        }
}

// ---------------------------------------------------------------------------
// Row softmax over 2048 keys (in place fp32) + fp16 P emit for PV.
// ---------------------------------------------------------------------------
__global__ void __launch_bounds__(256) softmax_kernel(
    float* __restrict__ attn, const int* __restrict__ src_mask,
    __half* __restrict__ pf)
{
    const int row = blockIdx.x;
    const int tid = threadIdx.x;
    float* p = attn + (size_t)row * MEL_LEN;

    float v[8];
    float m = -3.0e38f;
    #pragma unroll
    for (int i = 0; i < 8; ++i) { v[i] = p[tid + i * 256]; m = fmaxf(m, v[i]); }

    __shared__ float red[9];
    #pragma unroll
    for (int o = 16; o > 0; o >>= 1) m = fmaxf(m, __shfl_xor_sync(0xffffffffu, m, o));
    if ((tid & 31) == 0) red[tid >> 5] = m;
    __syncthreads();
    if (tid == 0) {
        float mm = red[0];
        #pragma unroll
        for (int i = 1; i < 8; ++i) mm = fmaxf(mm, red[i]);
        red[8] = mm;
    }
    __syncthreads();
    m = red[8];

    float s = 0.0f;
    #pragma unroll
    for (int i = 0; i < 8; ++i) { v[i] = expf(v[i] - m); s += v[i]; }
    #pragma unroll
    for (int o = 16; o > 0; o >>= 1) s += __shfl_xor_sync(0xffffffffu, s, o);
    __syncthreads();
    if ((tid & 31) == 0) red[tid >> 5] = s;
    __syncthreads();
    if (tid == 0) {
        float ss = 0.0f;
        #pragma unroll
        for (int i = 0; i < 8; ++i) ss += red[i];
        red[8] = ss;
    }
    __syncthreads();
    s = red[8];

    const float zf = src_mask[row] ? 0.0f : (1.0f / s);
    __half* ph = pf + (size_t)row * MEL_LEN;
    #pragma unroll
    for (int i = 0; i < 8; ++i) {
        float pv = v[i] * zf;
        p[tid + i * 256] = pv;
        ph[tid + i * 256] = __float2half(pv);
    }
}

// ---------------------------------------------------------------------------
// LayerNorm over last dim (256), in place.
// ---------------------------------------------------------------------------
__global__ void __launch_bounds__(256) ln_kernel(
    float* __restrict__ o, const float* __restrict__ gamma, const float* __restrict__ beta)
{
    const int row = blockIdx.x;
    const int tid = threadIdx.x;
    float* x = o + (size_t)row * DMODEL;
    float v = x[tid];

    __shared__ float red[9];
    float s = v;
    #pragma unroll
    for (int off = 16; off > 0; off >>= 1) s += __shfl_xor_sync(0xffffffffu, s, off);
    if ((tid & 31) == 0) red[tid >> 5] = s;
    __syncthreads();
    if (tid == 0) {
        float ss = 0.0f;
        #pragma unroll
        for (int i = 0; i < 8; ++i) ss += red[i];
        red[8] = ss * (1.0f / DMODEL);
    }
    __syncthreads();
    const float mu = red[8];
    __syncthreads();

    float d = v - mu;
    float q = d * d;
    #pragma unroll
    for (int off = 16; off > 0; off >>= 1) q += __shfl_xor_sync(0xffffffffu, q, off);
    if ((tid & 31) == 0) red[tid >> 5] = q;
    __syncthreads();
    if (tid == 0) {
        float qq = 0.0f;
        #pragma unroll
        for (int i = 0; i < 8; ++i) qq += red[i];
        red[8] = rsqrtf(qq * (1.0f / DMODEL) + 1e-5f);
    }
    __syncthreads();
    x[tid] = d * red[8] * gamma[tid] + beta[tid];
}

// ---------------------------------------------------------------------------
extern "C" void kernel_launch(void* const* d_in, const int* in_sizes, int n_in,
                              void* d_out, int out_size)
{
    const float* mel      = (const float*)d_in[0];
    const float* text     = (const float*)d_in[1];
    const int*   mel_mask = (const int*)d_in[2];
    const int*   src_mask = (const int*)d_in[3];
    const float* Wq       = (const float*)d_in[4];
    const float* Wk       = (const float*)d_in[5];
    const float* Wv       = (const float*)d_in[6];
    const float* gamma    = (const float*)d_in[7];
    const float* beta     = (const float*)d_in[8];

    float* out      = (float*)d_out;
    float* out_o    = out;                                      // [16,512,256]
    float* out_attn = out + (size_t)BATCH * SRC_LEN * DMODEL;   // [16,512,2048]

    __nv_bfloat16 *thi, *tlo, *mhi, *mlo, *wqh, *wql, *wkh, *wkl, *wvh, *wvl;
    __half *qf16, *kf16, *vf16, *pf16;
    cudaGetSymbolAddress((void**)&thi, Thi);  cudaGetSymbolAddress((void**)&tlo, Tlo);
    cudaGetSymbolAddress((void**)&mhi, Mhi);  cudaGetSymbolAddress((void**)&mlo, Mlo);
    cudaGetSymbolAddress((void**)&wqh, Wqhi); cudaGetSymbolAddress((void**)&wql, Wqlo);
    cudaGetSymbolAddress((void**)&wkh, Wkhi); cudaGetSymbolAddress((void**)&wkl, Wklo);
    cudaGetSymbolAddress((void**)&wvh, Wvhi); cudaGetSymbolAddress((void**)&wvl, Wvlo);
    cudaGetSymbolAddress((void**)&qf16, Qf16);
    cudaGetSymbolAddress((void**)&kf16, Kf16);
    cudaGetSymbolAddress((void**)&vf16, Vf16);
    cudaGetSymbolAddress((void**)&pf16, Pf16);

    cudaFuncSetAttribute(gemm_proj, cudaFuncAttributeMaxDynamicSharedMemorySize, PR_SMEM);
    cudaFuncSetAttribute(gemm_qk,   cudaFuncAttributeMaxDynamicSharedMemorySize, H_SMEM);
    cudaFuncSetAttribute(gemm_pv,   cudaFuncAttributeMaxDynamicSharedMemorySize, H_SMEM);

    const int nText = BATCH * SRC_LEN * DMODEL;
    const int nMel  = BATCH * MEL_LEN * DMODEL;
    const int nW    = DMODEL * DMODEL;

    // 1) Split inputs & weights to (hi, lo) bf16
    split_kernel<<<(nText + 255) / 256, 256>>>(text, thi, tlo, nText);
    split_kernel<<<(nMel + 255) / 256, 256>>>(mel, mhi, mlo, nMel);
    split_kernel<<<(nW + 255) / 256, 256>>>(Wq, wqh, wql, nW);
    split_kernel<<<(nW + 255) / 256, 256>>>(Wk, wkh, wkl, nW);
    split_kernel<<<(nW + 255) / 256, 256>>>(Wv, wvh, wvl, nW);

    // 2) Projections: 3-term bf16 compute, fp16 out
    gemm_proj<<<dim3(2, 64), 256, PR_SMEM>>>(thi, tlo, wqh, wql, qf16);
    gemm_proj<<<dim3(2, 256), 256, PR_SMEM>>>(mhi, mlo, wkh, wkl, kf16);
    gemm_proj<<<dim3(2, 256), 256, PR_SMEM>>>(mhi, mlo, wvh, wvl, vf16);

    // 3) Logits: fp16 single-term, *1/16 + mel mask -> fp32 attn region
    gemm_qk<<<dim3(MEL_LEN / 128, SRC_LEN / 128, BATCH), 256, H_SMEM>>>(
        qf16, kf16, mel_mask, out_attn);

    // 4) Softmax + src mask + fp16 P emit
    softmax_kernel<<<BATCH * SRC_LEN, 256>>>(out_attn, src_mask, pf16);

    // 5) O = P @ V  (fp16 single-term)
    gemm_pv<<<dim3(DMODEL / 128, SRC_LEN / 128, BATCH), 256, H_SMEM>>>(
        pf16, vf16, out_o);

    // 6) LayerNorm
    ln_kernel<<<BATCH * SRC_LEN, 256>>>(out_o, gamma, beta);
}

// round 8
// speedup vs baseline: 3.8324x; 1.3295x over previous
#include <cuda_runtime.h>
#include <cuda_bf16.h>
#include <cuda_fp16.h>
#include <math.h>
#include <stdint.h>

#define BATCH   16
#define SRC_LEN 512
#define MEL_LEN 2048
#define DMODEL  256

// ---------------------------------------------------------------------------
// Device-global scratch
// ---------------------------------------------------------------------------
__device__ __nv_bfloat16 Thi[BATCH * SRC_LEN * DMODEL], Tlo[BATCH * SRC_LEN * DMODEL];
__device__ __nv_bfloat16 Wqhi[DMODEL * DMODEL], Wqlo[DMODEL * DMODEL];
__device__ __half        Mf16[BATCH * MEL_LEN * DMODEL];    // mel in fp16
__device__ __half        Wkf16[DMODEL * DMODEL];
__device__ __half        Wvf16[DMODEL * DMODEL];
__device__ __half        Qf16[BATCH * SRC_LEN * DMODEL];    // [b][t][m]
__device__ __half        Kf16[BATCH * MEL_LEN * DMODEL];    // [b][s][m]
__device__ __half        Vf16[BATCH * MEL_LEN * DMODEL];    // [b][s][m]
__device__ __half        Pf16[BATCH * SRC_LEN * MEL_LEN];   // [b][t][s]

// ---------------------------------------------------------------------------
// PTX helpers (base sm_80+ features only)
// ---------------------------------------------------------------------------
__device__ __forceinline__ uint32_t smem_u32(const void* p) {
    uint32_t a;
    asm("{ .reg .u64 t; cvta.to.shared.u64 t, %1; cvt.u32.u64 %0, t; }" : "=r"(a) : "l"(p));
    return a;
}
__device__ __forceinline__ void cp16(uint32_t s, const void* g) {
    asm volatile("cp.async.cg.shared.global [%0], [%1], 16;"
                 :: "r"(s), "l"(__cvta_generic_to_global(g)));
}
#define CP_COMMIT() asm volatile("cp.async.commit_group;" ::: "memory")
#define CP_WAIT1()  asm volatile("cp.async.wait_group 1;" ::: "memory")

__device__ __forceinline__ void ldsm_x4(uint32_t* r, uint32_t a) {
    asm volatile("ldmatrix.sync.aligned.m8n8.x4.shared.b16 {%0,%1,%2,%3}, [%4];"
                 : "=r"(r[0]), "=r"(r[1]), "=r"(r[2]), "=r"(r[3]) : "r"(a));
}
__device__ __forceinline__ void ldsm_x2t(uint32_t* r, uint32_t a) {
    asm volatile("ldmatrix.sync.aligned.m8n8.x2.trans.shared.b16 {%0,%1}, [%2];"
                 : "=r"(r[0]), "=r"(r[1]) : "r"(a));
}
__device__ __forceinline__ void mma16816(float* c, const uint32_t* a, const uint32_t* b) {
    asm volatile(
        "mma.sync.aligned.m16n8k16.row.col.f32.bf16.bf16.f32 "
        "{%0,%1,%2,%3}, {%4,%5,%6,%7}, {%8,%9}, {%0,%1,%2,%3};"
        : "+f"(c[0]), "+f"(c[1]), "+f"(c[2]), "+f"(c[3])
        : "r"(a[0]), "r"(a[1]), "r"(a[2]), "r"(a[3]), "r"(b[0]), "r"(b[1]));
}
__device__ __forceinline__ void mma16816h(float* c, const uint32_t* a, const uint32_t* b) {
    asm volatile(
        "mma.sync.aligned.m16n8k16.row.col.f32.f16.f16.f32 "
        "{%0,%1,%2,%3}, {%4,%5,%6,%7}, {%8,%9}, {%0,%1,%2,%3};"
        : "+f"(c[0]), "+f"(c[1]), "+f"(c[2]), "+f"(c[3])
        : "r"(a[0]), "r"(a[1]), "r"(a[2]), "r"(a[3]), "r"(b[0]), "r"(b[1]));
}

// ---------------------------------------------------------------------------
// fp32 -> (bf16 hi, bf16 lo) split      |      fp32 -> fp16 convert
// ---------------------------------------------------------------------------
__global__ void __launch_bounds__(256) split_kernel(
    const float* __restrict__ x, __nv_bfloat16* __restrict__ hi,
    __nv_bfloat16* __restrict__ lo, int n)
{
    int i = blockIdx.x * 256 + threadIdx.x;
    if (i < n) {
        float v = x[i];
        __nv_bfloat16 h = __float2bfloat16(v);
        hi[i] = h;
        lo[i] = __float2bfloat16(v - __bfloat162float(h));
    }
}

__global__ void __launch_bounds__(256) conv16_kernel(
    const float* __restrict__ x, __half* __restrict__ y, int n)
{
    int i = blockIdx.x * 256 + threadIdx.x;
    if (i < n) y[i] = __float2half(x[i]);
}

#define NSTAGE 3

// ---------------------------------------------------------------------------
// Q projection: 3-term split-bf16 compute, fp16 output.
// Block 128x128x32, 8 warps (2x4), warp tile 64x32. A [m][k]; B [n][k].
// ---------------------------------------------------------------------------
#define PR_STG 40960
#define PR_SMEM (NSTAGE * PR_STG)

__global__ void __launch_bounds__(256) gemm_proj(
    const __nv_bfloat16* __restrict__ Ah, const __nv_bfloat16* __restrict__ Al,
    const __nv_bfloat16* __restrict__ Bh, const __nv_bfloat16* __restrict__ Bl,
    __half* __restrict__ outH)
{
    extern __shared__ char smem[];
    const uint32_t sb = smem_u32(smem);
    const int tid = threadIdx.x;
    const int wid = tid >> 5, lane = tid & 31;
    const int warp_m = wid & 1, warp_n = wid >> 1;
    const int n0 = blockIdx.x * 128;
    const int K = DMODEL;

    const __nv_bfloat16* gAh = Ah + (size_t)blockIdx.y * 128 * K;
    const __nv_bfloat16* gAl = Al + (size_t)blockIdx.y * 128 * K;
    const __nv_bfloat16* gBh = Bh + (size_t)n0 * K;
    const __nv_bfloat16* gBl = Bl + (size_t)n0 * K;

    const int kiters = K >> 5;   // 8

    auto load_stage = [&](int stg, int kc) {
        const uint32_t sbase = sb + (uint32_t)stg * PR_STG;
        const int k0 = kc << 5;
        #pragma unroll
        for (int i = 0; i < 2; ++i) {
            int q = tid + i * 256;
            int r = q >> 2, c = q & 3;
            uint32_t so = sbase + r * 80 + c * 16;
            size_t g = (size_t)r * K + k0 + c * 8;
            cp16(so, gAh + g);
            cp16(so + 10240u, gAl + g);
            cp16(so + 20480u, gBh + g);
            cp16(so + 30720u, gBl + g);
        }
    };

    float acc[4][4][4] = {};

    load_stage(0, 0); CP_COMMIT();
    load_stage(1, 1); CP_COMMIT();

    for (int kc = 0; kc < kiters; ++kc) {
        CP_WAIT1();
        __syncthreads();
        if (kc + 2 < kiters) load_stage((kc + 2) % NSTAGE, kc + 2);
        CP_COMMIT();

        const uint32_t sbase = sb + (uint32_t)(kc % NSTAGE) * PR_STG;
        #pragma unroll
        for (int ks = 0; ks < 2; ++ks) {
            uint32_t a_hi[4][4], a_lo[4][4], b_hi[4][2], b_lo[4][2];
            #pragma unroll
            for (int mt = 0; mt < 4; ++mt) {
                int row = warp_m * 64 + mt * 16 + (lane & 15);
                uint32_t ad = sbase + row * 80 + ks * 32 + ((lane >> 4) << 4);
                ldsm_x4(a_hi[mt], ad);
                ldsm_x4(a_lo[mt], ad + 10240u);
            }
            #pragma unroll
            for (int h = 0; h < 2; ++h) {
                int row = warp_n * 32 + h * 16 + ((lane >> 4) << 3) + (lane & 7);
                uint32_t ad = sbase + 20480u + row * 80 + ks * 32 + (((lane >> 3) & 1) << 4);
                uint32_t rh[4], rl[4];
                ldsm_x4(rh, ad);
                ldsm_x4(rl, ad + 10240u);
                b_hi[h * 2][0] = rh[0]; b_hi[h * 2][1] = rh[1];
                b_hi[h * 2 + 1][0] = rh[2]; b_hi[h * 2 + 1][1] = rh[3];
                b_lo[h * 2][0] = rl[0]; b_lo[h * 2][1] = rl[1];
                b_lo[h * 2 + 1][0] = rl[2]; b_lo[h * 2 + 1][1] = rl[3];
            }
            #pragma unroll
            for (int mt = 0; mt < 4; ++mt)
                #pragma unroll
                for (int nt = 0; nt < 4; ++nt) {
                    mma16816(acc[mt][nt], a_hi[mt], b_hi[nt]);
                    mma16816(acc[mt][nt], a_hi[mt], b_lo[nt]);
                    mma16816(acc[mt][nt], a_lo[mt], b_hi[nt]);
                }
        }
    }

    const int gId = lane >> 2, t4 = lane & 3;
    const int rowB = blockIdx.y * 128 + warp_m * 64 + gId;

    #pragma unroll
    for (int mt = 0; mt < 4; ++mt)
        #pragma unroll
        for (int nt = 0; nt < 4; ++nt) {
            const int col = n0 + warp_n * 32 + nt * 8 + t4 * 2;
            const int r0 = rowB + mt * 16;
            float* cc = acc[mt][nt];
            #pragma unroll
            for (int h = 0; h < 2; ++h) {
                size_t o = (size_t)(r0 + h * 8) * DMODEL + col;
                __half2 hv;
                hv.x = __float2half(cc[h * 2]);
                hv.y = __float2half(cc[h * 2 + 1]);
                *(__half2*)(outH + o) = hv;
            }
        }
}

// ---------------------------------------------------------------------------
// Single-fp16 GEMM A[m][k] @ B[n][k]^T -> fp16 out (ld=DMODEL). Used for
// K/V projections (K=256). Block 128x128x32, 8 warps.
// ---------------------------------------------------------------------------
#define H_STG 20480
#define H_SMEM (NSTAGE * H_STG)

__global__ void __launch_bounds__(256) gemm_projh(
    const __half* __restrict__ A, const __half* __restrict__ B,
    __half* __restrict__ outH)
{
    extern __shared__ char smem[];
    const uint32_t sb = smem_u32(smem);
    const int tid = threadIdx.x;
    const int wid = tid >> 5, lane = tid & 31;
    const int warp_m = wid & 1, warp_n = wid >> 1;
    const int n0 = blockIdx.x * 128;
    const int K = DMODEL;

    const __half* gA = A + (size_t)blockIdx.y * 128 * K;
    const __half* gB = B + (size_t)n0 * K;

    const int kiters = K >> 5;   // 8

    auto load_stage = [&](int stg, int kc) {
        const uint32_t sbase = sb + (uint32_t)stg * H_STG;
        const int k0 = kc << 5;
        #pragma unroll
        for (int i = 0; i < 2; ++i) {
            int q = tid + i * 256;
            int r = q >> 2, c = q & 3;
            uint32_t so = sbase + r * 80 + c * 16;
            size_t g = (size_t)r * K + k0 + c * 8;
            cp16(so, gA + g);
            cp16(so + 10240u, gB + g);
        }
    };

    float acc[4][4][4] = {};

    load_stage(0, 0); CP_COMMIT();
    load_stage(1, 1); CP_COMMIT();

    for (int kc = 0; kc < kiters; ++kc) {
        CP_WAIT1();
        __syncthreads();
        if (kc + 2 < kiters) load_stage((kc + 2) % NSTAGE, kc + 2);
        CP_COMMIT();

        const uint32_t sbase = sb + (uint32_t)(kc % NSTAGE) * H_STG;
        #pragma unroll
        for (int ks = 0; ks < 2; ++ks) {
            uint32_t a[4][4], b[4][2];
            #pragma unroll
            for (int mt = 0; mt < 4; ++mt) {
                int row = warp_m * 64 + mt * 16 + (lane & 15);
                uint32_t ad = sbase + row * 80 + ks * 32 + ((lane >> 4) << 4);
                ldsm_x4(a[mt], ad);
            }
            #pragma unroll
            for (int h = 0; h < 2; ++h) {
                int row = warp_n * 32 + h * 16 + ((lane >> 4) << 3) + (lane & 7);
                uint32_t ad = sbase + 10240u + row * 80 + ks * 32 + (((lane >> 3) & 1) << 4);
                uint32_t rr[4];
                ldsm_x4(rr, ad);
                b[h * 2][0] = rr[0]; b[h * 2][1] = rr[1];
                b[h * 2 + 1][0] = rr[2]; b[h * 2 + 1][1] = rr[3];
            }
            #pragma unroll
            for (int mt = 0; mt < 4; ++mt)
                #pragma unroll
                for (int nt = 0; nt < 4; ++nt)
                    mma16816h(acc[mt][nt], a[mt], b[nt]);
        }
    }

    const int gId = lane >> 2, t4 = lane & 3;
    const int rowB = blockIdx.y * 128 + warp_m * 64 + gId;

    #pragma unroll
    for (int mt = 0; mt < 4; ++mt)
        #pragma unroll
        for (int nt = 0; nt < 4; ++nt) {
            const int col = n0 + warp_n * 32 + nt * 8 + t4 * 2;
            const int r0 = rowB + mt * 16;
            float* cc = acc[mt][nt];
            #pragma unroll
            for (int h = 0; h < 2; ++h) {
                size_t o = (size_t)(r0 + h * 8) * DMODEL + col;
                __half2 hv;
                hv.x = __float2half(cc[h * 2]);
                hv.y = __float2half(cc[h * 2 + 1]);
                *(__half2*)(outH + o) = hv;
            }
        }
}

// ---------------------------------------------------------------------------
// QK logits: fp16 single-term. A = Q [t][m], B = K [s][m].
// Epilogue: *1/16, mel-mask -> fp32 attn region.
// ---------------------------------------------------------------------------
__global__ void __launch_bounds__(256) gemm_qk(
    const __half* __restrict__ Q, const __half* __restrict__ Kb,
    const int* __restrict__ mask, float* __restrict__ attn)
{
    extern __shared__ char smem[];
    const uint32_t sb = smem_u32(smem);
    const int tid = threadIdx.x;
    const int wid = tid >> 5, lane = tid & 31;
    const int warp_m = wid & 1, warp_n = wid >> 1;
    const int z = blockIdx.z;
    const int n0 = blockIdx.x * 128;
    const int K = DMODEL;

    const __half* gA = Q + (size_t)z * SRC_LEN * DMODEL + (size_t)blockIdx.y * 128 * K;
    const __half* gB = Kb + (size_t)z * MEL_LEN * DMODEL + (size_t)n0 * K;

    const int kiters = K >> 5;   // 8

    auto load_stage = [&](int stg, int kc) {
        const uint32_t sbase = sb + (uint32_t)stg * H_STG;
        const int k0 = kc << 5;
        #pragma unroll
        for (int i = 0; i < 2; ++i) {
            int q = tid + i * 256;
            int r = q >> 2, c = q & 3;
            uint32_t so = sbase + r * 80 + c * 16;
            size_t g = (size_t)r * K + k0 + c * 8;
            cp16(so, gA + g);
            cp16(so + 10240u, gB + g);
        }
    };

    float acc[4][4][4] = {};

    load_stage(0, 0); CP_COMMIT();
    load_stage(1, 1); CP_COMMIT();

    for (int kc = 0; kc < kiters; ++kc) {
        CP_WAIT1();
        __syncthreads();
        if (kc + 2 < kiters) load_stage((kc + 2) % NSTAGE, kc + 2);
        CP_COMMIT();

        const uint32_t sbase = sb + (uint32_t)(kc % NSTAGE) * H_STG;
        #pragma unroll
        for (int ks = 0; ks < 2; ++ks) {
            uint32_t a[4][4], b[4][2];
            #pragma unroll
            for (int mt = 0; mt < 4; ++mt) {
                int row = warp_m * 64 + mt * 16 + (lane & 15);
                uint32_t ad = sbase + row * 80 + ks * 32 + ((lane >> 4) << 4);
                ldsm_x4(a[mt], ad);
            }
            #pragma unroll
            for (int h = 0; h < 2; ++h) {
                int row = warp_n * 32 + h * 16 + ((lane >> 4) << 3) + (lane & 7);
                uint32_t ad = sbase + 10240u + row * 80 + ks * 32 + (((lane >> 3) & 1) << 4);
                uint32_t rr[4];
                ldsm_x4(rr, ad);
                b[h * 2][0] = rr[0]; b[h * 2][1] = rr[1];
                b[h * 2 + 1][0] = rr[2]; b[h * 2 + 1][1] = rr[3];
            }
            #pragma unroll
            for (int mt = 0; mt < 4; ++mt)
                #pragma unroll
                for (int nt = 0; nt < 4; ++nt)
                    mma16816h(acc[mt][nt], a[mt], b[nt]);
        }
    }

    const int gId = lane >> 2, t4 = lane & 3;
    const int rowB = blockIdx.y * 128 + warp_m * 64 + gId;
    float* O = attn + (size_t)z * SRC_LEN * MEL_LEN;

    #pragma unroll
    for (int mt = 0; mt < 4; ++mt)
        #pragma unroll
        for (int nt = 0; nt < 4; ++nt) {
            const int col = n0 + warp_n * 32 + nt * 8 + t4 * 2;
            const int r0 = rowB + mt * 16;
            const int* mk = mask + z * MEL_LEN + col;
            const int m0 = mk[0], m1 = mk[1];
            float* cc = acc[mt][nt];
            float2 v0, v1;
            v0.x = m0 ? -1e30f : cc[0] * 0.0625f;
            v0.y = m1 ? -1e30f : cc[1] * 0.0625f;
            v1.x = m0 ? -1e30f : cc[2] * 0.0625f;
            v1.y = m1 ? -1e30f : cc[3] * 0.0625f;
            *(float2*)(O + (size_t)r0 * MEL_LEN + col) = v0;
            *(float2*)(O + (size_t)(r0 + 8) * MEL_LEN + col) = v1;
        }
}

// ---------------------------------------------------------------------------
// PV GEMM: O[b] = P[b](fp16,[t][s]) @ V[b](fp16,[s][m]), single-term fp16 MMA.
// B loaded [k][n] with ldmatrix.trans.
// ---------------------------------------------------------------------------
__global__ void __launch_bounds__(256) gemm_pv(
    const __half* __restrict__ P, const __half* __restrict__ V,
    float* __restrict__ outF)
{
    extern __shared__ char smem[];
    const uint32_t sb = smem_u32(smem);
    const int tid = threadIdx.x;
    const int wid = tid >> 5, lane = tid & 31;
    const int warp_m = wid & 1, warp_n = wid >> 1;
    const int z = blockIdx.z;
    const int n0 = blockIdx.x * 128;
    const int K = MEL_LEN;

    const __half* gA = P + (size_t)z * SRC_LEN * MEL_LEN + (size_t)blockIdx.y * 128 * K;
    const __half* gB = V + (size_t)z * MEL_LEN * DMODEL + n0;

    const int kiters = K >> 5;   // 64

    auto load_stage = [&](int stg, int kc) {
        const uint32_t sbase = sb + (uint32_t)stg * H_STG;
        const int k0 = kc << 5;
        #pragma unroll
        for (int i = 0; i < 2; ++i) {
            int q = tid + i * 256;
            int r = q >> 2, c = q & 3;
            cp16(sbase + r * 80 + c * 16, gA + (size_t)r * K + k0 + c * 8);
        }
        #pragma unroll
        for (int i = 0; i < 2; ++i) {
            int q = tid + i * 256;
            int r = q >> 4, c = q & 15;
            cp16(sbase + 10240u + r * 272 + c * 16, gB + (size_t)(k0 + r) * DMODEL + c * 8);
        }
    };

    float acc[4][4][4] = {};

    load_stage(0, 0); CP_COMMIT();
    load_stage(1, 1); CP_COMMIT();

    for (int kc = 0; kc < kiters; ++kc) {
        CP_WAIT1();
        __syncthreads();
        if (kc + 2 < kiters) load_stage((kc + 2) % NSTAGE, kc + 2);
        CP_COMMIT();

        const uint32_t sbase = sb + (uint32_t)(kc % NSTAGE) * H_STG;
        #pragma unroll
        for (int ks = 0; ks < 2; ++ks) {
            uint32_t a[4][4], b[4][2];
            #pragma unroll
            for (int mt = 0; mt < 4; ++mt) {
                int row = warp_m * 64 + mt * 16 + (lane & 15);
                uint32_t ad = sbase + row * 80 + ks * 32 + ((lane >> 4) << 4);
                ldsm_x4(a[mt], ad);
            }
            #pragma unroll
            for (int nt = 0; nt < 4; ++nt) {
                uint32_t ad = sbase + 10240u + (ks * 16 + (lane & 15)) * 272
                            + (warp_n * 32 + nt * 8) * 2;
                ldsm_x2t(b[nt], ad);
            }
            #pragma unroll
            for (int mt = 0; mt < 4; ++mt)
                #pragma unroll
                for (int nt = 0; nt < 4; ++nt)
                    mma16816h(acc[mt][nt], a[mt], b[nt]);
        }
    }

    const int gId = lane >> 2, t4 = lane & 3;
    const int rowB = blockIdx.y * 128 + warp_m * 64 + gId;
    float* O = outF + (size_t)z * SRC_LEN * DMODEL;

    #pragma unroll
    for (int mt = 0; mt < 4; ++mt)
        #pragma unroll
        for (int nt = 0; nt < 4; ++nt) {
            const int col = n0 + warp_n * 32 + nt * 8 + t4 * 2;
            const int r0 = rowB + mt * 16;
            float* cc = acc[mt][nt];
            *(float2*)(O + (size_t)r0 * DMODEL + col) = make_float2(cc[0], cc[1]);
            *(float2*)(O + (size_t)(r0 + 8) * DMODEL + col) = make_float2(cc[2], cc[3]);
        }
}

// ---------------------------------------------------------------------------
// Row softmax over 2048 keys (in place fp32) + fp16 P emit for PV.
// ---------------------------------------------------------------------------
__global__ void __launch_bounds__(256) softmax_kernel(
    float* __restrict__ attn, const int* __restrict__ src_mask,
    __half* __restrict__ pf)
{
    const int row = blockIdx.x;
    const int tid = threadIdx.x;
    float* p = attn + (size_t)row * MEL_LEN;

    float v[8];
    float m = -3.0e38f;
    #pragma unroll
    for (int i = 0; i < 8; ++i) { v[i] = p[tid + i * 256]; m = fmaxf(m, v[i]); }

    __shared__ float red[9];
    #pragma unroll
    for (int o = 16; o > 0; o >>= 1) m = fmaxf(m, __shfl_xor_sync(0xffffffffu, m, o));
    if ((tid & 31) == 0) red[tid >> 5] = m;
    __syncthreads();
    if (tid == 0) {
        float mm = red[0];
        #pragma unroll
        for (int i = 1; i < 8; ++i) mm = fmaxf(mm, red[i]);
        red[8] = mm;
    }
    __syncthreads();
    m = red[8];

    float s = 0.0f;
    #pragma unroll
    for (int i = 0; i < 8; ++i) { v[i] = expf(v[i] - m); s += v[i]; }
    #pragma unroll
    for (int o = 16; o > 0; o >>= 1) s += __shfl_xor_sync(0xffffffffu, s, o);
    __syncthreads();
    if ((tid & 31) == 0) red[tid >> 5] = s;
    __syncthreads();
    if (tid == 0) {
        float ss = 0.0f;
        #pragma unroll
        for (int i = 0; i < 8; ++i) ss += red[i];
        red[8] = ss;
    }
    __syncthreads();
    s = red[8];

    const float zf = src_mask[row] ? 0.0f : (1.0f / s);
    __half* ph = pf + (size_t)row * MEL_LEN;
    #pragma unroll
    for (int i = 0; i < 8; ++i) {
        float pv = v[i] * zf;
        p[tid + i * 256] = pv;
        ph[tid + i * 256] = __float2half(pv);
    }
}

// ---------------------------------------------------------------------------
// LayerNorm over last dim (256), in place.
// ---------------------------------------------------------------------------
__global__ void __launch_bounds__(256) ln_kernel(
    float* __restrict__ o, const float* __restrict__ gamma, const float* __restrict__ beta)
{
    const int row = blockIdx.x;
    const int tid = threadIdx.x;
    float* x = o + (size_t)row * DMODEL;
    float v = x[tid];

    __shared__ float red[9];
    float s = v;
    #pragma unroll
    for (int off = 16; off > 0; off >>= 1) s += __shfl_xor_sync(0xffffffffu, s, off);
    if ((tid & 31) == 0) red[tid >> 5] = s;
    __syncthreads();
    if (tid == 0) {
        float ss = 0.0f;
        #pragma unroll
        for (int i = 0; i < 8; ++i) ss += red[i];
        red[8] = ss * (1.0f / DMODEL);
    }
    __syncthreads();
    const float mu = red[8];
    __syncthreads();

    float d = v - mu;
    float q = d * d;
    #pragma unroll
    for (int off = 16; off > 0; off >>= 1) q += __shfl_xor_sync(0xffffffffu, q, off);
    if ((tid & 31) == 0) red[tid >> 5] = q;
    __syncthreads();
    if (tid == 0) {
        float qq = 0.0f;
        #pragma unroll
        for (int i = 0; i < 8; ++i) qq += red[i];
        red[8] = rsqrtf(qq * (1.0f / DMODEL) + 1e-5f);
    }
    __syncthreads();
    x[tid] = d * red[8] * gamma[tid] + beta[tid];
}

// ---------------------------------------------------------------------------
extern "C" void kernel_launch(void* const* d_in, const int* in_sizes, int n_in,
                              void* d_out, int out_size)
{
    const float* mel      = (const float*)d_in[0];
    const float* text     = (const float*)d_in[1];
    const int*   mel_mask = (const int*)d_in[2];
    const int*   src_mask = (const int*)d_in[3];
    const float* Wq       = (const float*)d_in[4];
    const float* Wk       = (const float*)d_in[5];
    const float* Wv       = (const float*)d_in[6];
    const float* gamma    = (const float*)d_in[7];
    const float* beta     = (const float*)d_in[8];

    float* out      = (float*)d_out;
    float* out_o    = out;                                      // [16,512,256]
    float* out_attn = out + (size_t)BATCH * SRC_LEN * DMODEL;   // [16,512,2048]

    __nv_bfloat16 *thi, *tlo, *wqh, *wql;
    __half *mf16, *wkf, *wvf, *qf16, *kf16, *vf16, *pf16;
    cudaGetSymbolAddress((void**)&thi, Thi);  cudaGetSymbolAddress((void**)&tlo, Tlo);
    cudaGetSymbolAddress((void**)&wqh, Wqhi); cudaGetSymbolAddress((void**)&wql, Wqlo);
    cudaGetSymbolAddress((void**)&mf16, Mf16);
    cudaGetSymbolAddress((void**)&wkf, Wkf16);
    cudaGetSymbolAddress((void**)&wvf, Wvf16);
    cudaGetSymbolAddress((void**)&qf16, Qf16);
    cudaGetSymbolAddress((void**)&kf16, Kf16);
    cudaGetSymbolAddress((void**)&vf16, Vf16);
    cudaGetSymbolAddress((void**)&pf16, Pf16);

    cudaFuncSetAttribute(gemm_proj,  cudaFuncAttributeMaxDynamicSharedMemorySize, PR_SMEM);
    cudaFuncSetAttribute(gemm_projh, cudaFuncAttributeMaxDynamicSharedMemorySize, H_SMEM);
    cudaFuncSetAttribute(gemm_qk,    cudaFuncAttributeMaxDynamicSharedMemorySize, H_SMEM);
    cudaFuncSetAttribute(gemm_pv,    cudaFuncAttributeMaxDynamicSharedMemorySize, H_SMEM);

    const int nText = BATCH * SRC_LEN * DMODEL;
    const int nMel  = BATCH * MEL_LEN * DMODEL;
    const int nW    = DMODEL * DMODEL;

    // 1) Prepare operands: text/Wq -> split bf16; mel/Wk/Wv -> fp16
    split_kernel<<<(nText + 255) / 256, 256>>>(text, thi, tlo, nText);
    split_kernel<<<(nW + 255) / 256, 256>>>(Wq, wqh, wql, nW);
    conv16_kernel<<<(nMel + 255) / 256, 256>>>(mel, mf16, nMel);
    conv16_kernel<<<(nW + 255) / 256, 256>>>(Wk, wkf, nW);
    conv16_kernel<<<(nW + 255) / 256, 256>>>(Wv, wvf, nW);

    // 2) Projections: Q 3-term bf16; K, V single fp16
    gemm_proj<<<dim3(2, 64), 256, PR_SMEM>>>(thi, tlo, wqh, wql, qf16);
    gemm_projh<<<dim3(2, 256), 256, H_SMEM>>>(mf16, wkf, kf16);
    gemm_projh<<<dim3(2, 256), 256, H_SMEM>>>(mf16, wvf, vf16);

    // 3) Logits: fp16 single-term, *1/16 + mel mask -> fp32 attn region
    gemm_qk<<<dim3(MEL_LEN / 128, SRC_LEN / 128, BATCH), 256, H_SMEM>>>(
        qf16, kf16, mel_mask, out_attn);

    // 4) Softmax + src mask + fp16 P emit
    softmax_kernel<<<BATCH * SRC_LEN, 256>>>(out_attn, src_mask, pf16);

    // 5) O = P @ V  (fp16 single-term)
    gemm_pv<<<dim3(DMODEL / 128, SRC_LEN / 128, BATCH), 256, H_SMEM>>>(
        pf16, vf16, out_o);

    // 6) LayerNorm
    ln_kernel<<<BATCH * SRC_LEN, 256>>>(out_o, gamma, beta);
}

// round 9
// speedup vs baseline: 4.5347x; 1.1832x over previous
#include <cuda_runtime.h>
#include <cuda_fp16.h>
#include <math.h>
#include <stdint.h>

#define BATCH   16
#define SRC_LEN 512
#define MEL_LEN 2048
#define DMODEL  256

#define N_MEL  (BATCH * MEL_LEN * DMODEL)   // 8388608
#define N_TEXT (BATCH * SRC_LEN * DMODEL)   // 2097152
#define N_W    (DMODEL * DMODEL)            // 65536

// ---------------------------------------------------------------------------
// Device-global scratch (all fp16)
// ---------------------------------------------------------------------------
__device__ __half Mf16[N_MEL];
__device__ __half Tf16[N_TEXT];
__device__ __half Wqf16[N_W], Wkf16[N_W], Wvf16[N_W];
__device__ __half Qf16[BATCH * SRC_LEN * DMODEL];    // [b][t][m]
__device__ __half Kf16[BATCH * MEL_LEN * DMODEL];    // [b][s][m]
__device__ __half Vf16[BATCH * MEL_LEN * DMODEL];    // [b][s][m]
__device__ __half Pf16[BATCH * SRC_LEN * MEL_LEN];   // [b][t][s]

// ---------------------------------------------------------------------------
// PTX helpers (base sm_80+ features only)
// ---------------------------------------------------------------------------
__device__ __forceinline__ uint32_t smem_u32(const void* p) {
    uint32_t a;
    asm("{ .reg .u64 t; cvta.to.shared.u64 t, %1; cvt.u32.u64 %0, t; }" : "=r"(a) : "l"(p));
    return a;
}
__device__ __forceinline__ void cp16(uint32_t s, const void* g) {
    asm volatile("cp.async.cg.shared.global [%0], [%1], 16;"
                 :: "r"(s), "l"(__cvta_generic_to_global(g)));
}
#define CP_COMMIT() asm volatile("cp.async.commit_group;" ::: "memory")
#define CP_WAIT1()  asm volatile("cp.async.wait_group 1;" ::: "memory")

__device__ __forceinline__ void ldsm_x4(uint32_t* r, uint32_t a) {
    asm volatile("ldmatrix.sync.aligned.m8n8.x4.shared.b16 {%0,%1,%2,%3}, [%4];"
                 : "=r"(r[0]), "=r"(r[1]), "=r"(r[2]), "=r"(r[3]) : "r"(a));
}
__device__ __forceinline__ void ldsm_x2t(uint32_t* r, uint32_t a) {
    asm volatile("ldmatrix.sync.aligned.m8n8.x2.trans.shared.b16 {%0,%1}, [%2];"
                 : "=r"(r[0]), "=r"(r[1]) : "r"(a));
}
__device__ __forceinline__ void mma16816h(float* c, const uint32_t* a, const uint32_t* b) {
    asm volatile(
        "mma.sync.aligned.m16n8k16.row.col.f32.f16.f16.f32 "
        "{%0,%1,%2,%3}, {%4,%5,%6,%7}, {%8,%9}, {%0,%1,%2,%3};"
        : "+f"(c[0]), "+f"(c[1]), "+f"(c[2]), "+f"(c[3])
        : "r"(a[0]), "r"(a[1]), "r"(a[2]), "r"(a[3]), "r"(b[0]), "r"(b[1]));
}

// ---------------------------------------------------------------------------
// Fused prep: fp32 -> fp16 for mel, text, Wq, Wk, Wv (float4-vectorized).
// One thread = 4 elements. Segments laid out back to back.
// ---------------------------------------------------------------------------
#define QUADS_MEL  (N_MEL / 4)
#define QUADS_TEXT (N_TEXT / 4)
#define QUADS_W    (N_W / 4)
#define QUADS_TOT  (QUADS_MEL + QUADS_TEXT + 3 * QUADS_W)

__global__ void __launch_bounds__(256) prep_kernel(
    const float* __restrict__ mel, const float* __restrict__ text,
    const float* __restrict__ Wq, const float* __restrict__ Wk,
    const float* __restrict__ Wv,
    __half* __restrict__ mf, __half* __restrict__ tf,
    __half* __restrict__ wqf, __half* __restrict__ wkf, __half* __restrict__ wvf)
{
    int i = blockIdx.x * 256 + threadIdx.x;
    const float* src;
    __half* dst;
    if (i < QUADS_MEL)                        { src = mel;  dst = mf; }
    else if ((i -= QUADS_MEL) < QUADS_TEXT)   { src = text; dst = tf; }
    else if ((i -= QUADS_TEXT) < QUADS_W)     { src = Wq;   dst = wqf; }
    else if ((i -= QUADS_W) < QUADS_W)        { src = Wk;   dst = wkf; }
    else if ((i -= QUADS_W) < QUADS_W)        { src = Wv;   dst = wvf; }
    else return;
    float4 v = ((const float4*)src)[i];
    __half2* d = (__half2*)dst + 2 * i;
    d[0] = __floats2half2_rn(v.x, v.y);
    d[1] = __floats2half2_rn(v.z, v.w);
}

#define NSTAGE 3

// ---------------------------------------------------------------------------
// Single-fp16 projection GEMM: A[m][k] @ B[n][k]^T -> fp16 out (ld=DMODEL).
// Block 128x128x32, 8 warps (2x4), warp tile 64x32. Used for Q projection.
// ---------------------------------------------------------------------------
#define H_STG 20480
#define H_SMEM (NSTAGE * H_STG)

__global__ void __launch_bounds__(256) gemm_projh(
    const __half* __restrict__ A, const __half* __restrict__ B,
    __half* __restrict__ outH)
{
    extern __shared__ char smem[];
    const uint32_t sb = smem_u32(smem);
    const int tid = threadIdx.x;
    const int wid = tid >> 5, lane = tid & 31;
    const int warp_m = wid & 1, warp_n = wid >> 1;
    const int n0 = blockIdx.x * 128;
    const int K = DMODEL;

    const __half* gA = A + (size_t)blockIdx.y * 128 * K;
    const __half* gB = B + (size_t)n0 * K;

    const int kiters = K >> 5;   // 8

    auto load_stage = [&](int stg, int kc) {
        const uint32_t sbase = sb + (uint32_t)stg * H_STG;
        const int k0 = kc << 5;
        #pragma unroll
        for (int i = 0; i < 2; ++i) {
            int q = tid + i * 256;
            int r = q >> 2, c = q & 3;
            uint32_t so = sbase + r * 80 + c * 16;
            size_t g = (size_t)r * K + k0 + c * 8;
            cp16(so, gA + g);
            cp16(so + 10240u, gB + g);
        }
    };

    float acc[4][4][4] = {};

    load_stage(0, 0); CP_COMMIT();
    load_stage(1, 1); CP_COMMIT();

    for (int kc = 0; kc < kiters; ++kc) {
        CP_WAIT1();
        __syncthreads();
        if (kc + 2 < kiters) load_stage((kc + 2) % NSTAGE, kc + 2);
        CP_COMMIT();

        const uint32_t sbase = sb + (uint32_t)(kc % NSTAGE) * H_STG;
        #pragma unroll
        for (int ks = 0; ks < 2; ++ks) {
            uint32_t a[4][4], b[4][2];
            #pragma unroll
            for (int mt = 0; mt < 4; ++mt) {
                int row = warp_m * 64 + mt * 16 + (lane & 15);
                uint32_t ad = sbase + row * 80 + ks * 32 + ((lane >> 4) << 4);
                ldsm_x4(a[mt], ad);
            }
            #pragma unroll
            for (int h = 0; h < 2; ++h) {
                int row = warp_n * 32 + h * 16 + ((lane >> 4) << 3) + (lane & 7);
                uint32_t ad = sbase + 10240u + row * 80 + ks * 32 + (((lane >> 3) & 1) << 4);
                uint32_t rr[4];
                ldsm_x4(rr, ad);
                b[h * 2][0] = rr[0]; b[h * 2][1] = rr[1];
                b[h * 2 + 1][0] = rr[2]; b[h * 2 + 1][1] = rr[3];
            }
            #pragma unroll
            for (int mt = 0; mt < 4; ++mt)
                #pragma unroll
                for (int nt = 0; nt < 4; ++nt)
                    mma16816h(acc[mt][nt], a[mt], b[nt]);
        }
    }

    const int gId = lane >> 2, t4 = lane & 3;
    const int rowB = blockIdx.y * 128 + warp_m * 64 + gId;

    #pragma unroll
    for (int mt = 0; mt < 4; ++mt)
        #pragma unroll
        for (int nt = 0; nt < 4; ++nt) {
            const int col = n0 + warp_n * 32 + nt * 8 + t4 * 2;
            const int r0 = rowB + mt * 16;
            float* cc = acc[mt][nt];
            #pragma unroll
            for (int h = 0; h < 2; ++h) {
                size_t o = (size_t)(r0 + h * 8) * DMODEL + col;
                __half2 hv;
                hv.x = __float2half(cc[h * 2]);
                hv.y = __float2half(cc[h * 2 + 1]);
                *(__half2*)(outH + o) = hv;
            }
        }
}

// ---------------------------------------------------------------------------
// Merged K+V projection: 512 threads. Warps 0-7 compute K-tile, 8-15 V-tile,
// both sharing the A (mel) smem tile. A read once from DRAM.
// Stage: A (10240) + Bk (10240) + Bv (10240) = 30720 bytes.
// ---------------------------------------------------------------------------
#define KV_STG 30720
#define KV_SMEM (NSTAGE * KV_STG)

__global__ void __launch_bounds__(512) gemm_projkv(
    const __half* __restrict__ A, const __half* __restrict__ Bk,
    const __half* __restrict__ Bv,
    __half* __restrict__ outK, __half* __restrict__ outV)
{
    extern __shared__ char smem[];
    const uint32_t sb = smem_u32(smem);
    const int tid = threadIdx.x;
    const int wid = tid >> 5, lane = tid & 31;
    const int half_sel = wid >> 3;          // 0 = K, 1 = V
    const int w8 = wid & 7;
    const int warp_m = w8 & 1, warp_n = w8 >> 1;
    const int n0 = blockIdx.x * 128;
    const int K = DMODEL;

    const __half* gA  = A + (size_t)blockIdx.y * 128 * K;
    const __half* gBk = Bk + (size_t)n0 * K;
    const __half* gBv = Bv + (size_t)n0 * K;

    const int kiters = K >> 5;   // 8

    auto load_stage = [&](int stg, int kc) {
        const uint32_t sbase = sb + (uint32_t)stg * KV_STG;
        const int k0 = kc << 5;
        int r = tid >> 2, c = tid & 3;                      // 512 thr = 128x4 chunks
        uint32_t so = sbase + r * 80 + c * 16;
        size_t g = (size_t)r * K + k0 + c * 8;
        cp16(so, gA + g);
        cp16(so + 10240u, gBk + g);
        cp16(so + 20480u, gBv + g);
    };

    float acc[4][4][4] = {};

    load_stage(0, 0); CP_COMMIT();
    load_stage(1, 1); CP_COMMIT();

    const uint32_t bOff = 10240u + (uint32_t)half_sel * 10240u;

    for (int kc = 0; kc < kiters; ++kc) {
        CP_WAIT1();
        __syncthreads();
        if (kc + 2 < kiters) load_stage((kc + 2) % NSTAGE, kc + 2);
        CP_COMMIT();

        const uint32_t sbase = sb + (uint32_t)(kc % NSTAGE) * KV_STG;
        #pragma unroll
        for (int ks = 0; ks < 2; ++ks) {
            uint32_t a[4][4], b[4][2];
            #pragma unroll
            for (int mt = 0; mt < 4; ++mt) {
                int row = warp_m * 64 + mt * 16 + (lane & 15);
                uint32_t ad = sbase + row * 80 + ks * 32 + ((lane >> 4) << 4);
                ldsm_x4(a[mt], ad);
            }
            #pragma unroll
            for (int h = 0; h < 2; ++h) {
                int row = warp_n * 32 + h * 16 + ((lane >> 4) << 3) + (lane & 7);
                uint32_t ad = sbase + bOff + row * 80 + ks * 32 + (((lane >> 3) & 1) << 4);
                uint32_t rr[4];
                ldsm_x4(rr, ad);
                b[h * 2][0] = rr[0]; b[h * 2][1] = rr[1];
                b[h * 2 + 1][0] = rr[2]; b[h * 2 + 1][1] = rr[3];
            }
            #pragma unroll
            for (int mt = 0; mt < 4; ++mt)
                #pragma unroll
                for (int nt = 0; nt < 4; ++nt)
                    mma16816h(acc[mt][nt], a[mt], b[nt]);
        }
    }

    __half* outH = half_sel ? outV : outK;
    const int gId = lane >> 2, t4 = lane & 3;
    const int rowB = blockIdx.y * 128 + warp_m * 64 + gId;

    #pragma unroll
    for (int mt = 0; mt < 4; ++mt)
        #pragma unroll
        for (int nt = 0; nt < 4; ++nt) {
            const int col = n0 + warp_n * 32 + nt * 8 + t4 * 2;
            const int r0 = rowB + mt * 16;
            float* cc = acc[mt][nt];
            #pragma unroll
            for (int h = 0; h < 2; ++h) {
                size_t o = (size_t)(r0 + h * 8) * DMODEL + col;
                __half2 hv;
                hv.x = __float2half(cc[h * 2]);
                hv.y = __float2half(cc[h * 2 + 1]);
                *(__half2*)(outH + o) = hv;
            }
        }
}

// ---------------------------------------------------------------------------
// QK logits: fp16 single-term. A = Q [t][m], B = K [s][m].
// Epilogue: *1/16, mel-mask -> fp32 attn region.
// ---------------------------------------------------------------------------
__global__ void __launch_bounds__(256) gemm_qk(
    const __half* __restrict__ Q, const __half* __restrict__ Kb,
    const int* __restrict__ mask, float* __restrict__ attn)
{
    extern __shared__ char smem[];
    const uint32_t sb = smem_u32(smem);
    const int tid = threadIdx.x;
    const int wid = tid >> 5, lane = tid & 31;
    const int warp_m = wid & 1, warp_n = wid >> 1;
    const int z = blockIdx.z;
    const int n0 = blockIdx.x * 128;
    const int K = DMODEL;

    const __half* gA = Q + (size_t)z * SRC_LEN * DMODEL + (size_t)blockIdx.y * 128 * K;
    const __half* gB = Kb + (size_t)z * MEL_LEN * DMODEL + (size_t)n0 * K;

    const int kiters = K >> 5;   // 8

    auto load_stage = [&](int stg, int kc) {
        const uint32_t sbase = sb + (uint32_t)stg * H_STG;
        const int k0 = kc << 5;
        #pragma unroll
        for (int i = 0; i < 2; ++i) {
            int q = tid + i * 256;
            int r = q >> 2, c = q & 3;
            uint32_t so = sbase + r * 80 + c * 16;
            size_t g = (size_t)r * K + k0 + c * 8;
            cp16(so, gA + g);
            cp16(so + 10240u, gB + g);
        }
    };

    float acc[4][4][4] = {};

    load_stage(0, 0); CP_COMMIT();
    load_stage(1, 1); CP_COMMIT();

    for (int kc = 0; kc < kiters; ++kc) {
        CP_WAIT1();
        __syncthreads();
        if (kc + 2 < kiters) load_stage((kc + 2) % NSTAGE, kc + 2);
        CP_COMMIT();

        const uint32_t sbase = sb + (uint32_t)(kc % NSTAGE) * H_STG;
        #pragma unroll
        for (int ks = 0; ks < 2; ++ks) {
            uint32_t a[4][4], b[4][2];
            #pragma unroll
            for (int mt = 0; mt < 4; ++mt) {
                int row = warp_m * 64 + mt * 16 + (lane & 15);
                uint32_t ad = sbase + row * 80 + ks * 32 + ((lane >> 4) << 4);
                ldsm_x4(a[mt], ad);
            }
            #pragma unroll
            for (int h = 0; h < 2; ++h) {
                int row = warp_n * 32 + h * 16 + ((lane >> 4) << 3) + (lane & 7);
                uint32_t ad = sbase + 10240u + row * 80 + ks * 32 + (((lane >> 3) & 1) << 4);
                uint32_t rr[4];
                ldsm_x4(rr, ad);
                b[h * 2][0] = rr[0]; b[h * 2][1] = rr[1];
                b[h * 2 + 1][0] = rr[2]; b[h * 2 + 1][1] = rr[3];
            }
            #pragma unroll
            for (int mt = 0; mt < 4; ++mt)
                #pragma unroll
                for (int nt = 0; nt < 4; ++nt)
                    mma16816h(acc[mt][nt], a[mt], b[nt]);
        }
    }

    const int gId = lane >> 2, t4 = lane & 3;
    const int rowB = blockIdx.y * 128 + warp_m * 64 + gId;
    float* O = attn + (size_t)z * SRC_LEN * MEL_LEN;

    #pragma unroll
    for (int mt = 0; mt < 4; ++mt)
        #pragma unroll
        for (int nt = 0; nt < 4; ++nt) {
            const int col = n0 + warp_n * 32 + nt * 8 + t4 * 2;
            const int r0 = rowB + mt * 16;
            const int* mk = mask + z * MEL_LEN + col;
            const int m0 = mk[0], m1 = mk[1];
            float* cc = acc[mt][nt];
            float2 v0, v1;
            v0.x = m0 ? -1e30f : cc[0] * 0.0625f;
            v0.y = m1 ? -1e30f : cc[1] * 0.0625f;
            v1.x = m0 ? -1e30f : cc[2] * 0.0625f;
            v1.y = m1 ? -1e30f : cc[3] * 0.0625f;
            *(float2*)(O + (size_t)r0 * MEL_LEN + col) = v0;
            *(float2*)(O + (size_t)(r0 + 8) * MEL_LEN + col) = v1;
        }
}

// ---------------------------------------------------------------------------
// PV GEMM: O[b] = P[b](fp16,[t][s]) @ V[b](fp16,[s][m]), single-term fp16 MMA.
// B loaded [k][n] with ldmatrix.trans.
// ---------------------------------------------------------------------------
__global__ void __launch_bounds__(256) gemm_pv(
    const __half* __restrict__ P, const __half* __restrict__ V,
    float* __restrict__ outF)
{
    extern __shared__ char smem[];
    const uint32_t sb = smem_u32(smem);
    const int tid = threadIdx.x;
    const int wid = tid >> 5, lane = tid & 31;
    const int warp_m = wid & 1, warp_n = wid >> 1;
    const int z = blockIdx.z;
    const int n0 = blockIdx.x * 128;
    const int K = MEL_LEN;

    const __half* gA = P + (size_t)z * SRC_LEN * MEL_LEN + (size_t)blockIdx.y * 128 * K;
    const __half* gB = V + (size_t)z * MEL_LEN * DMODEL + n0;

    const int kiters = K >> 5;   // 64

    auto load_stage = [&](int stg, int kc) {
        const uint32_t sbase = sb + (uint32_t)stg * H_STG;
        const int k0 = kc << 5;
        #pragma unroll
        for (int i = 0; i < 2; ++i) {
            int q = tid + i * 256;
            int r = q >> 2, c = q & 3;
            cp16(sbase + r * 80 + c * 16, gA + (size_t)r * K + k0 + c * 8);
        }
        #pragma unroll
        for (int i = 0; i < 2; ++i) {
            int q = tid + i * 256;
            int r = q >> 4, c = q & 15;
            cp16(sbase + 10240u + r * 272 + c * 16, gB + (size_t)(k0 + r) * DMODEL + c * 8);
        }
    };

    float acc[4][4][4] = {};

    load_stage(0, 0); CP_COMMIT();
    load_stage(1, 1); CP_COMMIT();

    for (int kc = 0; kc < kiters; ++kc) {
        CP_WAIT1();
        __syncthreads();
        if (kc + 2 < kiters) load_stage((kc + 2) % NSTAGE, kc + 2);
        CP_COMMIT();

        const uint32_t sbase = sb + (uint32_t)(kc % NSTAGE) * H_STG;
        #pragma unroll
        for (int ks = 0; ks < 2; ++ks) {
            uint32_t a[4][4], b[4][2];
            #pragma unroll
            for (int mt = 0; mt < 4; ++mt) {
                int row = warp_m * 64 + mt * 16 + (lane & 15);
                uint32_t ad = sbase + row * 80 + ks * 32 + ((lane >> 4) << 4);
                ldsm_x4(a[mt], ad);
            }
            #pragma unroll
            for (int nt = 0; nt < 4; ++nt) {
                uint32_t ad = sbase + 10240u + (ks * 16 + (lane & 15)) * 272
                            + (warp_n * 32 + nt * 8) * 2;
                ldsm_x2t(b[nt], ad);
            }
            #pragma unroll
            for (int mt = 0; mt < 4; ++mt)
                #pragma unroll
                for (int nt = 0; nt < 4; ++nt)
                    mma16816h(acc[mt][nt], a[mt], b[nt]);
        }
    }

    const int gId = lane >> 2, t4 = lane & 3;
    const int rowB = blockIdx.y * 128 + warp_m * 64 + gId;
    float* O = outF + (size_t)z * SRC_LEN * DMODEL;

    #pragma unroll
    for (int mt = 0; mt < 4; ++mt)
        #pragma unroll
        for (int nt = 0; nt < 4; ++nt) {
            const int col = n0 + warp_n * 32 + nt * 8 + t4 * 2;
            const int r0 = rowB + mt * 16;
            float* cc = acc[mt][nt];
            *(float2*)(O + (size_t)r0 * DMODEL + col) = make_float2(cc[0], cc[1]);
            *(float2*)(O + (size_t)(r0 + 8) * DMODEL + col) = make_float2(cc[2], cc[3]);
        }
}

// ---------------------------------------------------------------------------
// Row softmax over 2048 keys (in place fp32) + fp16 P emit for PV.
// ---------------------------------------------------------------------------
__global__ void __launch_bounds__(256) softmax_kernel(
    float* __restrict__ attn, const int* __restrict__ src_mask,
    __half* __restrict__ pf)
{
    const int row = blockIdx.x;
    const int tid = threadIdx.x;
    float* p = attn + (size_t)row * MEL_LEN;

    float v[8];
    float m = -3.0e38f;
    #pragma unroll
    for (int i = 0; i < 8; ++i) { v[i] = p[tid + i * 256]; m = fmaxf(m, v[i]); }

    __shared__ float red[9];
    #pragma unroll
    for (int o = 16; o > 0; o >>= 1) m = fmaxf(m, __shfl_xor_sync(0xffffffffu, m, o));
    if ((tid & 31) == 0) red[tid >> 5] = m;
    __syncthreads();
    if (tid == 0) {
        float mm = red[0];
        #pragma unroll
        for (int i = 1; i < 8; ++i) mm = fmaxf(mm, red[i]);
        red[8] = mm;
    }
    __syncthreads();
    m = red[8];

    float s = 0.0f;
    #pragma unroll
    for (int i = 0; i < 8; ++i) { v[i] = expf(v[i] - m); s += v[i]; }
    #pragma unroll
    for (int o = 16; o > 0; o >>= 1) s += __shfl_xor_sync(0xffffffffu, s, o);
    __syncthreads();
    if ((tid & 31) == 0) red[tid >> 5] = s;
    __syncthreads();
    if (tid == 0) {
        float ss = 0.0f;
        #pragma unroll
        for (int i = 0; i < 8; ++i) ss += red[i];
        red[8] = ss;
    }
    __syncthreads();
    s = red[8];

    const float zf = src_mask[row] ? 0.0f : (1.0f / s);
    __half* ph = pf + (size_t)row * MEL_LEN;
    #pragma unroll
    for (int i = 0; i < 8; ++i) {
        float pv = v[i] * zf;
        p[tid + i * 256] = pv;
        ph[tid + i * 256] = __float2half(pv);
    }
}

// ---------------------------------------------------------------------------
// LayerNorm over last dim (256), in place.
// ---------------------------------------------------------------------------
__global__ void __launch_bounds__(256) ln_kernel(
    float* __restrict__ o, const float* __restrict__ gamma, const float* __restrict__ beta)
{
    const int row = blockIdx.x;
    const int tid = threadIdx.x;
    float* x = o + (size_t)row * DMODEL;
    float v = x[tid];

    __shared__ float red[9];
    float s = v;
    #pragma unroll
    for (int off = 16; off > 0; off >>= 1) s += __shfl_xor_sync(0xffffffffu, s, off);
    if ((tid & 31) == 0) red[tid >> 5] = s;
    __syncthreads();
    if (tid == 0) {
        float ss = 0.0f;
        #pragma unroll
        for (int i = 0; i < 8; ++i) ss += red[i];
        red[8] = ss * (1.0f / DMODEL);
    }
    __syncthreads();
    const float mu = red[8];
    __syncthreads();

    float d = v - mu;
    float q = d * d;
    #pragma unroll
    for (int off = 16; off > 0; off >>= 1) q += __shfl_xor_sync(0xffffffffu, q, off);
    if ((tid & 31) == 0) red[tid >> 5] = q;
    __syncthreads();
    if (tid == 0) {
        float qq = 0.0f;
        #pragma unroll
        for (int i = 0; i < 8; ++i) qq += red[i];
        red[8] = rsqrtf(qq * (1.0f / DMODEL) + 1e-5f);
    }
    __syncthreads();
    x[tid] = d * red[8] * gamma[tid] + beta[tid];
}

// ---------------------------------------------------------------------------
extern "C" void kernel_launch(void* const* d_in, const int* in_sizes, int n_in,
                              void* d_out, int out_size)
{
    const float* mel      = (const float*)d_in[0];
    const float* text     = (const float*)d_in[1];
    const int*   mel_mask = (const int*)d_in[2];
    const int*   src_mask = (const int*)d_in[3];
    const float* Wq       = (const float*)d_in[4];
    const float* Wk       = (const float*)d_in[5];
    const float* Wv       = (const float*)d_in[6];
    const float* gamma    = (const float*)d_in[7];
    const float* beta     = (const float*)d_in[8];

    float* out      = (float*)d_out;
    float* out_o    = out;                                      // [16,512,256]
    float* out_attn = out + (size_t)BATCH * SRC_LEN * DMODEL;   // [16,512,2048]

    __half *mf16, *tf16, *wqf, *wkf, *wvf, *qf16, *kf16, *vf16, *pf16;
    cudaGetSymbolAddress((void**)&mf16, Mf16);
    cudaGetSymbolAddress((void**)&tf16, Tf16);
    cudaGetSymbolAddress((void**)&wqf, Wqf16);
    cudaGetSymbolAddress((void**)&wkf, Wkf16);
    cudaGetSymbolAddress((void**)&wvf, Wvf16);
    cudaGetSymbolAddress((void**)&qf16, Qf16);
    cudaGetSymbolAddress((void**)&kf16, Kf16);
    cudaGetSymbolAddress((void**)&vf16, Vf16);
    cudaGetSymbolAddress((void**)&pf16, Pf16);

    cudaFuncSetAttribute(gemm_projh,  cudaFuncAttributeMaxDynamicSharedMemorySize, H_SMEM);
    cudaFuncSetAttribute(gemm_projkv, cudaFuncAttributeMaxDynamicSharedMemorySize, KV_SMEM);
    cudaFuncSetAttribute(gemm_qk,     cudaFuncAttributeMaxDynamicSharedMemorySize, H_SMEM);
    cudaFuncSetAttribute(gemm_pv,     cudaFuncAttributeMaxDynamicSharedMemorySize, H_SMEM);

    // 1) Fused prep: everything -> fp16
    prep_kernel<<<(QUADS_TOT + 255) / 256, 256>>>(
        mel, text, Wq, Wk, Wv, mf16, tf16, wqf, wkf, wvf);

    // 2) Projections: Q (single fp16); K+V merged (shared mel tile)
    gemm_projh<<<dim3(2, 64), 256, H_SMEM>>>(tf16, wqf, qf16);
    gemm_projkv<<<dim3(2, 256), 512, KV_SMEM>>>(mf16, wkf, wvf, kf16, vf16);

    // 3) Logits: fp16 single-term, *1/16 + mel mask -> fp32 attn region
    gemm_qk<<<dim3(MEL_LEN / 128, SRC_LEN / 128, BATCH), 256, H_SMEM>>>(
        qf16, kf16, mel_mask, out_attn);

    // 4) Softmax + src mask + fp16 P emit
    softmax_kernel<<<BATCH * SRC_LEN, 256>>>(out_attn, src_mask, pf16);

    // 5) O = P @ V  (fp16 single-term)
    gemm_pv<<<dim3(DMODEL / 128, SRC_LEN / 128, BATCH), 256, H_SMEM>>>(
        pf16, vf16, out_o);

    // 6) LayerNorm
    ln_kernel<<<BATCH * SRC_LEN, 256>>>(out_o, gamma, beta);
}

// round 10
// speedup vs baseline: 4.6864x; 1.0335x over previous
#include <cuda_runtime.h>
#include <cuda_fp16.h>
#include <math.h>
#include <stdint.h>

#define BATCH   16
#define SRC_LEN 512
#define MEL_LEN 2048
#define DMODEL  256

#define N_MEL  (BATCH * MEL_LEN * DMODEL)   // 8388608
#define N_TEXT (BATCH * SRC_LEN * DMODEL)   // 2097152
#define N_W    (DMODEL * DMODEL)            // 65536

// ---------------------------------------------------------------------------
// Device-global scratch
// ---------------------------------------------------------------------------
__device__ __half Mf16[N_MEL];
__device__ __half Tf16[N_TEXT];
__device__ __half Wqf16[N_W], Wkf16[N_W], Wvf16[N_W];
__device__ __half Qf16[BATCH * SRC_LEN * DMODEL];    // [b][t][m]
__device__ __half Kf16[BATCH * MEL_LEN * DMODEL];    // [b][s][m]
__device__ __half Vf16[BATCH * MEL_LEN * DMODEL];    // [b][s][m]
__device__ __half Pf16[BATCH * SRC_LEN * MEL_LEN];   // [b][t][s]
__device__ float  Opart0[N_TEXT];                    // PV partial, K half 0
__device__ float  Opart1[N_TEXT];                    // PV partial, K half 1

// ---------------------------------------------------------------------------
// PTX helpers (base sm_80+ features only)
// ---------------------------------------------------------------------------
__device__ __forceinline__ uint32_t smem_u32(const void* p) {
    uint32_t a;
    asm("{ .reg .u64 t; cvta.to.shared.u64 t, %1; cvt.u32.u64 %0, t; }" : "=r"(a) : "l"(p));
    return a;
}
__device__ __forceinline__ void cp16(uint32_t s, const void* g) {
    asm volatile("cp.async.cg.shared.global [%0], [%1], 16;"
                 :: "r"(s), "l"(__cvta_generic_to_global(g)));
}
#define CP_COMMIT() asm volatile("cp.async.commit_group;" ::: "memory")
#define CP_WAIT1()  asm volatile("cp.async.wait_group 1;" ::: "memory")

__device__ __forceinline__ void ldsm_x4(uint32_t* r, uint32_t a) {
    asm volatile("ldmatrix.sync.aligned.m8n8.x4.shared.b16 {%0,%1,%2,%3}, [%4];"
                 : "=r"(r[0]), "=r"(r[1]), "=r"(r[2]), "=r"(r[3]) : "r"(a));
}
__device__ __forceinline__ void ldsm_x2t(uint32_t* r, uint32_t a) {
    asm volatile("ldmatrix.sync.aligned.m8n8.x2.trans.shared.b16 {%0,%1}, [%2];"
                 : "=r"(r[0]), "=r"(r[1]) : "r"(a));
}
__device__ __forceinline__ void mma16816h(float* c, const uint32_t* a, const uint32_t* b) {
    asm volatile(
        "mma.sync.aligned.m16n8k16.row.col.f32.f16.f16.f32 "
        "{%0,%1,%2,%3}, {%4,%5,%6,%7}, {%8,%9}, {%0,%1,%2,%3};"
        : "+f"(c[0]), "+f"(c[1]), "+f"(c[2]), "+f"(c[3])
        : "r"(a[0]), "r"(a[1]), "r"(a[2]), "r"(a[3]), "r"(b[0]), "r"(b[1]));
}

// ---------------------------------------------------------------------------
// Fused prep: fp32 -> fp16 for mel, text, Wq, Wk, Wv (float4-vectorized).
// ---------------------------------------------------------------------------
#define QUADS_MEL  (N_MEL / 4)
#define QUADS_TEXT (N_TEXT / 4)
#define QUADS_W    (N_W / 4)
#define QUADS_TOT  (QUADS_MEL + QUADS_TEXT + 3 * QUADS_W)

__global__ void __launch_bounds__(256) prep_kernel(
    const float* __restrict__ mel, const float* __restrict__ text,
    const float* __restrict__ Wq, const float* __restrict__ Wk,
    const float* __restrict__ Wv,
    __half* __restrict__ mf, __half* __restrict__ tf,
    __half* __restrict__ wqf, __half* __restrict__ wkf, __half* __restrict__ wvf)
{
    int i = blockIdx.x * 256 + threadIdx.x;
    const float* src;
    __half* dst;
    if (i < QUADS_MEL)                        { src = mel;  dst = mf; }
    else if ((i -= QUADS_MEL) < QUADS_TEXT)   { src = text; dst = tf; }
    else if ((i -= QUADS_TEXT) < QUADS_W)     { src = Wq;   dst = wqf; }
    else if ((i -= QUADS_W) < QUADS_W)        { src = Wk;   dst = wkf; }
    else if ((i -= QUADS_W) < QUADS_W)        { src = Wv;   dst = wvf; }
    else return;
    float4 v = ((const float4*)src)[i];
    __half2* d = (__half2*)dst + 2 * i;
    d[0] = __floats2half2_rn(v.x, v.y);
    d[1] = __floats2half2_rn(v.z, v.w);
}

#define NSTAGE 3

// ---------------------------------------------------------------------------
// Single-fp16 projection GEMM: A[m][k] @ B[n][k]^T -> fp16 out (ld=DMODEL).
// Block 128x128x32, 8 warps (2x4), warp tile 64x32. Used for Q projection.
// ---------------------------------------------------------------------------
#define H_STG 20480
#define H_SMEM (NSTAGE * H_STG)

__global__ void __launch_bounds__(256) gemm_projh(
    const __half* __restrict__ A, const __half* __restrict__ B,
    __half* __restrict__ outH)
{
    extern __shared__ char smem[];
    const uint32_t sb = smem_u32(smem);
    const int tid = threadIdx.x;
    const int wid = tid >> 5, lane = tid & 31;
    const int warp_m = wid & 1, warp_n = wid >> 1;
    const int n0 = blockIdx.x * 128;
    const int K = DMODEL;

    const __half* gA = A + (size_t)blockIdx.y * 128 * K;
    const __half* gB = B + (size_t)n0 * K;

    const int kiters = K >> 5;   // 8

    auto load_stage = [&](int stg, int kc) {
        const uint32_t sbase = sb + (uint32_t)stg * H_STG;
        const int k0 = kc << 5;
        #pragma unroll
        for (int i = 0; i < 2; ++i) {
            int q = tid + i * 256;
            int r = q >> 2, c = q & 3;
            uint32_t so = sbase + r * 80 + c * 16;
            size_t g = (size_t)r * K + k0 + c * 8;
            cp16(so, gA + g);
            cp16(so + 10240u, gB + g);
        }
    };

    float acc[4][4][4] = {};

    load_stage(0, 0); CP_COMMIT();
    load_stage(1, 1); CP_COMMIT();

    for (int kc = 0; kc < kiters; ++kc) {
        CP_WAIT1();
        __syncthreads();
        if (kc + 2 < kiters) load_stage((kc + 2) % NSTAGE, kc + 2);
        CP_COMMIT();

        const uint32_t sbase = sb + (uint32_t)(kc % NSTAGE) * H_STG;
        #pragma unroll
        for (int ks = 0; ks < 2; ++ks) {
            uint32_t a[4][4], b[4][2];
            #pragma unroll
            for (int mt = 0; mt < 4; ++mt) {
                int row = warp_m * 64 + mt * 16 + (lane & 15);
                uint32_t ad = sbase + row * 80 + ks * 32 + ((lane >> 4) << 4);
                ldsm_x4(a[mt], ad);
            }
            #pragma unroll
            for (int h = 0; h < 2; ++h) {
                int row = warp_n * 32 + h * 16 + ((lane >> 4) << 3) + (lane & 7);
                uint32_t ad = sbase + 10240u + row * 80 + ks * 32 + (((lane >> 3) & 1) << 4);
                uint32_t rr[4];
                ldsm_x4(rr, ad);
                b[h * 2][0] = rr[0]; b[h * 2][1] = rr[1];
                b[h * 2 + 1][0] = rr[2]; b[h * 2 + 1][1] = rr[3];
            }
            #pragma unroll
            for (int mt = 0; mt < 4; ++mt)
                #pragma unroll
                for (int nt = 0; nt < 4; ++nt)
                    mma16816h(acc[mt][nt], a[mt], b[nt]);
        }
    }

    const int gId = lane >> 2, t4 = lane & 3;
    const int rowB = blockIdx.y * 128 + warp_m * 64 + gId;

    #pragma unroll
    for (int mt = 0; mt < 4; ++mt)
        #pragma unroll
        for (int nt = 0; nt < 4; ++nt) {
            const int col = n0 + warp_n * 32 + nt * 8 + t4 * 2;
            const int r0 = rowB + mt * 16;
            float* cc = acc[mt][nt];
            #pragma unroll
            for (int h = 0; h < 2; ++h) {
                size_t o = (size_t)(r0 + h * 8) * DMODEL + col;
                __half2 hv;
                hv.x = __float2half(cc[h * 2]);
                hv.y = __float2half(cc[h * 2 + 1]);
                *(__half2*)(outH + o) = hv;
            }
        }
}

// ---------------------------------------------------------------------------
// Merged K+V projection: 512 threads. Warps 0-7 K-tile, 8-15 V-tile, shared A.
// ---------------------------------------------------------------------------
#define KV_STG 30720
#define KV_SMEM (NSTAGE * KV_STG)

__global__ void __launch_bounds__(512) gemm_projkv(
    const __half* __restrict__ A, const __half* __restrict__ Bk,
    const __half* __restrict__ Bv,
    __half* __restrict__ outK, __half* __restrict__ outV)
{
    extern __shared__ char smem[];
    const uint32_t sb = smem_u32(smem);
    const int tid = threadIdx.x;
    const int wid = tid >> 5, lane = tid & 31;
    const int half_sel = wid >> 3;          // 0 = K, 1 = V
    const int w8 = wid & 7;
    const int warp_m = w8 & 1, warp_n = w8 >> 1;
    const int n0 = blockIdx.x * 128;
    const int K = DMODEL;

    const __half* gA  = A + (size_t)blockIdx.y * 128 * K;
    const __half* gBk = Bk + (size_t)n0 * K;
    const __half* gBv = Bv + (size_t)n0 * K;

    const int kiters = K >> 5;   // 8

    auto load_stage = [&](int stg, int kc) {
        const uint32_t sbase = sb + (uint32_t)stg * KV_STG;
        const int k0 = kc << 5;
        int r = tid >> 2, c = tid & 3;
        uint32_t so = sbase + r * 80 + c * 16;
        size_t g = (size_t)r * K + k0 + c * 8;
        cp16(so, gA + g);
        cp16(so + 10240u, gBk + g);
        cp16(so + 20480u, gBv + g);
    };

    float acc[4][4][4] = {};

    load_stage(0, 0); CP_COMMIT();
    load_stage(1, 1); CP_COMMIT();

    const uint32_t bOff = 10240u + (uint32_t)half_sel * 10240u;

    for (int kc = 0; kc < kiters; ++kc) {
        CP_WAIT1();
        __syncthreads();
        if (kc + 2 < kiters) load_stage((kc + 2) % NSTAGE, kc + 2);
        CP_COMMIT();

        const uint32_t sbase = sb + (uint32_t)(kc % NSTAGE) * KV_STG;
        #pragma unroll
        for (int ks = 0; ks < 2; ++ks) {
            uint32_t a[4][4], b[4][2];
            #pragma unroll
            for (int mt = 0; mt < 4; ++mt) {
                int row = warp_m * 64 + mt * 16 + (lane & 15);
                uint32_t ad = sbase + row * 80 + ks * 32 + ((lane >> 4) << 4);
                ldsm_x4(a[mt], ad);
            }
            #pragma unroll
            for (int h = 0; h < 2; ++h) {
                int row = warp_n * 32 + h * 16 + ((lane >> 4) << 3) + (lane & 7);
                uint32_t ad = sbase + bOff + row * 80 + ks * 32 + (((lane >> 3) & 1) << 4);
                uint32_t rr[4];
                ldsm_x4(rr, ad);
                b[h * 2][0] = rr[0]; b[h * 2][1] = rr[1];
                b[h * 2 + 1][0] = rr[2]; b[h * 2 + 1][1] = rr[3];
            }
            #pragma unroll
            for (int mt = 0; mt < 4; ++mt)
                #pragma unroll
                for (int nt = 0; nt < 4; ++nt)
                    mma16816h(acc[mt][nt], a[mt], b[nt]);
        }
    }

    __half* outH = half_sel ? outV : outK;
    const int gId = lane >> 2, t4 = lane & 3;
    const int rowB = blockIdx.y * 128 + warp_m * 64 + gId;

    #pragma unroll
    for (int mt = 0; mt < 4; ++mt)
        #pragma unroll
        for (int nt = 0; nt < 4; ++nt) {
            const int col = n0 + warp_n * 32 + nt * 8 + t4 * 2;
            const int r0 = rowB + mt * 16;
            float* cc = acc[mt][nt];
            #pragma unroll
            for (int h = 0; h < 2; ++h) {
                size_t o = (size_t)(r0 + h * 8) * DMODEL + col;
                __half2 hv;
                hv.x = __float2half(cc[h * 2]);
                hv.y = __float2half(cc[h * 2 + 1]);
                *(__half2*)(outH + o) = hv;
            }
        }
}

// ---------------------------------------------------------------------------
// QK logits: fp16 single-term. Epilogue: *1/16, mel-mask -> fp32 attn region.
// ---------------------------------------------------------------------------
__global__ void __launch_bounds__(256) gemm_qk(
    const __half* __restrict__ Q, const __half* __restrict__ Kb,
    const int* __restrict__ mask, float* __restrict__ attn)
{
    extern __shared__ char smem[];
    const uint32_t sb = smem_u32(smem);
    const int tid = threadIdx.x;
    const int wid = tid >> 5, lane = tid & 31;
    const int warp_m = wid & 1, warp_n = wid >> 1;
    const int z = blockIdx.z;
    const int n0 = blockIdx.x * 128;
    const int K = DMODEL;

    const __half* gA = Q + (size_t)z * SRC_LEN * DMODEL + (size_t)blockIdx.y * 128 * K;
    const __half* gB = Kb + (size_t)z * MEL_LEN * DMODEL + (size_t)n0 * K;

    const int kiters = K >> 5;   // 8

    auto load_stage = [&](int stg, int kc) {
        const uint32_t sbase = sb + (uint32_t)stg * H_STG;
        const int k0 = kc << 5;
        #pragma unroll
        for (int i = 0; i < 2; ++i) {
            int q = tid + i * 256;
            int r = q >> 2, c = q & 3;
            uint32_t so = sbase + r * 80 + c * 16;
            size_t g = (size_t)r * K + k0 + c * 8;
            cp16(so, gA + g);
            cp16(so + 10240u, gB + g);
        }
    };

    float acc[4][4][4] = {};

    load_stage(0, 0); CP_COMMIT();
    load_stage(1, 1); CP_COMMIT();

    for (int kc = 0; kc < kiters; ++kc) {
        CP_WAIT1();
        __syncthreads();
        if (kc + 2 < kiters) load_stage((kc + 2) % NSTAGE, kc + 2);
        CP_COMMIT();

        const uint32_t sbase = sb + (uint32_t)(kc % NSTAGE) * H_STG;
        #pragma unroll
        for (int ks = 0; ks < 2; ++ks) {
            uint32_t a[4][4], b[4][2];
            #pragma unroll
            for (int mt = 0; mt < 4; ++mt) {
                int row = warp_m * 64 + mt * 16 + (lane & 15);
                uint32_t ad = sbase + row * 80 + ks * 32 + ((lane >> 4) << 4);
                ldsm_x4(a[mt], ad);
            }
            #pragma unroll
            for (int h = 0; h < 2; ++h) {
                int row = warp_n * 32 + h * 16 + ((lane >> 4) << 3) + (lane & 7);
                uint32_t ad = sbase + 10240u + row * 80 + ks * 32 + (((lane >> 3) & 1) << 4);
                uint32_t rr[4];
                ldsm_x4(rr, ad);
                b[h * 2][0] = rr[0]; b[h * 2][1] = rr[1];
                b[h * 2 + 1][0] = rr[2]; b[h * 2 + 1][1] = rr[3];
            }
            #pragma unroll
            for (int mt = 0; mt < 4; ++mt)
                #pragma unroll
                for (int nt = 0; nt < 4; ++nt)
                    mma16816h(acc[mt][nt], a[mt], b[nt]);
        }
    }

    const int gId = lane >> 2, t4 = lane & 3;
    const int rowB = blockIdx.y * 128 + warp_m * 64 + gId;
    float* O = attn + (size_t)z * SRC_LEN * MEL_LEN;

    #pragma unroll
    for (int mt = 0; mt < 4; ++mt)
        #pragma unroll
        for (int nt = 0; nt < 4; ++nt) {
            const int col = n0 + warp_n * 32 + nt * 8 + t4 * 2;
            const int r0 = rowB + mt * 16;
            const int* mk = mask + z * MEL_LEN + col;
            const int m0 = mk[0], m1 = mk[1];
            float* cc = acc[mt][nt];
            float2 v0, v1;
            v0.x = m0 ? -1e30f : cc[0] * 0.0625f;
            v0.y = m1 ? -1e30f : cc[1] * 0.0625f;
            v1.x = m0 ? -1e30f : cc[2] * 0.0625f;
            v1.y = m1 ? -1e30f : cc[3] * 0.0625f;
            *(float2*)(O + (size_t)r0 * MEL_LEN + col) = v0;
            *(float2*)(O + (size_t)(r0 + 8) * MEL_LEN + col) = v1;
        }
}

// ---------------------------------------------------------------------------
// PV GEMM, split-K x2: O_half[b] = P[b][:, half*1024 : +1024] @ V[b][half...].
// grid (2, 4, 32): x=ntile, y=mtile, z = batch*2 + half. 256 CTAs = 1 wave.
// ---------------------------------------------------------------------------
__global__ void __launch_bounds__(256) gemm_pv(
    const __half* __restrict__ P, const __half* __restrict__ V,
    float* __restrict__ out0, float* __restrict__ out1)
{
    extern __shared__ char smem[];
    const uint32_t sb = smem_u32(smem);
    const int tid = threadIdx.x;
    const int wid = tid >> 5, lane = tid & 31;
    const int warp_m = wid & 1, warp_n = wid >> 1;
    const int z = blockIdx.z;
    const int batch = z >> 1, khalf = z & 1;
    const int n0 = blockIdx.x * 128;
    const int K = MEL_LEN;
    const int kbase = khalf * (MEL_LEN / 2);

    const __half* gA = P + (size_t)batch * SRC_LEN * MEL_LEN
                         + (size_t)blockIdx.y * 128 * K + kbase;
    const __half* gB = V + (size_t)batch * MEL_LEN * DMODEL
                         + (size_t)kbase * DMODEL + n0;

    const int kiters = (MEL_LEN / 2) >> 5;   // 32

    auto load_stage = [&](int stg, int kc) {
        const uint32_t sbase = sb + (uint32_t)stg * H_STG;
        const int k0 = kc << 5;
        #pragma unroll
        for (int i = 0; i < 2; ++i) {
            int q = tid + i * 256;
            int r = q >> 2, c = q & 3;
            cp16(sbase + r * 80 + c * 16, gA + (size_t)r * K + k0 + c * 8);
        }
        #pragma unroll
        for (int i = 0; i < 2; ++i) {
            int q = tid + i * 256;
            int r = q >> 4, c = q & 15;
            cp16(sbase + 10240u + r * 272 + c * 16, gB + (size_t)(k0 + r) * DMODEL + c * 8);
        }
    };

    float acc[4][4][4] = {};

    load_stage(0, 0); CP_COMMIT();
    load_stage(1, 1); CP_COMMIT();

    for (int kc = 0; kc < kiters; ++kc) {
        CP_WAIT1();
        __syncthreads();
        if (kc + 2 < kiters) load_stage((kc + 2) % NSTAGE, kc + 2);
        CP_COMMIT();

        const uint32_t sbase = sb + (uint32_t)(kc % NSTAGE) * H_STG;
        #pragma unroll
        for (int ks = 0; ks < 2; ++ks) {
            uint32_t a[4][4], b[4][2];
            #pragma unroll
            for (int mt = 0; mt < 4; ++mt) {
                int row = warp_m * 64 + mt * 16 + (lane & 15);
                uint32_t ad = sbase + row * 80 + ks * 32 + ((lane >> 4) << 4);
                ldsm_x4(a[mt], ad);
            }
            #pragma unroll
            for (int nt = 0; nt < 4; ++nt) {
                uint32_t ad = sbase + 10240u + (ks * 16 + (lane & 15)) * 272
                            + (warp_n * 32 + nt * 8) * 2;
                ldsm_x2t(b[nt], ad);
            }
            #pragma unroll
            for (int mt = 0; mt < 4; ++mt)
                #pragma unroll
                for (int nt = 0; nt < 4; ++nt)
                    mma16816h(acc[mt][nt], a[mt], b[nt]);
        }
    }

    const int gId = lane >> 2, t4 = lane & 3;
    const int rowB = blockIdx.y * 128 + warp_m * 64 + gId;
    float* O = (khalf ? out1 : out0) + (size_t)batch * SRC_LEN * DMODEL;

    #pragma unroll
    for (int mt = 0; mt < 4; ++mt)
        #pragma unroll
        for (int nt = 0; nt < 4; ++nt) {
            const int col = n0 + warp_n * 32 + nt * 8 + t4 * 2;
            const int r0 = rowB + mt * 16;
            float* cc = acc[mt][nt];
            *(float2*)(O + (size_t)r0 * DMODEL + col) = make_float2(cc[0], cc[1]);
            *(float2*)(O + (size_t)(r0 + 8) * DMODEL + col) = make_float2(cc[2], cc[3]);
        }
}

// ---------------------------------------------------------------------------
// Row softmax over 2048 keys (in place fp32) + fp16 P emit for PV.
// ---------------------------------------------------------------------------
__global__ void __launch_bounds__(256) softmax_kernel(
    float* __restrict__ attn, const int* __restrict__ src_mask,
    __half* __restrict__ pf)
{
    const int row = blockIdx.x;
    const int tid = threadIdx.x;
    float* p = attn + (size_t)row * MEL_LEN;

    float v[8];
    float m = -3.0e38f;
    #pragma unroll
    for (int i = 0; i < 8; ++i) { v[i] = p[tid + i * 256]; m = fmaxf(m, v[i]); }

    __shared__ float red[9];
    #pragma unroll
    for (int o = 16; o > 0; o >>= 1) m = fmaxf(m, __shfl_xor_sync(0xffffffffu, m, o));
    if ((tid & 31) == 0) red[tid >> 5] = m;
    __syncthreads();
    if (tid == 0) {
        float mm = red[0];
        #pragma unroll
        for (int i = 1; i < 8; ++i) mm = fmaxf(mm, red[i]);
        red[8] = mm;
    }
    __syncthreads();
    m = red[8];

    float s = 0.0f;
    #pragma unroll
    for (int i = 0; i < 8; ++i) { v[i] = expf(v[i] - m); s += v[i]; }
    #pragma unroll
    for (int o = 16; o > 0; o >>= 1) s += __shfl_xor_sync(0xffffffffu, s, o);
    __syncthreads();
    if ((tid & 31) == 0) red[tid >> 5] = s;
    __syncthreads();
    if (tid == 0) {
        float ss = 0.0f;
        #pragma unroll
        for (int i = 0; i < 8; ++i) ss += red[i];
        red[8] = ss;
    }
    __syncthreads();
    s = red[8];

    const float zf = src_mask[row] ? 0.0f : (1.0f / s);
    __half* ph = pf + (size_t)row * MEL_LEN;
    #pragma unroll
    for (int i = 0; i < 8; ++i) {
        float pv = v[i] * zf;
        p[tid + i * 256] = pv;
        ph[tid + i * 256] = __float2half(pv);
    }
}

// ---------------------------------------------------------------------------
// LayerNorm over last dim (256): sums the two PV partials, normalizes,
// writes final output.
// ---------------------------------------------------------------------------
__global__ void __launch_bounds__(256) ln_kernel(
    const float* __restrict__ o0, const float* __restrict__ o1,
    const float* __restrict__ gamma, const float* __restrict__ beta,
    float* __restrict__ out)
{
    const int row = blockIdx.x;
    const int tid = threadIdx.x;
    const size_t base = (size_t)row * DMODEL + tid;
    float v = o0[base] + o1[base];

    __shared__ float red[9];
    float s = v;
    #pragma unroll
    for (int off = 16; off > 0; off >>= 1) s += __shfl_xor_sync(0xffffffffu, s, off);
    if ((tid & 31) == 0) red[tid >> 5] = s;
    __syncthreads();
    if (tid == 0) {
        float ss = 0.0f;
        #pragma unroll
        for (int i = 0; i < 8; ++i) ss += red[i];
        red[8] = ss * (1.0f / DMODEL);
    }
    __syncthreads();
    const float mu = red[8];
    __syncthreads();

    float d = v - mu;
    float q = d * d;
    #pragma unroll
    for (int off = 16; off > 0; off >>= 1) q += __shfl_xor_sync(0xffffffffu, q, off);
    if ((tid & 31) == 0) red[tid >> 5] = q;
    __syncthreads();
    if (tid == 0) {
        float qq = 0.0f;
        #pragma unroll
        for (int i = 0; i < 8; ++i) qq += red[i];
        red[8] = rsqrtf(qq * (1.0f / DMODEL) + 1e-5f);
    }
    __syncthreads();
    out[base] = d * red[8] * gamma[tid] + beta[tid];
}

// ---------------------------------------------------------------------------
extern "C" void kernel_launch(void* const* d_in, const int* in_sizes, int n_in,
                              void* d_out, int out_size)
{
    const float* mel      = (const float*)d_in[0];
    const float* text     = (const float*)d_in[1];
    const int*   mel_mask = (const int*)d_in[2];
    const int*   src_mask = (const int*)d_in[3];
    const float* Wq       = (const float*)d_in[4];
    const float* Wk       = (const float*)d_in[5];
    const float* Wv       = (const float*)d_in[6];
    const float* gamma    = (const float*)d_in[7];
    const float* beta     = (const float*)d_in[8];

    float* out      = (float*)d_out;
    float* out_o    = out;                                      // [16,512,256]
    float* out_attn = out + (size_t)BATCH * SRC_LEN * DMODEL;   // [16,512,2048]

    __half *mf16, *tf16, *wqf, *wkf, *wvf, *qf16, *kf16, *vf16, *pf16;
    float *op0, *op1;
    cudaGetSymbolAddress((void**)&mf16, Mf16);
    cudaGetSymbolAddress((void**)&tf16, Tf16);
    cudaGetSymbolAddress((void**)&wqf, Wqf16);
    cudaGetSymbolAddress((void**)&wkf, Wkf16);
    cudaGetSymbolAddress((void**)&wvf, Wvf16);
    cudaGetSymbolAddress((void**)&qf16, Qf16);
    cudaGetSymbolAddress((void**)&kf16, Kf16);
    cudaGetSymbolAddress((void**)&vf16, Vf16);
    cudaGetSymbolAddress((void**)&pf16, Pf16);
    cudaGetSymbolAddress((void**)&op0, Opart0);
    cudaGetSymbolAddress((void**)&op1, Opart1);

    cudaFuncSetAttribute(gemm_projh,  cudaFuncAttributeMaxDynamicSharedMemorySize, H_SMEM);
    cudaFuncSetAttribute(gemm_projkv, cudaFuncAttributeMaxDynamicSharedMemorySize, KV_SMEM);
    cudaFuncSetAttribute(gemm_qk,     cudaFuncAttributeMaxDynamicSharedMemorySize, H_SMEM);
    cudaFuncSetAttribute(gemm_pv,     cudaFuncAttributeMaxDynamicSharedMemorySize, H_SMEM);

    // 1) Fused prep: everything -> fp16
    prep_kernel<<<(QUADS_TOT + 255) / 256, 256>>>(
        mel, text, Wq, Wk, Wv, mf16, tf16, wqf, wkf, wvf);

    // 2) Projections: Q; K+V merged
    gemm_projh<<<dim3(2, 64), 256, H_SMEM>>>(tf16, wqf, qf16);
    gemm_projkv<<<dim3(2, 256), 512, KV_SMEM>>>(mf16, wkf, wvf, kf16, vf16);

    // 3) Logits: *1/16 + mel mask -> fp32 attn region
    gemm_qk<<<dim3(MEL_LEN / 128, SRC_LEN / 128, BATCH), 256, H_SMEM>>>(
        qf16, kf16, mel_mask, out_attn);

    // 4) Softmax + src mask + fp16 P emit
    softmax_kernel<<<BATCH * SRC_LEN, 256>>>(out_attn, src_mask, pf16);

    // 5) O = P @ V  split-K x2 -> partial buffers (256 CTAs = full machine)
    gemm_pv<<<dim3(DMODEL / 128, SRC_LEN / 128, BATCH * 2), 256, H_SMEM>>>(
        pf16, vf16, op0, op1);

    // 6) LayerNorm (sums partials)
    ln_kernel<<<BATCH * SRC_LEN, 256>>>(op0, op1, gamma, beta, out_o);
}

// round 12
// speedup vs baseline: 4.8725x; 1.0397x over previous
#include <cuda_runtime.h>
#include <cuda_fp16.h>
#include <math.h>
#include <stdint.h>

#define BATCH   16
#define SRC_LEN 512
#define MEL_LEN 2048
#define DMODEL  256

#define N_MEL  (BATCH * MEL_LEN * DMODEL)
#define N_TEXT (BATCH * SRC_LEN * DMODEL)
#define N_W    (DMODEL * DMODEL)

// ---------------------------------------------------------------------------
// Device-global scratch
// ---------------------------------------------------------------------------
__device__ __half Mf16[N_MEL];
__device__ __half Tf16[N_TEXT];
__device__ __half Wqf16[N_W], Wkf16[N_W], Wvf16[N_W];
__device__ __half Qf16[BATCH * SRC_LEN * DMODEL];
__device__ __half Kf16[BATCH * MEL_LEN * DMODEL];
__device__ __half Vf16[BATCH * MEL_LEN * DMODEL];
__device__ __half Pf16[BATCH * SRC_LEN * MEL_LEN];
__device__ float  Opart0[N_TEXT];
__device__ float  Opart1[N_TEXT];

// ---------------------------------------------------------------------------
// PTX helpers
// ---------------------------------------------------------------------------
__device__ __forceinline__ uint32_t smem_u32(const void* p) {
    uint32_t a;
    asm("{ .reg .u64 t; cvta.to.shared.u64 t, %1; cvt.u32.u64 %0, t; }" : "=r"(a) : "l"(p));
    return a;
}
__device__ __forceinline__ void cp16(uint32_t s, const void* g) {
    asm volatile("cp.async.cg.shared.global [%0], [%1], 16;"
                 :: "r"(s), "l"(__cvta_generic_to_global(g)));
}
#define CP_COMMIT() asm volatile("cp.async.commit_group;" ::: "memory")
#define CP_WAIT1()  asm volatile("cp.async.wait_group 1;" ::: "memory")

__device__ __forceinline__ void ldsm_x4(uint32_t* r, uint32_t a) {
    asm volatile("ldmatrix.sync.aligned.m8n8.x4.shared.b16 {%0,%1,%2,%3}, [%4];"
                 : "=r"(r[0]), "=r"(r[1]), "=r"(r[2]), "=r"(r[3]) : "r"(a));
}
__device__ __forceinline__ void ldsm_x2t(uint32_t* r, uint32_t a) {
    asm volatile("ldmatrix.sync.aligned.m8n8.x2.trans.shared.b16 {%0,%1}, [%2];"
                 : "=r"(r[0]), "=r"(r[1]) : "r"(a));
}
__device__ __forceinline__ void mma16816h(float* c, const uint32_t* a, const uint32_t* b) {
    asm volatile(
        "mma.sync.aligned.m16n8k16.row.col.f32.f16.f16.f32 "
        "{%0,%1,%2,%3}, {%4,%5,%6,%7}, {%8,%9}, {%0,%1,%2,%3};"
        : "+f"(c[0]), "+f"(c[1]), "+f"(c[2]), "+f"(c[3])
        : "r"(a[0]), "r"(a[1]), "r"(a[2]), "r"(a[3]), "r"(b[0]), "r"(b[1]));
}

// ---------------------------------------------------------------------------
// Fused prep: fp32 -> fp16 (float4-vectorized)
// ---------------------------------------------------------------------------
#define QUADS_MEL  (N_MEL / 4)
#define QUADS_TEXT (N_TEXT / 4)
#define QUADS_W    (N_W / 4)
#define QUADS_TOT  (QUADS_MEL + QUADS_TEXT + 3 * QUADS_W)

__global__ void __launch_bounds__(256) prep_kernel(
    const float* __restrict__ mel, const float* __restrict__ text,
    const float* __restrict__ Wq, const float* __restrict__ Wk,
    const float* __restrict__ Wv,
    __half* __restrict__ mf, __half* __restrict__ tf,
    __half* __restrict__ wqf, __half* __restrict__ wkf, __half* __restrict__ wvf)
{
    int i = blockIdx.x * 256 + threadIdx.x;
    const float* src;
    __half* dst;
    if (i < QUADS_MEL)                        { src = mel;  dst = mf; }
    else if ((i -= QUADS_MEL) < QUADS_TEXT)   { src = text; dst = tf; }
    else if ((i -= QUADS_TEXT) < QUADS_W)     { src = Wq;   dst = wqf; }
    else if ((i -= QUADS_W) < QUADS_W)        { src = Wk;   dst = wkf; }
    else if ((i -= QUADS_W) < QUADS_W)        { src = Wv;   dst = wvf; }
    else return;
    float4 v = ((const float4*)src)[i];
    __half2* d = (__half2*)dst + 2 * i;
    d[0] = __floats2half2_rn(v.x, v.y);
    d[1] = __floats2half2_rn(v.z, v.w);
}

#define NSTAGE 3

// K-chunk 64 layouts: k-major tile row = 128B data + 16B pad = 144B stride.
#define ROW_A  144
#define TILE_A 18432            // 128 rows * 144
#define ROW_BN 272              // pv B: 256B data + 16B pad
#define TILE_BN 17408           // 64 rows * 272

#define H2_STG  (2 * TILE_A)            // A + B(k-major)
#define H2_SMEM (NSTAGE * H2_STG)
#define PV_STG  (TILE_A + TILE_BN)
#define PV_SMEM (NSTAGE * PV_STG)
#define KV_STG  (3 * TILE_A)
#define KV_SMEM (NSTAGE * KV_STG)

// Fragment load helpers (chunk-64): ks in 0..3
__device__ __forceinline__ void load_a_frags(
    uint32_t a[4][4], uint32_t abase, int warp_m, int lane, int ks)
{
    #pragma unroll
    for (int mt = 0; mt < 4; ++mt) {
        int row = warp_m * 64 + mt * 16 + (lane & 15);
        ldsm_x4(a[mt], abase + row * ROW_A + ks * 32 + ((lane >> 4) << 4));
    }
}
__device__ __forceinline__ void load_b_frags_k(
    uint32_t b[4][2], uint32_t bbase, int warp_n, int lane, int ks)
{
    #pragma unroll
    for (int h = 0; h < 2; ++h) {
        int row = warp_n * 32 + h * 16 + ((lane >> 4) << 3) + (lane & 7);
        uint32_t rr[4];
        ldsm_x4(rr, bbase + row * ROW_A + ks * 32 + (((lane >> 3) & 1) << 4));
        b[h * 2][0] = rr[0]; b[h * 2][1] = rr[1];
        b[h * 2 + 1][0] = rr[2]; b[h * 2 + 1][1] = rr[3];
    }
}
__device__ __forceinline__ void mma_tile(
    float acc[4][4][4], uint32_t a[4][4], uint32_t b[4][2])
{
    #pragma unroll
    for (int mt = 0; mt < 4; ++mt)
        #pragma unroll
        for (int nt = 0; nt < 4; ++nt)
            mma16816h(acc[mt][nt], a[mt], b[nt]);
}

// ---------------------------------------------------------------------------
// Q projection GEMM (single fp16): A[m][k] @ B[n][k]^T -> fp16, K=256.
// ---------------------------------------------------------------------------
__global__ void __launch_bounds__(256) gemm_projh(
    const __half* __restrict__ A, const __half* __restrict__ B,
    __half* __restrict__ outH)
{
    extern __shared__ char smem[];
    const uint32_t sb = smem_u32(smem);
    const int tid = threadIdx.x;
    const int wid = tid >> 5, lane = tid & 31;
    const int warp_m = wid & 1, warp_n = wid >> 1;
    const int n0 = blockIdx.x * 128;
    const int K = DMODEL;

    const __half* gA = A + (size_t)blockIdx.y * 128 * K;
    const __half* gB = B + (size_t)n0 * K;

    const int kiters = K >> 6;   // 4

    auto load_stage = [&](int stg, int kc) {
        const uint32_t sbase = sb + (uint32_t)stg * H2_STG;
        const int k0 = kc << 6;
        #pragma unroll
        for (int i = 0; i < 4; ++i) {
            int q = tid + i * 256;
            int r = q >> 3, c = q & 7;
            uint32_t so = sbase + r * ROW_A + c * 16;
            size_t g = (size_t)r * K + k0 + c * 8;
            cp16(so, gA + g);
            cp16(so + TILE_A, gB + g);
        }
    };

    float acc[4][4][4] = {};

    load_stage(0, 0); CP_COMMIT();
    load_stage(1, 1); CP_COMMIT();

    for (int kc = 0; kc < kiters; ++kc) {
        CP_WAIT1();
        __syncthreads();
        if (kc + 2 < kiters) load_stage((kc + 2) % NSTAGE, kc + 2);
        CP_COMMIT();

        const uint32_t sbase = sb + (uint32_t)(kc % NSTAGE) * H2_STG;
        #pragma unroll
        for (int ks = 0; ks < 4; ++ks) {
            uint32_t a[4][4], b[4][2];
            load_a_frags(a, sbase, warp_m, lane, ks);
            load_b_frags_k(b, sbase + TILE_A, warp_n, lane, ks);
            mma_tile(acc, a, b);
        }
    }

    const int gId = lane >> 2, t4 = lane & 3;
    const int rowB = blockIdx.y * 128 + warp_m * 64 + gId;

    #pragma unroll
    for (int mt = 0; mt < 4; ++mt)
        #pragma unroll
        for (int nt = 0; nt < 4; ++nt) {
            const int col = n0 + warp_n * 32 + nt * 8 + t4 * 2;
            const int r0 = rowB + mt * 16;
            float* cc = acc[mt][nt];
            #pragma unroll
            for (int h = 0; h < 2; ++h) {
                size_t o = (size_t)(r0 + h * 8) * DMODEL + col;
                __half2 hv;
                hv.x = __float2half(cc[h * 2]);
                hv.y = __float2half(cc[h * 2 + 1]);
                *(__half2*)(outH + o) = hv;
            }
        }
}

// ---------------------------------------------------------------------------
// Merged K+V projection: 512 threads, shared A tile.
// ---------------------------------------------------------------------------
__global__ void __launch_bounds__(512) gemm_projkv(
    const __half* __restrict__ A, const __half* __restrict__ Bk,
    const __half* __restrict__ Bv,
    __half* __restrict__ outK, __half* __restrict__ outV)
{
    extern __shared__ char smem[];
    const uint32_t sb = smem_u32(smem);
    const int tid = threadIdx.x;
    const int wid = tid >> 5, lane = tid & 31;
    const int half_sel = wid >> 3;
    const int w8 = wid & 7;
    const int warp_m = w8 & 1, warp_n = w8 >> 1;
    const int n0 = blockIdx.x * 128;
    const int K = DMODEL;

    const __half* gA  = A + (size_t)blockIdx.y * 128 * K;
    const __half* gBk = Bk + (size_t)n0 * K;
    const __half* gBv = Bv + (size_t)n0 * K;

    const int kiters = K >> 6;   // 4

    auto load_stage = [&](int stg, int kc) {
        const uint32_t sbase = sb + (uint32_t)stg * KV_STG;
        const int k0 = kc << 6;
        #pragma unroll
        for (int i = 0; i < 2; ++i) {
            int q = tid + i * 512;
            int r = q >> 3, c = q & 7;
            uint32_t so = sbase + r * ROW_A + c * 16;
            size_t g = (size_t)r * K + k0 + c * 8;
            cp16(so, gA + g);
            cp16(so + TILE_A, gBk + g);
            cp16(so + 2 * TILE_A, gBv + g);
        }
    };

    float acc[4][4][4] = {};

    load_stage(0, 0); CP_COMMIT();
    load_stage(1, 1); CP_COMMIT();

    const uint32_t bOff = TILE_A + (uint32_t)half_sel * TILE_A;

    for (int kc = 0; kc < kiters; ++kc) {
        CP_WAIT1();
        __syncthreads();
        if (kc + 2 < kiters) load_stage((kc + 2) % NSTAGE, kc + 2);
        CP_COMMIT();

        const uint32_t sbase = sb + (uint32_t)(kc % NSTAGE) * KV_STG;
        #pragma unroll
        for (int ks = 0; ks < 4; ++ks) {
            uint32_t a[4][4], b[4][2];
            load_a_frags(a, sbase, warp_m, lane, ks);
            load_b_frags_k(b, sbase + bOff, warp_n, lane, ks);
            mma_tile(acc, a, b);
        }
    }

    __half* outH = half_sel ? outV : outK;
    const int gId = lane >> 2, t4 = lane & 3;
    const int rowB = blockIdx.y * 128 + warp_m * 64 + gId;

    #pragma unroll
    for (int mt = 0; mt < 4; ++mt)
        #pragma unroll
        for (int nt = 0; nt < 4; ++nt) {
            const int col = n0 + warp_n * 32 + nt * 8 + t4 * 2;
            const int r0 = rowB + mt * 16;
            float* cc = acc[mt][nt];
            #pragma unroll
            for (int h = 0; h < 2; ++h) {
                size_t o = (size_t)(r0 + h * 8) * DMODEL + col;
                __half2 hv;
                hv.x = __float2half(cc[h * 2]);
                hv.y = __float2half(cc[h * 2 + 1]);
                *(__half2*)(outH + o) = hv;
            }
        }
}

// ---------------------------------------------------------------------------
// QK logits: fp16 single-term, *1/16 + mel-mask -> fp32 attn region.
// ---------------------------------------------------------------------------
__global__ void __launch_bounds__(256) gemm_qk(
    const __half* __restrict__ Q, const __half* __restrict__ Kb,
    const int* __restrict__ mask, float* __restrict__ attn)
{
    extern __shared__ char smem[];
    const uint32_t sb = smem_u32(smem);
    const int tid = threadIdx.x;
    const int wid = tid >> 5, lane = tid & 31;
    const int warp_m = wid & 1, warp_n = wid >> 1;
    const int z = blockIdx.z;
    const int n0 = blockIdx.x * 128;
    const int K = DMODEL;

    const __half* gA = Q + (size_t)z * SRC_LEN * DMODEL + (size_t)blockIdx.y * 128 * K;
    const __half* gB = Kb + (size_t)z * MEL_LEN * DMODEL + (size_t)n0 * K;

    const int kiters = K >> 6;   // 4

    auto load_stage = [&](int stg, int kc) {
        const uint32_t sbase = sb + (uint32_t)stg * H2_STG;
        const int k0 = kc << 6;
        #pragma unroll
        for (int i = 0; i < 4; ++i) {
            int q = tid + i * 256;
            int r = q >> 3, c = q & 7;
            uint32_t so = sbase + r * ROW_A + c * 16;
            size_t g = (size_t)r * K + k0 + c * 8;
            cp16(so, gA + g);
            cp16(so + TILE_A, gB + g);
        }
    };

    float acc[4][4][4] = {};

    load_stage(0, 0); CP_COMMIT();
    load_stage(1, 1); CP_COMMIT();

    for (int kc = 0; kc < kiters; ++kc) {
        CP_WAIT1();
        __syncthreads();
        if (kc + 2 < kiters) load_stage((kc + 2) % NSTAGE, kc + 2);
        CP_COMMIT();

        const uint32_t sbase = sb + (uint32_t)(kc % NSTAGE) * H2_STG;
        #pragma unroll
        for (int ks = 0; ks < 4; ++ks) {
            uint32_t a[4][4], b[4][2];
            load_a_frags(a, sbase, warp_m, lane, ks);
            load_b_frags_k(b, sbase + TILE_A, warp_n, lane, ks);
            mma_tile(acc, a, b);
        }
    }

    const int gId = lane >> 2, t4 = lane & 3;
    const int rowB = blockIdx.y * 128 + warp_m * 64 + gId;
    float* O = attn + (size_t)z * SRC_LEN * MEL_LEN;

    #pragma unroll
    for (int mt = 0; mt < 4; ++mt)
        #pragma unroll
        for (int nt = 0; nt < 4; ++nt) {
            const int col = n0 + warp_n * 32 + nt * 8 + t4 * 2;
            const int r0 = rowB + mt * 16;
            const int* mk = mask + z * MEL_LEN + col;
            const int m0 = mk[0], m1 = mk[1];
            float* cc = acc[mt][nt];
            float2 v0, v1;
            v0.x = m0 ? -1e30f : cc[0] * 0.0625f;
            v0.y = m1 ? -1e30f : cc[1] * 0.0625f;
            v1.x = m0 ? -1e30f : cc[2] * 0.0625f;
            v1.y = m1 ? -1e30f : cc[3] * 0.0625f;
            *(float2*)(O + (size_t)r0 * MEL_LEN + col) = v0;
            *(float2*)(O + (size_t)(r0 + 8) * MEL_LEN + col) = v1;
        }
}

// ---------------------------------------------------------------------------
// PV GEMM, split-K x2. B is [k][n]; ldmatrix.trans.
// ---------------------------------------------------------------------------
__global__ void __launch_bounds__(256) gemm_pv(
    const __half* __restrict__ P, const __half* __restrict__ V,
    float* __restrict__ out0, float* __restrict__ out1)
{
    extern __shared__ char smem[];
    const uint32_t sb = smem_u32(smem);
    const int tid = threadIdx.x;
    const int wid = tid >> 5, lane = tid & 31;
    const int warp_m = wid & 1, warp_n = wid >> 1;
    const int z = blockIdx.z;
    const int batch = z >> 1, khalf = z & 1;
    const int n0 = blockIdx.x * 128;
    const int K = MEL_LEN;
    const int kbase = khalf * (MEL_LEN / 2);

    const __half* gA = P + (size_t)batch * SRC_LEN * MEL_LEN
                         + (size_t)blockIdx.y * 128 * K + kbase;
    const __half* gB = V + (size_t)batch * MEL_LEN * DMODEL
                         + (size_t)kbase * DMODEL + n0;

    const int kiters = (MEL_LEN / 2) >> 6;   // 16

    auto load_stage = [&](int stg, int kc) {
        const uint32_t sbase = sb + (uint32_t)stg * PV_STG;
        const int k0 = kc << 6;
        #pragma unroll
        for (int i = 0; i < 4; ++i) {
            int q = tid + i * 256;
            int r = q >> 3, c = q & 7;
            cp16(sbase + r * ROW_A + c * 16, gA + (size_t)r * K + k0 + c * 8);
        }
        #pragma unroll
        for (int i = 0; i < 4; ++i) {
            int q = tid + i * 256;
            int r = q >> 4, c = q & 15;
            cp16(sbase + TILE_A + r * ROW_BN + c * 16,
                 gB + (size_t)(k0 + r) * DMODEL + c * 8);
        }
    };

    float acc[4][4][4] = {};

    load_stage(0, 0); CP_COMMIT();
    load_stage(1, 1); CP_COMMIT();

    for (int kc = 0; kc < kiters; ++kc) {
        CP_WAIT1();
        __syncthreads();
        if (kc + 2 < kiters) load_stage((kc + 2) % NSTAGE, kc + 2);
        CP_COMMIT();

        const uint32_t sbase = sb + (uint32_t)(kc % NSTAGE) * PV_STG;
        #pragma unroll
        for (int ks = 0; ks < 4; ++ks) {
            uint32_t a[4][4], b[4][2];
            load_a_frags(a, sbase, warp_m, lane, ks);
            #pragma unroll
            for (int nt = 0; nt < 4; ++nt) {
                uint32_t ad = sbase + TILE_A + (ks * 16 + (lane & 15)) * ROW_BN
                            + (warp_n * 32 + nt * 8) * 2;
                ldsm_x2t(b[nt], ad);
            }
            mma_tile(acc, a, b);
        }
    }

    const int gId = lane >> 2, t4 = lane & 3;
    const int rowB = blockIdx.y * 128 + warp_m * 64 + gId;
    float* O = (khalf ? out1 : out0) + (size_t)batch * SRC_LEN * DMODEL;

    #pragma unroll
    for (int mt = 0; mt < 4; ++mt)
        #pragma unroll
        for (int nt = 0; nt < 4; ++nt) {
            const int col = n0 + warp_n * 32 + nt * 8 + t4 * 2;
            const int r0 = rowB + mt * 16;
            float* cc = acc[mt][nt];
            *(float2*)(O + (size_t)r0 * DMODEL + col) = make_float2(cc[0], cc[1]);
            *(float2*)(O + (size_t)(r0 + 8) * DMODEL + col) = make_float2(cc[2], cc[3]);
        }
}

// ---------------------------------------------------------------------------
// Row softmax over 2048 keys (in place fp32) + fp16 P emit.
// ---------------------------------------------------------------------------
__global__ void __launch_bounds__(256) softmax_kernel(
    float* __restrict__ attn, const int* __restrict__ src_mask,
    __half* __restrict__ pf)
{
    const int row = blockIdx.x;
    const int tid = threadIdx.x;
    float* p = attn + (size_t)row * MEL_LEN;

    float v[8];
    float m = -3.0e38f;
    #pragma unroll
    for (int i = 0; i < 8; ++i) { v[i] = p[tid + i * 256]; m = fmaxf(m, v[i]); }

    __shared__ float red[9];
    #pragma unroll
    for (int o = 16; o > 0; o >>= 1) m = fmaxf(m, __shfl_xor_sync(0xffffffffu, m, o));
    if ((tid & 31) == 0) red[tid >> 5] = m;
    __syncthreads();
    if (tid == 0) {
        float mm = red[0];
        #pragma unroll
        for (int i = 1; i < 8; ++i) mm = fmaxf(mm, red[i]);
        red[8] = mm;
    }
    __syncthreads();
    m = red[8];

    float s = 0.0f;
    #pragma unroll
    for (int i = 0; i < 8; ++i) { v[i] = expf(v[i] - m); s += v[i]; }
    #pragma unroll
    for (int o = 16; o > 0; o >>= 1) s += __shfl_xor_sync(0xffffffffu, s, o);
    __syncthreads();
    if ((tid & 31) == 0) red[tid >> 5] = s;
    __syncthreads();
    if (tid == 0) {
        float ss = 0.0f;
        #pragma unroll
        for (int i = 0; i < 8; ++i) ss += red[i];
        red[8] = ss;
    }
    __syncthreads();
    s = red[8];

    const float zf = src_mask[row] ? 0.0f : (1.0f / s);
    __half* ph = pf + (size_t)row * MEL_LEN;
    #pragma unroll
    for (int i = 0; i < 8; ++i) {
        float pv = v[i] * zf;
        p[tid + i * 256] = pv;
        ph[tid + i * 256] = __float2half(pv);
    }
}

// ---------------------------------------------------------------------------
// LayerNorm: sums PV partials, normalizes, writes final output.
// ---------------------------------------------------------------------------
__global__ void __launch_bounds__(256) ln_kernel(
    const float* __restrict__ o0, const float* __restrict__ o1,
    const float* __restrict__ gamma, const float* __restrict__ beta,
    float* __restrict__ out)
{
    const int row = blockIdx.x;
    const int tid = threadIdx.x;
    const size_t base = (size_t)row * DMODEL + tid;
    float v = o0[base] + o1[base];

    __shared__ float red[9];
    float s = v;
    #pragma unroll
    for (int off = 16; off > 0; off >>= 1) s += __shfl_xor_sync(0xffffffffu, s, off);
    if ((tid & 31) == 0) red[tid >> 5] = s;
    __syncthreads();
    if (tid == 0) {
        float ss = 0.0f;
        #pragma unroll
        for (int i = 0; i < 8; ++i) ss += red[i];
        red[8] = ss * (1.0f / DMODEL);
    }
    __syncthreads();
    const float mu = red[8];
    __syncthreads();

    float d = v - mu;
    float q = d * d;
    #pragma unroll
    for (int off = 16; off > 0; off >>= 1) q += __shfl_xor_sync(0xffffffffu, q, off);
    if ((tid & 31) == 0) red[tid >> 5] = q;
    __syncthreads();
    if (tid == 0) {
        float qq = 0.0f;
        #pragma unroll
        for (int i = 0; i < 8; ++i) qq += red[i];
        red[8] = rsqrtf(qq * (1.0f / DMODEL) + 1e-5f);
    }
    __syncthreads();
    out[base] = d * red[8] * gamma[tid] + beta[tid];
}

// ---------------------------------------------------------------------------
extern "C" void kernel_launch(void* const* d_in, const int* in_sizes, int n_in,
                              void* d_out, int out_size)
{
    const float* mel      = (const float*)d_in[0];
    const float* text     = (const float*)d_in[1];
    const int*   mel_mask = (const int*)d_in[2];
    const int*   src_mask = (const int*)d_in[3];
    const float* Wq       = (const float*)d_in[4];
    const float* Wk       = (const float*)d_in[5];
    const float* Wv       = (const float*)d_in[6];
    const float* gamma    = (const float*)d_in[7];
    const float* beta     = (const float*)d_in[8];

    float* out      = (float*)d_out;
    float* out_o    = out;
    float* out_attn = out + (size_t)BATCH * SRC_LEN * DMODEL;

    __half *mf16, *tf16, *wqf, *wkf, *wvf, *qf16, *kf16, *vf16, *pf16;
    float *op0, *op1;
    cudaGetSymbolAddress((void**)&mf16, Mf16);
    cudaGetSymbolAddress((void**)&tf16, Tf16);
    cudaGetSymbolAddress((void**)&wqf, Wqf16);
    cudaGetSymbolAddress((void**)&wkf, Wkf16);
    cudaGetSymbolAddress((void**)&wvf, Wvf16);
    cudaGetSymbolAddress((void**)&qf16, Qf16);
    cudaGetSymbolAddress((void**)&kf16, Kf16);
    cudaGetSymbolAddress((void**)&vf16, Vf16);
    cudaGetSymbolAddress((void**)&pf16, Pf16);
    cudaGetSymbolAddress((void**)&op0, Opart0);
    cudaGetSymbolAddress((void**)&op1, Opart1);

    cudaFuncSetAttribute(gemm_projh,  cudaFuncAttributeMaxDynamicSharedMemorySize, H2_SMEM);
    cudaFuncSetAttribute(gemm_projkv, cudaFuncAttributeMaxDynamicSharedMemorySize, KV_SMEM);
    cudaFuncSetAttribute(gemm_qk,     cudaFuncAttributeMaxDynamicSharedMemorySize, H2_SMEM);
    cudaFuncSetAttribute(gemm_pv,     cudaFuncAttributeMaxDynamicSharedMemorySize, PV_SMEM);

    // 1) Fused prep
    prep_kernel<<<(QUADS_TOT + 255) / 256, 256>>>(
        mel, text, Wq, Wk, Wv, mf16, tf16, wqf, wkf, wvf);

    // 2) Projections
    gemm_projh<<<dim3(2, 64), 256, H2_SMEM>>>(tf16, wqf, qf16);
    gemm_projkv<<<dim3(2, 256), 512, KV_SMEM>>>(mf16, wkf, wvf, kf16, vf16);

    // 3) Logits
    gemm_qk<<<dim3(MEL_LEN / 128, SRC_LEN / 128, BATCH), 256, H2_SMEM>>>(
        qf16, kf16, mel_mask, out_attn);

    // 4) Softmax + P emit
    softmax_kernel<<<BATCH * SRC_LEN, 256>>>(out_attn, src_mask, pf16);

    // 5) PV split-K x2
    gemm_pv<<<dim3(DMODEL / 128, SRC_LEN / 128, BATCH * 2), 256, PV_SMEM>>>(
        pf16, vf16, op0, op1);

    // 6) LayerNorm
    ln_kernel<<<BATCH * SRC_LEN, 256>>>(op0, op1, gamma, beta, out_o);
}